// round 1
// baseline (speedup 1.0000x reference)
#include <cuda_runtime.h>
#include <math.h>

#define BB   2
#define SS   4096
#define DD   512
#define HH   8
#define DKV  64
#define ROWS (BB*SS)     // 8192
#define DFF  2048

// ---------------- scratch (static device allocations only) ----------------
__device__ float g_Qn [ROWS*DD];
__device__ float g_q  [ROWS*DD];
__device__ float g_k  [ROWS*DD];
__device__ float g_v  [ROWS*DD];
__device__ float g_ctx[ROWS*DD];
__device__ float g_X  [ROWS*DD];
__device__ float g_Xn [ROWS*DD];
__device__ float g_h  [ROWS*DFF];

// ---------------- LayerNorm: one block per row, 128 threads ----------------
__global__ void ln_kernel(const float* __restrict__ x, const float* __restrict__ g,
                          const float* __restrict__ b, float* __restrict__ y)
{
    __shared__ float red[8];
    int row = blockIdx.x;
    int t = threadIdx.x;                       // 0..127, 4 floats each
    float4 v = ((const float4*)(x + (size_t)row*DD))[t];
    float s  = v.x+v.y+v.z+v.w;
    float s2 = v.x*v.x+v.y*v.y+v.z*v.z+v.w*v.w;
    #pragma unroll
    for (int o=16;o>0;o>>=1){
        s  += __shfl_xor_sync(0xffffffffu, s,  o);
        s2 += __shfl_xor_sync(0xffffffffu, s2, o);
    }
    if ((t&31)==0){ red[t>>5]=s; red[4+(t>>5)]=s2; }
    __syncthreads();
    s  = red[0]+red[1]+red[2]+red[3];
    s2 = red[4]+red[5]+red[6]+red[7];
    float mu  = s * (1.0f/DD);
    float var = s2 * (1.0f/DD) - mu*mu;
    float inv = rsqrtf(var + 1e-5f);
    float4 gv = ((const float4*)g)[t];
    float4 bv = ((const float4*)b)[t];
    float4 o4;
    o4.x = (v.x-mu)*inv*gv.x + bv.x;
    o4.y = (v.y-mu)*inv*gv.y + bv.y;
    o4.z = (v.z-mu)*inv*gv.z + bv.z;
    o4.w = (v.w-mu)*inv*gv.w + bv.w;
    ((float4*)(y + (size_t)row*DD))[t] = o4;
}

// ---------------- SGEMM: 128x128x16 tiles, 8x8 per-thread ----------------
// EPI: 0 = C=AB ; 1 = C=AB+resid ; 2 = C=gelu(AB+bias) ; 3 = C=AB+bias+resid
// TRANSB=false: B is KxN row-major.  TRANSB=true: B is NxK row-major (Linear weight).
__device__ __forceinline__ float gelu_exact(float x) {
    return 0.5f * x * (1.0f + erff(x * 0.70710678118654752440f));
}

template<int EPI, bool TRANSB>
__global__ __launch_bounds__(256)
void gemm_kernel(int M, int N, int K,
                 const float* __restrict__ A,
                 const float* __restrict__ B,
                 const float* __restrict__ bias,
                 const float* __restrict__ resid,
                 float* __restrict__ C)
{
    const int BM=128, BN=128, BK=16;
    __shared__ float As[BK][BM];
    __shared__ float Bs[BK][BN];

    int tid = threadIdx.x;
    int tx  = tid & 15;
    int ty  = tid >> 4;
    int rowBase = blockIdx.y * BM;
    int colBase = blockIdx.x * BN;

    float acc[8][8];
    #pragma unroll
    for (int i=0;i<8;i++)
        #pragma unroll
        for (int j=0;j<8;j++) acc[i][j]=0.f;

    for (int kt=0; kt<K; kt+=BK) {
        // ---- load A tile (128 x 16) ----
        {
            int r = tid >> 2;            // 0..63
            int c = (tid & 3) * 4;       // 0,4,8,12
            #pragma unroll
            for (int i=0;i<2;i++){
                int rr = r + i*64;
                float4 v = *(const float4*)(A + (size_t)(rowBase+rr)*K + kt + c);
                As[c+0][rr]=v.x; As[c+1][rr]=v.y; As[c+2][rr]=v.z; As[c+3][rr]=v.w;
            }
        }
        // ---- load B tile (16 x 128) ----
        if (!TRANSB) {
            int r = tid >> 5;            // 0..7
            int c = (tid & 31) * 4;      // 0..124
            #pragma unroll
            for (int i=0;i<2;i++){
                int rr = r + i*8;
                float4 v = *(const float4*)(B + (size_t)(kt+rr)*N + colBase + c);
                Bs[rr][c+0]=v.x; Bs[rr][c+1]=v.y; Bs[rr][c+2]=v.z; Bs[rr][c+3]=v.w;
            }
        } else {
            int n = tid >> 2;            // 0..63
            int c = (tid & 3) * 4;
            #pragma unroll
            for (int i=0;i<2;i++){
                int nn = n + i*64;
                float4 v = *(const float4*)(B + (size_t)(colBase+nn)*K + kt + c);
                Bs[c+0][nn]=v.x; Bs[c+1][nn]=v.y; Bs[c+2][nn]=v.z; Bs[c+3][nn]=v.w;
            }
        }
        __syncthreads();

        #pragma unroll
        for (int kk=0;kk<BK;kk++){
            float ra[8], rb[8];
            #pragma unroll
            for (int i=0;i<8;i++) ra[i] = As[kk][ty*8+i];
            #pragma unroll
            for (int j=0;j<8;j++) rb[j] = Bs[kk][tx*8+j];
            #pragma unroll
            for (int i=0;i<8;i++)
                #pragma unroll
                for (int j=0;j<8;j++)
                    acc[i][j] += ra[i]*rb[j];
        }
        __syncthreads();
    }

    // ---- epilogue ----
    int row0 = rowBase + ty*8;
    int col0 = colBase + tx*8;
    #pragma unroll
    for (int i=0;i<8;i++){
        size_t ro = (size_t)(row0+i)*N + col0;
        #pragma unroll
        for (int j=0;j<8;j+=4){
            float4 o4;
            float vv[4];
            #pragma unroll
            for (int jj=0;jj<4;jj++){
                float v = acc[i][j+jj];
                if (EPI==1) v = v + resid[ro + j + jj];
                if (EPI==2) v = gelu_exact(v + bias[col0 + j + jj]);
                if (EPI==3) v = v + bias[col0 + j + jj] + resid[ro + j + jj];
                vv[jj]=v;
            }
            o4.x=vv[0]; o4.y=vv[1]; o4.z=vv[2]; o4.w=vv[3];
            *(float4*)(C + ro + j) = o4;
        }
    }
}

// ---------------- Flash attention: 128 queries x 64 keys per tile ----------------
// Block: 256 threads. Thread (rg = tid/16, c = tid%16) owns 8 rows x 4 dims.
// smem stride 65 to dodge bank conflicts.
#define SDP 65
#define ATTN_SMEM ((128 + 64 + 64 + 128) * SDP * 4)   // 99840 bytes

__global__ __launch_bounds__(256)
void attn_kernel(const float* __restrict__ qg, const float* __restrict__ kg,
                 const float* __restrict__ vg, float* __restrict__ og)
{
    extern __shared__ float smx[];
    float* sq = smx;                  // 128 * SDP
    float* sk = sq + 128*SDP;         // 64  * SDP
    float* sv = sk + 64*SDP;          // 64  * SDP
    float* sp = sv + 64*SDP;          // 128 * SDP

    int qt  = blockIdx.x;             // 0..31 (128-query tiles)
    int h   = blockIdx.y;
    int b   = blockIdx.z;
    int tid = threadIdx.x;
    int c   = tid & 15;               // col group (4 dims / 4 keys)
    int rg  = tid >> 4;               // row group (8 rows)
    size_t hb = ((size_t)b*SS)*DD + (size_t)h*DKV;

    // load Q tile (128 x 64)
    {
        int r   = tid >> 1;
        int off = (tid & 1) * 32;
        const float* src = qg + hb + (size_t)(qt*128 + r)*DD + off;
        float* dst = sq + r*SDP + off;
        #pragma unroll
        for (int i=0;i<8;i++){
            float4 t4 = *(const float4*)(src + i*4);
            dst[i*4+0]=t4.x; dst[i*4+1]=t4.y; dst[i*4+2]=t4.z; dst[i*4+3]=t4.w;
        }
    }

    float m[8], l[8], acc[8][4];
    #pragma unroll
    for (int i=0;i<8;i++){
        m[i] = -INFINITY; l[i] = 0.f;
        #pragma unroll
        for (int j=0;j<4;j++) acc[i][j] = 0.f;
    }
    const float scale = (float)(1.0/(8.0 + 1e-6));

    for (int kt=0; kt<SS/64; kt++) {
        __syncthreads();   // previous pv done before overwriting K/V tiles
        // load K,V tiles (64 x 64 each)
        {
            int r   = tid >> 2;
            int off = (tid & 3) * 16;
            const float* ksrc = kg + hb + (size_t)(kt*64 + r)*DD + off;
            const float* vsrc = vg + hb + (size_t)(kt*64 + r)*DD + off;
            float* kd = sk + r*SDP + off;
            float* vd = sv + r*SDP + off;
            #pragma unroll
            for (int i=0;i<4;i++){
                float4 t4 = *(const float4*)(ksrc + i*4);
                kd[i*4+0]=t4.x; kd[i*4+1]=t4.y; kd[i*4+2]=t4.z; kd[i*4+3]=t4.w;
                float4 u4 = *(const float4*)(vsrc + i*4);
                vd[i*4+0]=u4.x; vd[i*4+1]=u4.y; vd[i*4+2]=u4.z; vd[i*4+3]=u4.w;
            }
        }
        __syncthreads();

        // scores: s[8][4] for rows rg*8+i, keys c*4+j
        float s[8][4];
        #pragma unroll
        for (int i=0;i<8;i++)
            #pragma unroll
            for (int j=0;j<4;j++) s[i][j]=0.f;
        const float* sqb = sq + (rg*8)*SDP;
        const float* skb = sk + (c*4)*SDP;
        #pragma unroll 4
        for (int d=0; d<DKV; d++){
            float kv[4];
            #pragma unroll
            for (int j=0;j<4;j++) kv[j] = skb[j*SDP + d];
            #pragma unroll
            for (int i=0;i<8;i++){
                float qv = sqb[i*SDP + d];
                #pragma unroll
                for (int j=0;j<4;j++) s[i][j] += qv * kv[j];
            }
        }

        // streaming softmax update (reduce across 16 lanes of the row group)
        #pragma unroll
        for (int i=0;i<8;i++){
            #pragma unroll
            for (int j=0;j<4;j++) s[i][j] *= scale;
            float mx = fmaxf(fmaxf(s[i][0],s[i][1]), fmaxf(s[i][2],s[i][3]));
            #pragma unroll
            for (int o=8;o>0;o>>=1) mx = fmaxf(mx, __shfl_xor_sync(0xffffffffu, mx, o));
            float mn   = fmaxf(m[i], mx);
            float corr = __expf(m[i]-mn);
            float ps = 0.f;
            #pragma unroll
            for (int j=0;j<4;j++){ float p = __expf(s[i][j]-mn); s[i][j]=p; ps += p; }
            #pragma unroll
            for (int o=8;o>0;o>>=1) ps += __shfl_xor_sync(0xffffffffu, ps, o);
            l[i] = l[i]*corr + ps;
            m[i] = mn;
            #pragma unroll
            for (int j=0;j<4;j++) acc[i][j] *= corr;
            #pragma unroll
            for (int j=0;j<4;j++) sp[(rg*8+i)*SDP + c*4 + j] = s[i][j];
        }
        __syncthreads();

        // acc += P @ V   (rows rg*8+i, dims c*4+j)
        const float* spb = sp + (rg*8)*SDP;
        const float* svb = sv + c*4;
        #pragma unroll 2
        for (int k2=0; k2<64; k2++){
            float vv[4];
            #pragma unroll
            for (int j=0;j<4;j++) vv[j] = svb[(size_t)k2*SDP + j];
            #pragma unroll
            for (int i=0;i<8;i++){
                float pv = spb[i*SDP + k2];
                #pragma unroll
                for (int j=0;j<4;j++) acc[i][j] += pv * vv[j];
            }
        }
    }

    // normalize + write ctx (layout [B,S,H*DV])
    #pragma unroll
    for (int i=0;i<8;i++){
        float inv = 1.0f / l[i];
        int row = qt*128 + rg*8 + i;
        float4 o4;
        o4.x = acc[i][0]*inv; o4.y = acc[i][1]*inv;
        o4.z = acc[i][2]*inv; o4.w = acc[i][3]*inv;
        *(float4*)(og + hb + (size_t)row*DD + c*4) = o4;
    }
}

// ---------------- launcher ----------------
extern "C" void kernel_launch(void* const* d_in, const int* in_sizes, int n_in,
                              void* d_out, int out_size)
{
    (void)in_sizes; (void)n_in; (void)out_size;
    const float* Q     = (const float*)d_in[0];
    const float* Kin   = (const float*)d_in[1];
    const float* Vin   = (const float*)d_in[2];
    const float* W_q   = (const float*)d_in[3];
    const float* W_k   = (const float*)d_in[4];
    const float* W_v   = (const float*)d_in[5];
    const float* W_o   = (const float*)d_in[6];
    const float* ln1_g = (const float*)d_in[7];
    const float* ln1_b = (const float*)d_in[8];
    const float* ln2_g = (const float*)d_in[9];
    const float* ln2_b = (const float*)d_in[10];
    const float* w1    = (const float*)d_in[11];
    const float* b1    = (const float*)d_in[12];
    const float* w2    = (const float*)d_in[13];
    const float* b2    = (const float*)d_in[14];
    float* out = (float*)d_out;

    float *Qn,*q,*k,*v,*ctx,*X,*Xn,*hbuf;
    cudaGetSymbolAddress((void**)&Qn,  g_Qn);
    cudaGetSymbolAddress((void**)&q,   g_q);
    cudaGetSymbolAddress((void**)&k,   g_k);
    cudaGetSymbolAddress((void**)&v,   g_v);
    cudaGetSymbolAddress((void**)&ctx, g_ctx);
    cudaGetSymbolAddress((void**)&X,   g_X);
    cudaGetSymbolAddress((void**)&Xn,  g_Xn);
    cudaGetSymbolAddress((void**)&hbuf,g_h);

    cudaFuncSetAttribute(attn_kernel, cudaFuncAttributeMaxDynamicSharedMemorySize, ATTN_SMEM);

    // 1. LN1(Q)
    ln_kernel<<<ROWS,128>>>(Q, ln1_g, ln1_b, Qn);
    // 2-4. projections
    gemm_kernel<0,false><<<dim3(DD/128,  ROWS/128), 256>>>(ROWS, DD,  DD,  Qn,  W_q, nullptr, nullptr, q);
    gemm_kernel<0,false><<<dim3(DD/128,  ROWS/128), 256>>>(ROWS, DD,  DD,  Kin, W_k, nullptr, nullptr, k);
    gemm_kernel<0,false><<<dim3(DD/128,  ROWS/128), 256>>>(ROWS, DD,  DD,  Vin, W_v, nullptr, nullptr, v);
    // 5. attention
    attn_kernel<<<dim3(SS/128, HH, BB), 256, ATTN_SMEM>>>(q, k, v, ctx);
    // 6. X = Q + ctx @ W_o
    gemm_kernel<1,false><<<dim3(DD/128,  ROWS/128), 256>>>(ROWS, DD,  DD,  ctx, W_o, nullptr, Q, X);
    // 7. LN2(X)
    ln_kernel<<<ROWS,128>>>(X, ln2_g, ln2_b, Xn);
    // 8. h = gelu(Xn @ w1^T + b1)
    gemm_kernel<2,true ><<<dim3(DFF/128, ROWS/128), 256>>>(ROWS, DFF, DD,  Xn,  w1,  b1, nullptr, hbuf);
    // 9. out = X + h @ w2^T + b2
    gemm_kernel<3,true ><<<dim3(DD/128,  ROWS/128), 256>>>(ROWS, DD,  DFF, hbuf, w2, b2, X, out);
}

// round 5
// speedup vs baseline: 2.1304x; 2.1304x over previous
#include <cuda_runtime.h>
#include <cuda_bf16.h>
#include <cstdint>
#include <math.h>

#define BB   2
#define SS   4096
#define DD   512
#define HH   8
#define ROWS (BB*SS)
#define DFF  2048

typedef __nv_bfloat16  bf16;
typedef __nv_bfloat162 bf162;

// split layout: [row][2C] bf16 ; col2(k,part) = (k>>5)*64 + (k&31) + 32*part
__device__ bf16 g_Qn2 [ROWS*2*DD];
__device__ bf16 g_Kin2[ROWS*2*DD];
__device__ bf16 g_Vin2[ROWS*2*DD];
__device__ bf16 g_q2  [ROWS*2*DD];
__device__ bf16 g_k2  [ROWS*2*DD];
__device__ bf16 g_v2  [ROWS*2*DD];
__device__ bf16 g_ctx2[ROWS*2*DD];
__device__ bf16 g_Xn2 [ROWS*2*DD];
__device__ bf16 g_h2  [(size_t)ROWS*2*DFF];
__device__ float g_X  [ROWS*DD];
__device__ bf16 g_Wq2 [DD*2*DD];
__device__ bf16 g_Wk2 [DD*2*DD];
__device__ bf16 g_Wv2 [DD*2*DD];
__device__ bf16 g_Wo2 [DD*2*DD];
__device__ bf16 g_w12 [DFF*2*DD];
__device__ bf16 g_w22 [DD*2*DFF];

// ---------------- asm helpers ----------------
__device__ __forceinline__ uint32_t smem_u32(const void* p) {
    uint32_t a;
    asm("{ .reg .u64 t; cvta.to.shared.u64 t, %1; cvt.u32.u64 %0, t; }" : "=r"(a) : "l"(p));
    return a;
}
__device__ __forceinline__ void cp16(uint32_t dst, const void* src){
    asm volatile("cp.async.cg.shared.global [%0], [%1], 16;" :: "r"(dst), "l"(src));
}
__device__ __forceinline__ void cp_commit(){ asm volatile("cp.async.commit_group;" ::: "memory"); }
__device__ __forceinline__ void cp_wait0(){ asm volatile("cp.async.wait_group 0;" ::: "memory"); }
__device__ __forceinline__ void cp_wait1(){ asm volatile("cp.async.wait_group 1;" ::: "memory"); }

__device__ __forceinline__ void ldsm4(uint32_t* r, uint32_t a){
    asm volatile("ldmatrix.sync.aligned.m8n8.x4.shared.b16 {%0,%1,%2,%3}, [%4];"
        : "=r"(r[0]),"=r"(r[1]),"=r"(r[2]),"=r"(r[3]) : "r"(a));
}
__device__ __forceinline__ void ldsm4t(uint32_t* r, uint32_t a){
    asm volatile("ldmatrix.sync.aligned.m8n8.x4.trans.shared.b16 {%0,%1,%2,%3}, [%4];"
        : "=r"(r[0]),"=r"(r[1]),"=r"(r[2]),"=r"(r[3]) : "r"(a));
}
__device__ __forceinline__ void mmabf(float* d, const uint32_t* a, uint32_t b0, uint32_t b1){
    asm volatile("mma.sync.aligned.m16n8k16.row.col.f32.bf16.bf16.f32 "
        "{%0,%1,%2,%3}, {%4,%5,%6,%7}, {%8,%9}, {%0,%1,%2,%3};"
        : "+f"(d[0]),"+f"(d[1]),"+f"(d[2]),"+f"(d[3])
        : "r"(a[0]),"r"(a[1]),"r"(a[2]),"r"(a[3]), "r"(b0), "r"(b1));
}
__device__ __forceinline__ float gelu_exact(float x) {
    return 0.5f * x * (1.0f + erff(x * 0.70710678118654752440f));
}
__device__ __forceinline__ void split_pair_store(bf16* base, float v0, float v1){
    bf16 h0 = __float2bfloat16(v0), h1 = __float2bfloat16(v1);
    bf162 hp; hp.x = h0; hp.y = h1;
    *(bf162*)(base) = hp;
    bf162 lp;
    lp.x = __float2bfloat16(v0 - __bfloat162float(h0));
    lp.y = __float2bfloat16(v1 - __bfloat162float(h1));
    *(bf162*)(base + 32) = lp;
}

// ---------------- LayerNorm -> split bf16 ----------------
__global__ void ln_split(const float* __restrict__ x, const float* __restrict__ g,
                         const float* __restrict__ b, bf16* __restrict__ y2)
{
    __shared__ float red[8];
    int row = blockIdx.x;
    int t = threadIdx.x;
    float4 v = ((const float4*)(x + (size_t)row*DD))[t];
    float s  = v.x+v.y+v.z+v.w;
    float s2 = v.x*v.x+v.y*v.y+v.z*v.z+v.w*v.w;
    #pragma unroll
    for (int o=16;o>0;o>>=1){
        s  += __shfl_xor_sync(0xffffffffu, s,  o);
        s2 += __shfl_xor_sync(0xffffffffu, s2, o);
    }
    if ((t&31)==0){ red[t>>5]=s; red[4+(t>>5)]=s2; }
    __syncthreads();
    s  = red[0]+red[1]+red[2]+red[3];
    s2 = red[4]+red[5]+red[6]+red[7];
    float mu  = s * (1.0f/DD);
    float var = s2 * (1.0f/DD) - mu*mu;
    float inv = rsqrtf(var + 1e-5f);
    float4 gv = ((const float4*)g)[t];
    float4 bv = ((const float4*)b)[t];
    float o0 = (v.x-mu)*inv*gv.x + bv.x;
    float o1 = (v.y-mu)*inv*gv.y + bv.y;
    float o2 = (v.z-mu)*inv*gv.z + bv.z;
    float o3 = (v.w-mu)*inv*gv.w + bv.w;
    int k = 4*t;
    bf16* yr = y2 + (size_t)row*(2*DD) + ((k>>5)<<6) + (k&31);
    split_pair_store(yr, o0, o1);
    split_pair_store(yr + 2, o2, o3);
}

// ---------------- fp32 [R][C] -> split bf16 [R][2C] ----------------
__global__ void split_k(const float* __restrict__ in, bf16* __restrict__ out,
                        int C, int total4)
{
    int i = blockIdx.x*blockDim.x + threadIdx.x;
    if (i >= total4) return;
    size_t e = (size_t)i*4;
    int r = (int)(e / C); int k = (int)(e % C);
    float4 v = *(const float4*)(in + e);
    bf16* o = out + (size_t)r*2*C + ((k>>5)<<6) + (k&31);
    split_pair_store(o, v.x, v.y);
    split_pair_store(o + 2, v.z, v.w);
}

// ---------------- transpose + split: W[512k][512n] -> out[n][1024] ----------------
__global__ void tsplit(const float* __restrict__ Win, bf16* __restrict__ out)
{
    __shared__ float t[32][33];
    int bk = blockIdx.y*32, bn = blockIdx.x*32;
    int x = threadIdx.x, y = threadIdx.y;
    #pragma unroll
    for (int j=0;j<4;j++)
        t[y+8*j][x] = Win[(size_t)(bk+y+8*j)*DD + bn + x];
    __syncthreads();
    #pragma unroll
    for (int j=0;j<4;j++){
        int n = bn + y + 8*j;
        float v = t[x][y+8*j];
        bf16 hv = __float2bfloat16(v);
        bf16* o = out + (size_t)n*(2*DD) + ((bk>>5)<<6);
        o[x]      = hv;
        o[x + 32] = __float2bfloat16(v - __bfloat162float(hv));
    }
}

// ================= bf16-split GEMM (mma.sync) =================
// C = A2 (*) B2^T, 128x128 tile, 32-k chunks (row = 128B hi32|lo32), 3-stage cp.async.
// EPI: 0 split-out ; 1 fp32 +resid ; 2 gelu(+bias) split-out ; 3 fp32 +bias+resid
#define GEMM_SMEM (3*32768)

template<int EPI>
__global__ __launch_bounds__(256)
void gemm_mma(const bf16* __restrict__ A2, const bf16* __restrict__ B2,
              int N, int K,
              const float* __restrict__ bias, const float* __restrict__ resid,
              float* __restrict__ Cf, bf16* __restrict__ C2)
{
    extern __shared__ char smc[];
    uint32_t sb = smem_u32(smc);
    const int tid = threadIdx.x, lane = tid&31, w = tid>>5;
    const int wr = w>>2, wc = w&3;
    const int rowBase = blockIdx.y*128, colBase = blockIdx.x*128;
    const int K2 = 2*K;
    const int nC = K>>5;

    float acc[4][4][4];
    #pragma unroll
    for (int a=0;a<4;a++)
        #pragma unroll
        for (int b=0;b<4;b++)
            #pragma unroll
            for (int c=0;c<4;c++) acc[a][b][c]=0.f;

#define G_LOAD(chunk, s) do{                                                   \
    uint32_t sA_ = sb + (uint32_t)(s)*32768u; uint32_t sB_ = sA_ + 16384u;     \
    _Pragma("unroll")                                                          \
    for (int i_=0;i_<4;i_++){                                                  \
        int idx_ = tid*4 + i_; int r_ = idx_>>3, u_ = idx_&7;                  \
        cp16(sA_ + (uint32_t)(r_*128 + ((u_^(r_&7))<<4)),                      \
             A2 + (size_t)(rowBase+r_)*K2 + (chunk)*64 + u_*8);                \
        cp16(sB_ + (uint32_t)(r_*128 + ((u_^(r_&7))<<4)),                      \
             B2 + (size_t)(colBase+r_)*K2 + (chunk)*64 + u_*8);                \
    } cp_commit(); } while(0)

    G_LOAD(0, 0);
    if (nC > 1) G_LOAD(1, 1);

    for (int c=0;c<nC;c++){
        int s = c % 3;
        if (c == nC-1) cp_wait0(); else cp_wait1();
        __syncthreads();
        if (c+2 < nC) G_LOAD(c+2, (c+2)%3);
        uint32_t sA = sb + (uint32_t)s*32768u, sB = sA + 16384u;
        #pragma unroll
        for (int ks=0;ks<2;ks++){
            uint32_t ah[4][4], al[4][4], bh4[2][4], bl4[2][4];
            #pragma unroll
            for (int mt=0;mt<4;mt++){
                int r = wr*64 + mt*16 + (lane&15);
                uint32_t uh = ks*2 + (lane>>4);
                ldsm4(ah[mt], sA + r*128 + ((uh^(r&7))<<4));
                ldsm4(al[mt], sA + r*128 + (((uh+4)^(r&7))<<4));
            }
            #pragma unroll
            for (int np=0;np<2;np++){
                int r = wc*32 + np*16 + (lane&15);
                uint32_t uh = ks*2 + (lane>>4);
                ldsm4(bh4[np], sB + r*128 + ((uh^(r&7))<<4));
                ldsm4(bl4[np], sB + r*128 + (((uh+4)^(r&7))<<4));
            }
            #pragma unroll
            for (int mt=0;mt<4;mt++)
                #pragma unroll
                for (int nt=0;nt<4;nt++){
                    uint32_t b0 = bh4[nt>>1][nt&1], b1 = bh4[nt>>1][2+(nt&1)];
                    mmabf(acc[mt][nt], ah[mt], b0, b1);
                    mmabf(acc[mt][nt], al[mt], b0, b1);
                    uint32_t c0 = bl4[nt>>1][nt&1], c1 = bl4[nt>>1][2+(nt&1)];
                    mmabf(acc[mt][nt], ah[mt], c0, c1);
                }
        }
        __syncthreads();
    }
#undef G_LOAD

    int ra = lane>>2;
    #pragma unroll
    for (int mt=0;mt<4;mt++){
        int r0 = rowBase + wr*64 + mt*16 + ra;
        #pragma unroll
        for (int nt=0;nt<4;nt++){
            int n0 = colBase + wc*32 + nt*8 + 2*(lane&3);
            float* a = acc[mt][nt];
            #pragma unroll
            for (int hh=0;hh<2;hh++){
                int r = r0 + hh*8;
                float v0 = a[2*hh+0], v1 = a[2*hh+1];
                if (EPI==0 || EPI==2){
                    if (EPI==2){ v0 = gelu_exact(v0 + bias[n0]); v1 = gelu_exact(v1 + bias[n0+1]); }
                    int c2 = ((n0>>5)<<6) + (n0&31);
                    split_pair_store(C2 + (size_t)r*(size_t)(2*N) + c2, v0, v1);
                } else {
                    size_t o = (size_t)r*N + n0;
                    if (EPI==1){ v0 += resid[o]; v1 += resid[o+1]; }
                    else       { v0 += bias[n0] + resid[o]; v1 += bias[n0+1] + resid[o+1]; }
                    float2 f2; f2.x=v0; f2.y=v1;
                    *(float2*)(Cf + o) = f2;
                }
            }
        }
    }
}

// ================= Flash attention (mma.sync, bf16 split) =================
// smem: Qh 16K | Ql 16K | 2 stages x [Kh 8K|Kl 8K|Vh 8K|Vl 8K] | 8 x [Ph 2K|Pl 2K]
#define A_QH 0u
#define A_QL 16384u
#define A_KV 32768u
#define A_P  98304u
#define ATTN_SMEM 131072

__global__ __launch_bounds__(256)
void attn_mma(const bf16* __restrict__ q2, const bf16* __restrict__ k2,
              const bf16* __restrict__ v2, bf16* __restrict__ ctx2)
{
    extern __shared__ char smc[];
    uint32_t sb = smem_u32(smc);
    char* smb = smc;
    const int tid = threadIdx.x, lane = tid&31, w = tid>>5;
    const int qt = blockIdx.x, h = blockIdx.y, b = blockIdx.z;
    const int rowQ0 = b*SS + qt*128;
    const int hoff = h*128;               // bf16 offset of head in 1024-wide row

#define KV_LOAD(it, s) do{                                                     \
    uint32_t stg_ = sb + A_KV + (uint32_t)(s)*32768u;                          \
    int rk0_ = b*SS + (it)*64;                                                 \
    _Pragma("unroll")                                                          \
    for (int i_=0;i_<8;i_++){                                                  \
        int idx_ = tid*8 + i_;                                                 \
        const bf16* src_ = (idx_ < 1024) ? k2 : v2;                            \
        uint32_t tb_ = (idx_ < 1024) ? stg_ : (stg_ + 16384u);                 \
        int j_ = idx_ & 1023; int r_ = j_>>4, c_ = (j_>>3)&1, u8_ = j_&7;      \
        uint32_t un_ = (u8_<4) ? (uint32_t)(c_*4 + u8_) : (uint32_t)(c_*4 + u8_ - 4); \
        uint32_t dst_ = tb_ + ((u8_<4)?0u:8192u)                               \
                      + (uint32_t)(r_*128 + ((un_^(r_&7))<<4));                \
        cp16(dst_, src_ + (size_t)(rk0_+r_)*1024 + hoff + c_*64 + u8_*8);      \
    } cp_commit(); } while(0)

    // prologue: Q + KV0 (group 0), KV1 (group 1)
    {
        #pragma unroll
        for (int i=0;i<8;i++){
            int idx = tid*8 + i;
            int r = idx>>4, c = (idx>>3)&1, u8 = idx&7;
            uint32_t un = (u8<4) ? (uint32_t)(c*4 + u8) : (uint32_t)(c*4 + u8 - 4);
            uint32_t dst = sb + ((u8<4)?A_QH:A_QL) + (uint32_t)(r*128 + ((un^(r&7))<<4));
            cp16(dst, q2 + (size_t)(rowQ0+r)*1024 + hoff + c*64 + u8*8);
        }
        KV_LOAD(0, 0);
        KV_LOAD(1, 1);
    }

    uint32_t qh[4][4], ql[4][4];
    float m0=-INFINITY, m1=-INFINITY, l0=0.f, l1=0.f;
    float ctx[8][4];
    #pragma unroll
    for (int nt=0;nt<8;nt++){ ctx[nt][0]=0;ctx[nt][1]=0;ctx[nt][2]=0;ctx[nt][3]=0; }
    const float SCALE = (float)(1.0/(8.0 + 1e-6));
    const uint32_t Pw = sb + A_P + (uint32_t)w*4096u;
    char* Pwc = smb + A_P + w*4096;

    for (int it=0; it<SS/64; it++){
        int s = it&1;
        if (it == SS/64-1) cp_wait0(); else cp_wait1();
        __syncthreads();
        if (it == 0){
            #pragma unroll
            for (int ks=0;ks<4;ks++){
                int r = w*16 + (lane&15);
                uint32_t u = ks*2 + (lane>>4);
                ldsm4(qh[ks], sb + A_QH + r*128 + ((u^(r&7))<<4));
                ldsm4(ql[ks], sb + A_QL + r*128 + ((u^(r&7))<<4));
            }
        }
        uint32_t sK = sb + A_KV + (uint32_t)s*32768u;
        uint32_t sV = sK + 16384u;

        // ---- QK^T (3-pass): 8 n8-tiles over 64 keys ----
        float sc[8][4];
        #pragma unroll
        for (int nt=0;nt<8;nt++){ sc[nt][0]=0;sc[nt][1]=0;sc[nt][2]=0;sc[nt][3]=0; }
        #pragma unroll
        for (int ks=0;ks<4;ks++){
            uint32_t kh4[4][4], kl4[4][4];
            #pragma unroll
            for (int np=0;np<4;np++){
                int r = np*16 + (lane&15);
                uint32_t u = ks*2 + (lane>>4);
                ldsm4(kh4[np], sK + r*128 + ((u^(r&7))<<4));
                ldsm4(kl4[np], sK + 8192 + r*128 + ((u^(r&7))<<4));
            }
            #pragma unroll
            for (int nt=0;nt<8;nt++){
                uint32_t b0 = kh4[nt>>1][nt&1], b1 = kh4[nt>>1][2+(nt&1)];
                mmabf(sc[nt], qh[ks], b0, b1);
                mmabf(sc[nt], ql[ks], b0, b1);
                uint32_t c0 = kl4[nt>>1][nt&1], c1 = kl4[nt>>1][2+(nt&1)];
                mmabf(sc[nt], qh[ks], c0, c1);
            }
        }

        // ---- streaming softmax (rows lane>>2 and +8) ----
        float mxa=-INFINITY, mxb=-INFINITY;
        #pragma unroll
        for (int nt=0;nt<8;nt++){
            sc[nt][0]*=SCALE; sc[nt][1]*=SCALE; sc[nt][2]*=SCALE; sc[nt][3]*=SCALE;
            mxa = fmaxf(mxa, fmaxf(sc[nt][0], sc[nt][1]));
            mxb = fmaxf(mxb, fmaxf(sc[nt][2], sc[nt][3]));
        }
        mxa = fmaxf(mxa, __shfl_xor_sync(0xffffffffu, mxa, 1));
        mxa = fmaxf(mxa, __shfl_xor_sync(0xffffffffu, mxa, 2));
        mxb = fmaxf(mxb, __shfl_xor_sync(0xffffffffu, mxb, 1));
        mxb = fmaxf(mxb, __shfl_xor_sync(0xffffffffu, mxb, 2));
        float na = fmaxf(m0, mxa), nb = fmaxf(m1, mxb);
        float ca = __expf(m0 - na), cb = __expf(m1 - nb);
        m0 = na; m1 = nb;
        int rA = lane>>2, rB = rA + 8;
        float sa = 0.f, sbm = 0.f;
        #pragma unroll
        for (int nt=0;nt<8;nt++){
            float p0 = __expf(sc[nt][0]-na), p1 = __expf(sc[nt][1]-na);
            float p2 = __expf(sc[nt][2]-nb), p3 = __expf(sc[nt][3]-nb);
            sa += p0+p1; sbm += p2+p3;
            int c = nt*8 + 2*(lane&3);
            int offA = rA*128 + ((((c>>3))^(rA&7))<<4) + (c&7)*2;
            int offB = rB*128 + ((((c>>3))^(rB&7))<<4) + (c&7)*2;
            bf162 t;
            bf16 h0=__float2bfloat16(p0), h1=__float2bfloat16(p1);
            t.x=h0; t.y=h1; *(bf162*)(Pwc + offA) = t;
            t.x=__float2bfloat16(p0-__bfloat162float(h0));
            t.y=__float2bfloat16(p1-__bfloat162float(h1));
            *(bf162*)(Pwc + 2048 + offA) = t;
            bf16 h2=__float2bfloat16(p2), h3=__float2bfloat16(p3);
            t.x=h2; t.y=h3; *(bf162*)(Pwc + offB) = t;
            t.x=__float2bfloat16(p2-__bfloat162float(h2));
            t.y=__float2bfloat16(p3-__bfloat162float(h3));
            *(bf162*)(Pwc + 2048 + offB) = t;
        }
        sa  += __shfl_xor_sync(0xffffffffu, sa, 1);
        sa  += __shfl_xor_sync(0xffffffffu, sa, 2);
        sbm += __shfl_xor_sync(0xffffffffu, sbm, 1);
        sbm += __shfl_xor_sync(0xffffffffu, sbm, 2);
        l0 = l0*ca + sa; l1 = l1*cb + sbm;
        #pragma unroll
        for (int nt=0;nt<8;nt++){ ctx[nt][0]*=ca; ctx[nt][1]*=ca; ctx[nt][2]*=cb; ctx[nt][3]*=cb; }
        __syncwarp();

        // ---- P @ V (3-pass): np2 = dim-16 group (0..3), nt = 2*np2 + q2i ----
        #pragma unroll
        for (int ks=0;ks<4;ks++){
            uint32_t aPh[4], aPl[4];
            {
                int r = lane&15;
                uint32_t u = ks*2 + (lane>>4);
                ldsm4(aPh, Pw + r*128 + ((u^(r&7))<<4));
                ldsm4(aPl, Pw + 2048 + r*128 + ((u^(r&7))<<4));
            }
            #pragma unroll
            for (int np2=0;np2<4;np2++){
                uint32_t vh4[4], vl4[4];
                int r = ks*16 + (lane&15);
                uint32_t u = np2*2 + (lane>>4);
                ldsm4t(vh4, sV + r*128 + ((u^(r&7))<<4));
                ldsm4t(vl4, sV + 8192 + r*128 + ((u^(r&7))<<4));
                #pragma unroll
                for (int q2i=0;q2i<2;q2i++){
                    int nt = np2*2 + q2i;
                    uint32_t b0 = vh4[q2i*2], b1 = vh4[q2i*2+1];
                    mmabf(ctx[nt], aPh, b0, b1);
                    mmabf(ctx[nt], aPl, b0, b1);
                    uint32_t c0 = vl4[q2i*2], c1 = vl4[q2i*2+1];
                    mmabf(ctx[nt], aPh, c0, c1);
                }
            }
        }
        __syncthreads();
        if (it+2 < SS/64) KV_LOAD(it+2, s);
    }
#undef KV_LOAD

    // ---- normalize + write ctx2 (split layout) ----
    float i0 = 1.0f/l0, i1 = 1.0f/l1;
    #pragma unroll
    for (int nt=0;nt<8;nt++){
        int d = nt*8 + 2*(lane&3);
        int c2 = hoff + ((d>>5)<<6) + (d&31);
        int rA = rowQ0 + w*16 + (lane>>2);
        split_pair_store(ctx2 + (size_t)rA*(2*DD) + c2, ctx[nt][0]*i0, ctx[nt][1]*i0);
        split_pair_store(ctx2 + (size_t)(rA+8)*(2*DD) + c2, ctx[nt][2]*i1, ctx[nt][3]*i1);
    }
}

extern "C" void kernel_launch(void* const* d_in, const int* in_sizes, int n_in,
                              void* d_out, int out_size)
{
    (void)in_sizes; (void)n_in; (void)out_size;
    const float* Q     = (const float*)d_in[0];
    const float* Kin   = (const float*)d_in[1];
    const float* Vin   = (const float*)d_in[2];
    const float* W_q   = (const float*)d_in[3];
    const float* W_k   = (const float*)d_in[4];
    const float* W_v   = (const float*)d_in[5];
    const float* W_o   = (const float*)d_in[6];
    const float* ln1_g = (const float*)d_in[7];
    const float* ln1_b = (const float*)d_in[8];
    const float* ln2_g = (const float*)d_in[9];
    const float* ln2_b = (const float*)d_in[10];
    const float* w1    = (const float*)d_in[11];
    const float* b1    = (const float*)d_in[12];
    const float* w2    = (const float*)d_in[13];
    const float* b2    = (const float*)d_in[14];
    float* out = (float*)d_out;

    bf16 *Qn2,*Kin2,*Vin2,*q2,*k2,*v2,*ctx2,*Xn2,*h2,*Wq2,*Wk2,*Wv2,*Wo2,*w12,*w22;
    float *X;
    cudaGetSymbolAddress((void**)&Qn2,  g_Qn2);
    cudaGetSymbolAddress((void**)&Kin2, g_Kin2);
    cudaGetSymbolAddress((void**)&Vin2, g_Vin2);
    cudaGetSymbolAddress((void**)&q2,   g_q2);
    cudaGetSymbolAddress((void**)&k2,   g_k2);
    cudaGetSymbolAddress((void**)&v2,   g_v2);
    cudaGetSymbolAddress((void**)&ctx2, g_ctx2);
    cudaGetSymbolAddress((void**)&Xn2,  g_Xn2);
    cudaGetSymbolAddress((void**)&h2,   g_h2);
    cudaGetSymbolAddress((void**)&X,    g_X);
    cudaGetSymbolAddress((void**)&Wq2,  g_Wq2);
    cudaGetSymbolAddress((void**)&Wk2,  g_Wk2);
    cudaGetSymbolAddress((void**)&Wv2,  g_Wv2);
    cudaGetSymbolAddress((void**)&Wo2,  g_Wo2);
    cudaGetSymbolAddress((void**)&w12,  g_w12);
    cudaGetSymbolAddress((void**)&w22,  g_w22);

    cudaFuncSetAttribute(attn_mma,    cudaFuncAttributeMaxDynamicSharedMemorySize, ATTN_SMEM);
    cudaFuncSetAttribute(gemm_mma<0>, cudaFuncAttributeMaxDynamicSharedMemorySize, GEMM_SMEM);
    cudaFuncSetAttribute(gemm_mma<1>, cudaFuncAttributeMaxDynamicSharedMemorySize, GEMM_SMEM);
    cudaFuncSetAttribute(gemm_mma<2>, cudaFuncAttributeMaxDynamicSharedMemorySize, GEMM_SMEM);
    cudaFuncSetAttribute(gemm_mma<3>, cudaFuncAttributeMaxDynamicSharedMemorySize, GEMM_SMEM);

    dim3 tb(32, 8), tg(16, 16);

    // conversions
    ln_split<<<ROWS,128>>>(Q, ln1_g, ln1_b, Qn2);
    split_k<<<(ROWS*DD/4+255)/256,256>>>(Kin, Kin2, DD, ROWS*DD/4);
    split_k<<<(ROWS*DD/4+255)/256,256>>>(Vin, Vin2, DD, ROWS*DD/4);
    tsplit<<<tg, tb>>>(W_q, Wq2);
    tsplit<<<tg, tb>>>(W_k, Wk2);
    tsplit<<<tg, tb>>>(W_v, Wv2);
    tsplit<<<tg, tb>>>(W_o, Wo2);
    split_k<<<(DFF*DD/4+255)/256,256>>>(w1, w12, DD, DFF*DD/4);
    split_k<<<(DD*DFF/4+255)/256,256>>>(w2, w22, DFF, DD*DFF/4);

    // projections
    gemm_mma<0><<<dim3(DD/128,  ROWS/128), 256, GEMM_SMEM>>>(Qn2,  Wq2, DD,  DD,  nullptr, nullptr, nullptr, q2);
    gemm_mma<0><<<dim3(DD/128,  ROWS/128), 256, GEMM_SMEM>>>(Kin2, Wk2, DD,  DD,  nullptr, nullptr, nullptr, k2);
    gemm_mma<0><<<dim3(DD/128,  ROWS/128), 256, GEMM_SMEM>>>(Vin2, Wv2, DD,  DD,  nullptr, nullptr, nullptr, v2);
    // attention
    attn_mma<<<dim3(SS/128, HH, BB), 256, ATTN_SMEM>>>(q2, k2, v2, ctx2);
    // X = Q + ctx @ Wo
    gemm_mma<1><<<dim3(DD/128,  ROWS/128), 256, GEMM_SMEM>>>(ctx2, Wo2, DD,  DD,  nullptr, Q, X, nullptr);
    // LN2 + FFN
    ln_split<<<ROWS,128>>>(X, ln2_g, ln2_b, Xn2);
    gemm_mma<2><<<dim3(DFF/128, ROWS/128), 256, GEMM_SMEM>>>(Xn2,  w12, DFF, DD,  b1, nullptr, nullptr, h2);
    gemm_mma<3><<<dim3(DD/128,  ROWS/128), 256, GEMM_SMEM>>>(h2,   w22, DD,  DFF, b2, X, out, nullptr);
}

// round 6
// speedup vs baseline: 2.1862x; 1.0262x over previous
#include <cuda_runtime.h>
#include <cuda_bf16.h>
#include <cstdint>
#include <math.h>

#define BB   2
#define SS   4096
#define DD   512
#define HH   8
#define ROWS (BB*SS)
#define DFF  2048

typedef __nv_bfloat16  bf16;
typedef __nv_bfloat162 bf162;

// split layout: [row][2C] bf16 ; col2(k,part) = (k>>5)*64 + (k&31) + 32*part
__device__ bf16 g_Qn2 [ROWS*2*DD];
__device__ bf16 g_Kin2[ROWS*2*DD];
__device__ bf16 g_Vin2[ROWS*2*DD];
__device__ bf16 g_q2  [ROWS*2*DD];
__device__ bf16 g_k2  [ROWS*2*DD];
__device__ bf16 g_v2  [ROWS*2*DD];
__device__ bf16 g_ctx2[ROWS*2*DD];
__device__ bf16 g_Xn2 [ROWS*2*DD];
__device__ bf16 g_h2  [(size_t)ROWS*2*DFF];
__device__ float g_X  [ROWS*DD];
__device__ bf16 g_Wq2 [DD*2*DD];
__device__ bf16 g_Wk2 [DD*2*DD];
__device__ bf16 g_Wv2 [DD*2*DD];
__device__ bf16 g_Wo2 [DD*2*DD];
__device__ bf16 g_w12 [DFF*2*DD];
__device__ bf16 g_w22 [DD*2*DFF];

// ---------------- asm helpers ----------------
__device__ __forceinline__ uint32_t smem_u32(const void* p) {
    uint32_t a;
    asm("{ .reg .u64 t; cvta.to.shared.u64 t, %1; cvt.u32.u64 %0, t; }" : "=r"(a) : "l"(p));
    return a;
}
__device__ __forceinline__ void cp16(uint32_t dst, const void* src){
    asm volatile("cp.async.cg.shared.global [%0], [%1], 16;" :: "r"(dst), "l"(src));
}
__device__ __forceinline__ void cp_commit(){ asm volatile("cp.async.commit_group;" ::: "memory"); }
__device__ __forceinline__ void cp_wait0(){ asm volatile("cp.async.wait_group 0;" ::: "memory"); }
__device__ __forceinline__ void cp_wait1(){ asm volatile("cp.async.wait_group 1;" ::: "memory"); }

__device__ __forceinline__ void ldsm4(uint32_t* r, uint32_t a){
    asm volatile("ldmatrix.sync.aligned.m8n8.x4.shared.b16 {%0,%1,%2,%3}, [%4];"
        : "=r"(r[0]),"=r"(r[1]),"=r"(r[2]),"=r"(r[3]) : "r"(a));
}
__device__ __forceinline__ void ldsm4t(uint32_t* r, uint32_t a){
    asm volatile("ldmatrix.sync.aligned.m8n8.x4.trans.shared.b16 {%0,%1,%2,%3}, [%4];"
        : "=r"(r[0]),"=r"(r[1]),"=r"(r[2]),"=r"(r[3]) : "r"(a));
}
__device__ __forceinline__ void mmabf(float* d, const uint32_t* a, uint32_t b0, uint32_t b1){
    asm volatile("mma.sync.aligned.m16n8k16.row.col.f32.bf16.bf16.f32 "
        "{%0,%1,%2,%3}, {%4,%5,%6,%7}, {%8,%9}, {%0,%1,%2,%3};"
        : "+f"(d[0]),"+f"(d[1]),"+f"(d[2]),"+f"(d[3])
        : "r"(a[0]),"r"(a[1]),"r"(a[2]),"r"(a[3]), "r"(b0), "r"(b1));
}
__device__ __forceinline__ float gelu_exact(float x) {
    return 0.5f * x * (1.0f + erff(x * 0.70710678118654752440f));
}
__device__ __forceinline__ void split_pair_store(bf16* base, float v0, float v1){
    bf16 h0 = __float2bfloat16(v0), h1 = __float2bfloat16(v1);
    bf162 hp; hp.x = h0; hp.y = h1;
    *(bf162*)(base) = hp;
    bf162 lp;
    lp.x = __float2bfloat16(v0 - __bfloat162float(h0));
    lp.y = __float2bfloat16(v1 - __bfloat162float(h1));
    *(bf162*)(base + 32) = lp;
}
// pack two fp32 into bf16x2 hi-fragment + bf16x2 lo-residual-fragment
__device__ __forceinline__ void packPair(float a, float b, uint32_t& hi, uint32_t& lo){
    bf16 ha = __float2bfloat16(a), hb = __float2bfloat16(b);
    bf162 h; h.x = ha; h.y = hb; hi = *(uint32_t*)&h;
    bf162 l;
    l.x = __float2bfloat16(a - __bfloat162float(ha));
    l.y = __float2bfloat16(b - __bfloat162float(hb));
    lo = *(uint32_t*)&l;
}

// ---------------- LayerNorm -> split bf16 ----------------
__global__ void ln_split(const float* __restrict__ x, const float* __restrict__ g,
                         const float* __restrict__ b, bf16* __restrict__ y2)
{
    __shared__ float red[8];
    int row = blockIdx.x;
    int t = threadIdx.x;
    float4 v = ((const float4*)(x + (size_t)row*DD))[t];
    float s  = v.x+v.y+v.z+v.w;
    float s2 = v.x*v.x+v.y*v.y+v.z*v.z+v.w*v.w;
    #pragma unroll
    for (int o=16;o>0;o>>=1){
        s  += __shfl_xor_sync(0xffffffffu, s,  o);
        s2 += __shfl_xor_sync(0xffffffffu, s2, o);
    }
    if ((t&31)==0){ red[t>>5]=s; red[4+(t>>5)]=s2; }
    __syncthreads();
    s  = red[0]+red[1]+red[2]+red[3];
    s2 = red[4]+red[5]+red[6]+red[7];
    float mu  = s * (1.0f/DD);
    float var = s2 * (1.0f/DD) - mu*mu;
    float inv = rsqrtf(var + 1e-5f);
    float4 gv = ((const float4*)g)[t];
    float4 bv = ((const float4*)b)[t];
    float o0 = (v.x-mu)*inv*gv.x + bv.x;
    float o1 = (v.y-mu)*inv*gv.y + bv.y;
    float o2 = (v.z-mu)*inv*gv.z + bv.z;
    float o3 = (v.w-mu)*inv*gv.w + bv.w;
    int k = 4*t;
    bf16* yr = y2 + (size_t)row*(2*DD) + ((k>>5)<<6) + (k&31);
    split_pair_store(yr, o0, o1);
    split_pair_store(yr + 2, o2, o3);
}

// ---------------- fp32 [R][C] -> split bf16 [R][2C] ----------------
__global__ void split_k(const float* __restrict__ in, bf16* __restrict__ out,
                        int C, int total4)
{
    int i = blockIdx.x*blockDim.x + threadIdx.x;
    if (i >= total4) return;
    size_t e = (size_t)i*4;
    int r = (int)(e / C); int k = (int)(e % C);
    float4 v = *(const float4*)(in + e);
    bf16* o = out + (size_t)r*2*C + ((k>>5)<<6) + (k&31);
    split_pair_store(o, v.x, v.y);
    split_pair_store(o + 2, v.z, v.w);
}

// ---------------- transpose + split: W[512k][512n] -> out[n][1024] ----------------
__global__ void tsplit(const float* __restrict__ Win, bf16* __restrict__ out)
{
    __shared__ float t[32][33];
    int bk = blockIdx.y*32, bn = blockIdx.x*32;
    int x = threadIdx.x, y = threadIdx.y;
    #pragma unroll
    for (int j=0;j<4;j++)
        t[y+8*j][x] = Win[(size_t)(bk+y+8*j)*DD + bn + x];
    __syncthreads();
    #pragma unroll
    for (int j=0;j<4;j++){
        int n = bn + y + 8*j;
        float v = t[x][y+8*j];
        bf16 hv = __float2bfloat16(v);
        bf16* o = out + (size_t)n*(2*DD) + ((bk>>5)<<6);
        o[x]      = hv;
        o[x + 32] = __float2bfloat16(v - __bfloat162float(hv));
    }
}

// ================= bf16-split GEMM (mma.sync) =================
// C = A2 (*) B2^T, 128x128 tile, 32-k chunks, 3-stage cp.async, pass-major mma order.
// EPI: 0 split-out ; 1 fp32 +resid ; 2 gelu(+bias) split-out ; 3 fp32 +bias+resid
#define GEMM_SMEM (3*32768)

template<int EPI>
__global__ __launch_bounds__(256)
void gemm_mma(const bf16* __restrict__ A2, const bf16* __restrict__ B2,
              int N, int K,
              const float* __restrict__ bias, const float* __restrict__ resid,
              float* __restrict__ Cf, bf16* __restrict__ C2)
{
    extern __shared__ char smc[];
    uint32_t sb = smem_u32(smc);
    const int tid = threadIdx.x, lane = tid&31, w = tid>>5;
    const int wr = w>>2, wc = w&3;
    const int rowBase = blockIdx.y*128, colBase = blockIdx.x*128;
    const int K2 = 2*K;
    const int nC = K>>5;

    float acc[4][4][4];
    #pragma unroll
    for (int a=0;a<4;a++)
        #pragma unroll
        for (int b=0;b<4;b++)
            #pragma unroll
            for (int c=0;c<4;c++) acc[a][b][c]=0.f;

#define G_LOAD(chunk, s) do{                                                   \
    uint32_t sA_ = sb + (uint32_t)(s)*32768u; uint32_t sB_ = sA_ + 16384u;     \
    _Pragma("unroll")                                                          \
    for (int i_=0;i_<4;i_++){                                                  \
        int idx_ = tid*4 + i_; int r_ = idx_>>3, u_ = idx_&7;                  \
        cp16(sA_ + (uint32_t)(r_*128 + ((u_^(r_&7))<<4)),                      \
             A2 + (size_t)(rowBase+r_)*K2 + (chunk)*64 + u_*8);                \
        cp16(sB_ + (uint32_t)(r_*128 + ((u_^(r_&7))<<4)),                      \
             B2 + (size_t)(colBase+r_)*K2 + (chunk)*64 + u_*8);                \
    } cp_commit(); } while(0)

    G_LOAD(0, 0);
    if (nC > 1) G_LOAD(1, 1);

    for (int c=0;c<nC;c++){
        int s = c % 3;
        if (c == nC-1) cp_wait0(); else cp_wait1();
        __syncthreads();
        if (c+2 < nC) G_LOAD(c+2, (c+2)%3);
        uint32_t sA = sb + (uint32_t)s*32768u, sB = sA + 16384u;
        #pragma unroll
        for (int ks=0;ks<2;ks++){
            uint32_t ah[4][4], al[4][4], bh4[2][4], bl4[2][4];
            #pragma unroll
            for (int mt=0;mt<4;mt++){
                int r = wr*64 + mt*16 + (lane&15);
                uint32_t uh = ks*2 + (lane>>4);
                ldsm4(ah[mt], sA + r*128 + ((uh^(r&7))<<4));
                ldsm4(al[mt], sA + r*128 + (((uh+4)^(r&7))<<4));
            }
            #pragma unroll
            for (int np=0;np<2;np++){
                int r = wc*32 + np*16 + (lane&15);
                uint32_t uh = ks*2 + (lane>>4);
                ldsm4(bh4[np], sB + r*128 + ((uh^(r&7))<<4));
                ldsm4(bl4[np], sB + r*128 + (((uh+4)^(r&7))<<4));
            }
            // pass-major: all 16 tiles per pass -> accumulator reuse distance 16
            #pragma unroll
            for (int mt=0;mt<4;mt++)
                #pragma unroll
                for (int nt=0;nt<4;nt++)
                    mmabf(acc[mt][nt], ah[mt], bh4[nt>>1][nt&1], bh4[nt>>1][2+(nt&1)]);
            #pragma unroll
            for (int mt=0;mt<4;mt++)
                #pragma unroll
                for (int nt=0;nt<4;nt++)
                    mmabf(acc[mt][nt], al[mt], bh4[nt>>1][nt&1], bh4[nt>>1][2+(nt&1)]);
            #pragma unroll
            for (int mt=0;mt<4;mt++)
                #pragma unroll
                for (int nt=0;nt<4;nt++)
                    mmabf(acc[mt][nt], ah[mt], bl4[nt>>1][nt&1], bl4[nt>>1][2+(nt&1)]);
        }
        __syncthreads();
    }
#undef G_LOAD

    int ra = lane>>2;
    #pragma unroll
    for (int mt=0;mt<4;mt++){
        int r0 = rowBase + wr*64 + mt*16 + ra;
        #pragma unroll
        for (int nt=0;nt<4;nt++){
            int n0 = colBase + wc*32 + nt*8 + 2*(lane&3);
            float* a = acc[mt][nt];
            #pragma unroll
            for (int hh=0;hh<2;hh++){
                int r = r0 + hh*8;
                float v0 = a[2*hh+0], v1 = a[2*hh+1];
                if (EPI==0 || EPI==2){
                    if (EPI==2){ v0 = gelu_exact(v0 + bias[n0]); v1 = gelu_exact(v1 + bias[n0+1]); }
                    int c2 = ((n0>>5)<<6) + (n0&31);
                    split_pair_store(C2 + (size_t)r*(size_t)(2*N) + c2, v0, v1);
                } else {
                    size_t o = (size_t)r*N + n0;
                    if (EPI==1){ v0 += resid[o]; v1 += resid[o+1]; }
                    else       { v0 += bias[n0] + resid[o]; v1 += bias[n0+1] + resid[o+1]; }
                    float2 f2; f2.x=v0; f2.y=v1;
                    *(float2*)(Cf + o) = f2;
                }
            }
        }
    }
}

// ================= Flash attention (mma.sync, bf16 split, register-P) =================
// smem: Qh 16K | Ql 16K | 2 stages x [Kh 8K|Kl 8K|Vh 8K|Vl 8K] = 96KB total
#define A_QH 0u
#define A_QL 16384u
#define A_KV 32768u
#define ATTN_SMEM 98304

__global__ __launch_bounds__(256)
void attn_mma(const bf16* __restrict__ q2, const bf16* __restrict__ k2,
              const bf16* __restrict__ v2, bf16* __restrict__ ctx2)
{
    extern __shared__ char smc[];
    uint32_t sb = smem_u32(smc);
    const int tid = threadIdx.x, lane = tid&31, w = tid>>5;
    const int qt = blockIdx.x, h = blockIdx.y, b = blockIdx.z;
    const int rowQ0 = b*SS + qt*128;
    const int hoff = h*128;               // bf16 offset of head in 1024-wide row

#define KV_LOAD(it, s) do{                                                     \
    uint32_t stg_ = sb + A_KV + (uint32_t)(s)*32768u;                          \
    int rk0_ = b*SS + (it)*64;                                                 \
    _Pragma("unroll")                                                          \
    for (int i_=0;i_<8;i_++){                                                  \
        int idx_ = tid*8 + i_;                                                 \
        const bf16* src_ = (idx_ < 1024) ? k2 : v2;                            \
        uint32_t tb_ = (idx_ < 1024) ? stg_ : (stg_ + 16384u);                 \
        int j_ = idx_ & 1023; int r_ = j_>>4, c_ = (j_>>3)&1, u8_ = j_&7;      \
        uint32_t un_ = (u8_<4) ? (uint32_t)(c_*4 + u8_) : (uint32_t)(c_*4 + u8_ - 4); \
        uint32_t dst_ = tb_ + ((u8_<4)?0u:8192u)                               \
                      + (uint32_t)(r_*128 + ((un_^(r_&7))<<4));                \
        cp16(dst_, src_ + (size_t)(rk0_+r_)*1024 + hoff + c_*64 + u8_*8);      \
    } cp_commit(); } while(0)

    // prologue: Q + KV0 (group 0), KV1 (group 1)
    {
        #pragma unroll
        for (int i=0;i<8;i++){
            int idx = tid*8 + i;
            int r = idx>>4, c = (idx>>3)&1, u8 = idx&7;
            uint32_t un = (u8<4) ? (uint32_t)(c*4 + u8) : (uint32_t)(c*4 + u8 - 4);
            uint32_t dst = sb + ((u8<4)?A_QH:A_QL) + (uint32_t)(r*128 + ((un^(r&7))<<4));
            cp16(dst, q2 + (size_t)(rowQ0+r)*1024 + hoff + c*64 + u8*8);
        }
        KV_LOAD(0, 0);
        KV_LOAD(1, 1);
    }

    uint32_t qh[4][4], ql[4][4];
    float m0=-INFINITY, m1=-INFINITY, l0=0.f, l1=0.f;
    float ctx[8][4];
    #pragma unroll
    for (int nt=0;nt<8;nt++){ ctx[nt][0]=0;ctx[nt][1]=0;ctx[nt][2]=0;ctx[nt][3]=0; }
    const float SCALE = (float)(1.0/(8.0 + 1e-6));

    for (int it=0; it<SS/64; it++){
        int s = it&1;
        if (it == SS/64-1) cp_wait0(); else cp_wait1();
        __syncthreads();
        if (it == 0){
            #pragma unroll
            for (int ks=0;ks<4;ks++){
                int r = w*16 + (lane&15);
                uint32_t u = ks*2 + (lane>>4);
                ldsm4(qh[ks], sb + A_QH + r*128 + ((u^(r&7))<<4));
                ldsm4(ql[ks], sb + A_QL + r*128 + ((u^(r&7))<<4));
            }
        }
        uint32_t sK = sb + A_KV + (uint32_t)s*32768u;
        uint32_t sV = sK + 16384u;

        // ---- QK^T (3-pass, pass-major) ----
        float sc[8][4];
        #pragma unroll
        for (int nt=0;nt<8;nt++){ sc[nt][0]=0;sc[nt][1]=0;sc[nt][2]=0;sc[nt][3]=0; }
        #pragma unroll
        for (int ks=0;ks<4;ks++){
            uint32_t kh4[4][4], kl4[4][4];
            #pragma unroll
            for (int np=0;np<4;np++){
                int r = np*16 + (lane&15);
                uint32_t u = ks*2 + (lane>>4);
                ldsm4(kh4[np], sK + r*128 + ((u^(r&7))<<4));
                ldsm4(kl4[np], sK + 8192 + r*128 + ((u^(r&7))<<4));
            }
            #pragma unroll
            for (int nt=0;nt<8;nt++)
                mmabf(sc[nt], qh[ks], kh4[nt>>1][nt&1], kh4[nt>>1][2+(nt&1)]);
            #pragma unroll
            for (int nt=0;nt<8;nt++)
                mmabf(sc[nt], ql[ks], kh4[nt>>1][nt&1], kh4[nt>>1][2+(nt&1)]);
            #pragma unroll
            for (int nt=0;nt<8;nt++)
                mmabf(sc[nt], qh[ks], kl4[nt>>1][nt&1], kl4[nt>>1][2+(nt&1)]);
        }

        // ---- streaming softmax (rows lane>>2 and +8); P kept in sc ----
        float mxa=-INFINITY, mxb=-INFINITY;
        #pragma unroll
        for (int nt=0;nt<8;nt++){
            sc[nt][0]*=SCALE; sc[nt][1]*=SCALE; sc[nt][2]*=SCALE; sc[nt][3]*=SCALE;
            mxa = fmaxf(mxa, fmaxf(sc[nt][0], sc[nt][1]));
            mxb = fmaxf(mxb, fmaxf(sc[nt][2], sc[nt][3]));
        }
        mxa = fmaxf(mxa, __shfl_xor_sync(0xffffffffu, mxa, 1));
        mxa = fmaxf(mxa, __shfl_xor_sync(0xffffffffu, mxa, 2));
        mxb = fmaxf(mxb, __shfl_xor_sync(0xffffffffu, mxb, 1));
        mxb = fmaxf(mxb, __shfl_xor_sync(0xffffffffu, mxb, 2));
        float na = fmaxf(m0, mxa), nb = fmaxf(m1, mxb);
        float ca = __expf(m0 - na), cb = __expf(m1 - nb);
        m0 = na; m1 = nb;
        float sa = 0.f, sbm = 0.f;
        #pragma unroll
        for (int nt=0;nt<8;nt++){
            float p0 = __expf(sc[nt][0]-na), p1 = __expf(sc[nt][1]-na);
            float p2 = __expf(sc[nt][2]-nb), p3 = __expf(sc[nt][3]-nb);
            sc[nt][0]=p0; sc[nt][1]=p1; sc[nt][2]=p2; sc[nt][3]=p3;
            sa += p0+p1; sbm += p2+p3;
        }
        sa  += __shfl_xor_sync(0xffffffffu, sa, 1);
        sa  += __shfl_xor_sync(0xffffffffu, sa, 2);
        sbm += __shfl_xor_sync(0xffffffffu, sbm, 1);
        sbm += __shfl_xor_sync(0xffffffffu, sbm, 2);
        l0 = l0*ca + sa; l1 = l1*cb + sbm;
        #pragma unroll
        for (int nt=0;nt<8;nt++){ ctx[nt][0]*=ca; ctx[nt][1]*=ca; ctx[nt][2]*=cb; ctx[nt][3]*=cb; }

        // ---- P @ V (3-pass, register-built P fragments, pass-major) ----
        #pragma unroll
        for (int ks=0;ks<4;ks++){
            uint32_t aPh[4], aPl[4];
            packPair(sc[2*ks  ][0], sc[2*ks  ][1], aPh[0], aPl[0]);
            packPair(sc[2*ks  ][2], sc[2*ks  ][3], aPh[1], aPl[1]);
            packPair(sc[2*ks+1][0], sc[2*ks+1][1], aPh[2], aPl[2]);
            packPair(sc[2*ks+1][2], sc[2*ks+1][3], aPh[3], aPl[3]);
            uint32_t vh4[4][4], vl4[4][4];
            #pragma unroll
            for (int np2=0;np2<4;np2++){
                int r = ks*16 + (lane&15);
                uint32_t u = np2*2 + (lane>>4);
                ldsm4t(vh4[np2], sV + r*128 + ((u^(r&7))<<4));
                ldsm4t(vl4[np2], sV + 8192 + r*128 + ((u^(r&7))<<4));
            }
            #pragma unroll
            for (int np2=0;np2<4;np2++)
                #pragma unroll
                for (int q2i=0;q2i<2;q2i++)
                    mmabf(ctx[np2*2+q2i], aPh, vh4[np2][q2i*2], vh4[np2][q2i*2+1]);
            #pragma unroll
            for (int np2=0;np2<4;np2++)
                #pragma unroll
                for (int q2i=0;q2i<2;q2i++)
                    mmabf(ctx[np2*2+q2i], aPl, vh4[np2][q2i*2], vh4[np2][q2i*2+1]);
            #pragma unroll
            for (int np2=0;np2<4;np2++)
                #pragma unroll
                for (int q2i=0;q2i<2;q2i++)
                    mmabf(ctx[np2*2+q2i], aPh, vl4[np2][q2i*2], vl4[np2][q2i*2+1]);
        }
        __syncthreads();
        if (it+2 < SS/64) KV_LOAD(it+2, s);
    }
#undef KV_LOAD

    // ---- normalize + write ctx2 (split layout) ----
    float i0 = 1.0f/l0, i1 = 1.0f/l1;
    #pragma unroll
    for (int nt=0;nt<8;nt++){
        int d = nt*8 + 2*(lane&3);
        int c2 = hoff + ((d>>5)<<6) + (d&31);
        int rA = rowQ0 + w*16 + (lane>>2);
        split_pair_store(ctx2 + (size_t)rA*(2*DD) + c2, ctx[nt][0]*i0, ctx[nt][1]*i0);
        split_pair_store(ctx2 + (size_t)(rA+8)*(2*DD) + c2, ctx[nt][2]*i1, ctx[nt][3]*i1);
    }
}

extern "C" void kernel_launch(void* const* d_in, const int* in_sizes, int n_in,
                              void* d_out, int out_size)
{
    (void)in_sizes; (void)n_in; (void)out_size;
    const float* Q     = (const float*)d_in[0];
    const float* Kin   = (const float*)d_in[1];
    const float* Vin   = (const float*)d_in[2];
    const float* W_q   = (const float*)d_in[3];
    const float* W_k   = (const float*)d_in[4];
    const float* W_v   = (const float*)d_in[5];
    const float* W_o   = (const float*)d_in[6];
    const float* ln1_g = (const float*)d_in[7];
    const float* ln1_b = (const float*)d_in[8];
    const float* ln2_g = (const float*)d_in[9];
    const float* ln2_b = (const float*)d_in[10];
    const float* w1    = (const float*)d_in[11];
    const float* b1    = (const float*)d_in[12];
    const float* w2    = (const float*)d_in[13];
    const float* b2    = (const float*)d_in[14];
    float* out = (float*)d_out;

    bf16 *Qn2,*Kin2,*Vin2,*q2,*k2,*v2,*ctx2,*Xn2,*h2,*Wq2,*Wk2,*Wv2,*Wo2,*w12,*w22;
    float *X;
    cudaGetSymbolAddress((void**)&Qn2,  g_Qn2);
    cudaGetSymbolAddress((void**)&Kin2, g_Kin2);
    cudaGetSymbolAddress((void**)&Vin2, g_Vin2);
    cudaGetSymbolAddress((void**)&q2,   g_q2);
    cudaGetSymbolAddress((void**)&k2,   g_k2);
    cudaGetSymbolAddress((void**)&v2,   g_v2);
    cudaGetSymbolAddress((void**)&ctx2, g_ctx2);
    cudaGetSymbolAddress((void**)&Xn2,  g_Xn2);
    cudaGetSymbolAddress((void**)&h2,   g_h2);
    cudaGetSymbolAddress((void**)&X,    g_X);
    cudaGetSymbolAddress((void**)&Wq2,  g_Wq2);
    cudaGetSymbolAddress((void**)&Wk2,  g_Wk2);
    cudaGetSymbolAddress((void**)&Wv2,  g_Wv2);
    cudaGetSymbolAddress((void**)&Wo2,  g_Wo2);
    cudaGetSymbolAddress((void**)&w12,  g_w12);
    cudaGetSymbolAddress((void**)&w22,  g_w22);

    cudaFuncSetAttribute(attn_mma,    cudaFuncAttributeMaxDynamicSharedMemorySize, ATTN_SMEM);
    cudaFuncSetAttribute(gemm_mma<0>, cudaFuncAttributeMaxDynamicSharedMemorySize, GEMM_SMEM);
    cudaFuncSetAttribute(gemm_mma<1>, cudaFuncAttributeMaxDynamicSharedMemorySize, GEMM_SMEM);
    cudaFuncSetAttribute(gemm_mma<2>, cudaFuncAttributeMaxDynamicSharedMemorySize, GEMM_SMEM);
    cudaFuncSetAttribute(gemm_mma<3>, cudaFuncAttributeMaxDynamicSharedMemorySize, GEMM_SMEM);

    dim3 tb(32, 8), tg(16, 16);

    // conversions
    ln_split<<<ROWS,128>>>(Q, ln1_g, ln1_b, Qn2);
    split_k<<<(ROWS*DD/4+255)/256,256>>>(Kin, Kin2, DD, ROWS*DD/4);
    split_k<<<(ROWS*DD/4+255)/256,256>>>(Vin, Vin2, DD, ROWS*DD/4);
    tsplit<<<tg, tb>>>(W_q, Wq2);
    tsplit<<<tg, tb>>>(W_k, Wk2);
    tsplit<<<tg, tb>>>(W_v, Wv2);
    tsplit<<<tg, tb>>>(W_o, Wo2);
    split_k<<<(DFF*DD/4+255)/256,256>>>(w1, w12, DD, DFF*DD/4);
    split_k<<<(DD*DFF/4+255)/256,256>>>(w2, w22, DFF, DD*DFF/4);

    // projections
    gemm_mma<0><<<dim3(DD/128,  ROWS/128), 256, GEMM_SMEM>>>(Qn2,  Wq2, DD,  DD,  nullptr, nullptr, nullptr, q2);
    gemm_mma<0><<<dim3(DD/128,  ROWS/128), 256, GEMM_SMEM>>>(Kin2, Wk2, DD,  DD,  nullptr, nullptr, nullptr, k2);
    gemm_mma<0><<<dim3(DD/128,  ROWS/128), 256, GEMM_SMEM>>>(Vin2, Wv2, DD,  DD,  nullptr, nullptr, nullptr, v2);
    // attention
    attn_mma<<<dim3(SS/128, HH, BB), 256, ATTN_SMEM>>>(q2, k2, v2, ctx2);
    // X = Q + ctx @ Wo
    gemm_mma<1><<<dim3(DD/128,  ROWS/128), 256, GEMM_SMEM>>>(ctx2, Wo2, DD,  DD,  nullptr, Q, X, nullptr);
    // LN2 + FFN
    ln_split<<<ROWS,128>>>(X, ln2_g, ln2_b, Xn2);
    gemm_mma<2><<<dim3(DFF/128, ROWS/128), 256, GEMM_SMEM>>>(Xn2,  w12, DFF, DD,  b1, nullptr, nullptr, h2);
    gemm_mma<3><<<dim3(DD/128,  ROWS/128), 256, GEMM_SMEM>>>(h2,   w22, DD,  DFF, b2, X, out, nullptr);
}

// round 7
// speedup vs baseline: 2.5457x; 1.1644x over previous
#include <cuda_runtime.h>
#include <cuda_bf16.h>
#include <cuda_fp16.h>
#include <cstdint>
#include <math.h>

#define BB   2
#define SS   4096
#define DD   512
#define HH   8
#define ROWS (BB*SS)
#define DFF  2048

typedef __nv_bfloat16  bf16;
typedef __nv_bfloat162 bf162;

// bf16 split layout: [row][2C] ; col2(k,part) = (k>>5)*64 + (k&31) + 32*part
__device__ bf16 g_Qn2 [ROWS*2*DD];
__device__ bf16 g_Kin2[ROWS*2*DD];
__device__ bf16 g_Vin2[ROWS*2*DD];
__device__ bf16 g_ctx2[ROWS*2*DD];
__device__ bf16 g_Xn2 [ROWS*2*DD];
__device__ bf16 g_h2  [(size_t)ROWS*2*DFF];
__device__ float g_X  [ROWS*DD];
__device__ bf16 g_Wq2 [DD*2*DD];
__device__ bf16 g_Wk2 [DD*2*DD];
__device__ bf16 g_Wv2 [DD*2*DD];
__device__ bf16 g_Wo2 [DD*2*DD];
__device__ bf16 g_w12 [DFF*2*DD];
__device__ bf16 g_w22 [DD*2*DFF];
// fp16 attention operands
__device__ __half g_q2h[ROWS*DD];        // plain [row][512] (hi only)
__device__ __half g_k2h[ROWS*2*DD];      // split [row][1024] hi/lo
__device__ __half g_v2h[ROWS*DD];        // plain [row][512] (hi only)

// ---------------- asm helpers ----------------
__device__ __forceinline__ uint32_t smem_u32(const void* p) {
    uint32_t a;
    asm("{ .reg .u64 t; cvta.to.shared.u64 t, %1; cvt.u32.u64 %0, t; }" : "=r"(a) : "l"(p));
    return a;
}
__device__ __forceinline__ void cp16(uint32_t dst, const void* src){
    asm volatile("cp.async.cg.shared.global [%0], [%1], 16;" :: "r"(dst), "l"(src));
}
__device__ __forceinline__ void cp_commit(){ asm volatile("cp.async.commit_group;" ::: "memory"); }
__device__ __forceinline__ void cp_wait0(){ asm volatile("cp.async.wait_group 0;" ::: "memory"); }
__device__ __forceinline__ void cp_wait1(){ asm volatile("cp.async.wait_group 1;" ::: "memory"); }

__device__ __forceinline__ void ldsm4(uint32_t* r, uint32_t a){
    asm volatile("ldmatrix.sync.aligned.m8n8.x4.shared.b16 {%0,%1,%2,%3}, [%4];"
        : "=r"(r[0]),"=r"(r[1]),"=r"(r[2]),"=r"(r[3]) : "r"(a));
}
__device__ __forceinline__ void ldsm4t(uint32_t* r, uint32_t a){
    asm volatile("ldmatrix.sync.aligned.m8n8.x4.trans.shared.b16 {%0,%1,%2,%3}, [%4];"
        : "=r"(r[0]),"=r"(r[1]),"=r"(r[2]),"=r"(r[3]) : "r"(a));
}
__device__ __forceinline__ void mmabf(float* d, const uint32_t* a, uint32_t b0, uint32_t b1){
    asm volatile("mma.sync.aligned.m16n8k16.row.col.f32.bf16.bf16.f32 "
        "{%0,%1,%2,%3}, {%4,%5,%6,%7}, {%8,%9}, {%0,%1,%2,%3};"
        : "+f"(d[0]),"+f"(d[1]),"+f"(d[2]),"+f"(d[3])
        : "r"(a[0]),"r"(a[1]),"r"(a[2]),"r"(a[3]), "r"(b0), "r"(b1));
}
__device__ __forceinline__ void mmafp(float* d, const uint32_t* a, uint32_t b0, uint32_t b1){
    asm volatile("mma.sync.aligned.m16n8k16.row.col.f32.f16.f16.f32 "
        "{%0,%1,%2,%3}, {%4,%5,%6,%7}, {%8,%9}, {%0,%1,%2,%3};"
        : "+f"(d[0]),"+f"(d[1]),"+f"(d[2]),"+f"(d[3])
        : "r"(a[0]),"r"(a[1]),"r"(a[2]),"r"(a[3]), "r"(b0), "r"(b1));
}
__device__ __forceinline__ float gelu_exact(float x) {
    return 0.5f * x * (1.0f + erff(x * 0.70710678118654752440f));
}
__device__ __forceinline__ void split_pair_store(bf16* base, float v0, float v1){
    bf16 h0 = __float2bfloat16(v0), h1 = __float2bfloat16(v1);
    bf162 hp; hp.x = h0; hp.y = h1;
    *(bf162*)(base) = hp;
    bf162 lp;
    lp.x = __float2bfloat16(v0 - __bfloat162float(h0));
    lp.y = __float2bfloat16(v1 - __bfloat162float(h1));
    *(bf162*)(base + 32) = lp;
}
// pack two fp32 into f16x2 hi + f16x2 residual fragments
__device__ __forceinline__ void packPairH(float a, float b, uint32_t& hi, uint32_t& lo){
    __half ha = __float2half_rn(a), hb = __float2half_rn(b);
    __half2 h; h.x = ha; h.y = hb; hi = *(uint32_t*)&h;
    __half2 l;
    l.x = __float2half_rn(a - __half2float(ha));
    l.y = __float2half_rn(b - __half2float(hb));
    lo = *(uint32_t*)&l;
}

// ---------------- LayerNorm -> bf16 split ----------------
__global__ void ln_split(const float* __restrict__ x, const float* __restrict__ g,
                         const float* __restrict__ b, bf16* __restrict__ y2)
{
    __shared__ float red[8];
    int row = blockIdx.x;
    int t = threadIdx.x;
    float4 v = ((const float4*)(x + (size_t)row*DD))[t];
    float s  = v.x+v.y+v.z+v.w;
    float s2 = v.x*v.x+v.y*v.y+v.z*v.z+v.w*v.w;
    #pragma unroll
    for (int o=16;o>0;o>>=1){
        s  += __shfl_xor_sync(0xffffffffu, s,  o);
        s2 += __shfl_xor_sync(0xffffffffu, s2, o);
    }
    if ((t&31)==0){ red[t>>5]=s; red[4+(t>>5)]=s2; }
    __syncthreads();
    s  = red[0]+red[1]+red[2]+red[3];
    s2 = red[4]+red[5]+red[6]+red[7];
    float mu  = s * (1.0f/DD);
    float var = s2 * (1.0f/DD) - mu*mu;
    float inv = rsqrtf(var + 1e-5f);
    float4 gv = ((const float4*)g)[t];
    float4 bv = ((const float4*)b)[t];
    float o0 = (v.x-mu)*inv*gv.x + bv.x;
    float o1 = (v.y-mu)*inv*gv.y + bv.y;
    float o2 = (v.z-mu)*inv*gv.z + bv.z;
    float o3 = (v.w-mu)*inv*gv.w + bv.w;
    int k = 4*t;
    bf16* yr = y2 + (size_t)row*(2*DD) + ((k>>5)<<6) + (k&31);
    split_pair_store(yr, o0, o1);
    split_pair_store(yr + 2, o2, o3);
}

// ---------------- fp32 [R][C] -> bf16 split [R][2C] ----------------
__global__ void split_k(const float* __restrict__ in, bf16* __restrict__ out,
                        int C, int total4)
{
    int i = blockIdx.x*blockDim.x + threadIdx.x;
    if (i >= total4) return;
    size_t e = (size_t)i*4;
    int r = (int)(e / C); int k = (int)(e % C);
    float4 v = *(const float4*)(in + e);
    bf16* o = out + (size_t)r*2*C + ((k>>5)<<6) + (k&31);
    split_pair_store(o, v.x, v.y);
    split_pair_store(o + 2, v.z, v.w);
}

// ---------------- transpose + split: W[512k][512n] -> out[n][1024] ----------------
__global__ void tsplit(const float* __restrict__ Win, bf16* __restrict__ out)
{
    __shared__ float t[32][33];
    int bk = blockIdx.y*32, bn = blockIdx.x*32;
    int x = threadIdx.x, y = threadIdx.y;
    #pragma unroll
    for (int j=0;j<4;j++)
        t[y+8*j][x] = Win[(size_t)(bk+y+8*j)*DD + bn + x];
    __syncthreads();
    #pragma unroll
    for (int j=0;j<4;j++){
        int n = bn + y + 8*j;
        float v = t[x][y+8*j];
        bf16 hv = __float2bfloat16(v);
        bf16* o = out + (size_t)n*(2*DD) + ((bk>>5)<<6);
        o[x]      = hv;
        o[x + 32] = __float2bfloat16(v - __bfloat162float(hv));
    }
}

// ================= bf16-split GEMM (mma.sync) =================
// C = A2 (*) B2^T, 128x128 tile, 32-k chunks, 3-stage cp.async, pass-major.
// EPI: 1 fp32+resid ; 2 gelu(+bias) bf16-split ; 3 fp32+bias+resid ;
//      4 fp16 plain-hi ; 5 fp16 split
#define GEMM_SMEM (3*32768)

template<int EPI>
__global__ __launch_bounds__(256)
void gemm_mma(const bf16* __restrict__ A2, const bf16* __restrict__ B2,
              int N, int K,
              const float* __restrict__ bias, const float* __restrict__ resid,
              float* __restrict__ Cf, bf16* __restrict__ C2, __half* __restrict__ Ch)
{
    extern __shared__ char smc[];
    uint32_t sb = smem_u32(smc);
    const int tid = threadIdx.x, lane = tid&31, w = tid>>5;
    const int wr = w>>2, wc = w&3;
    const int rowBase = blockIdx.y*128, colBase = blockIdx.x*128;
    const int K2 = 2*K;
    const int nC = K>>5;

    float acc[4][4][4];
    #pragma unroll
    for (int a=0;a<4;a++)
        #pragma unroll
        for (int b=0;b<4;b++)
            #pragma unroll
            for (int c=0;c<4;c++) acc[a][b][c]=0.f;

#define G_LOAD(chunk, s) do{                                                   \
    uint32_t sA_ = sb + (uint32_t)(s)*32768u; uint32_t sB_ = sA_ + 16384u;     \
    _Pragma("unroll")                                                          \
    for (int i_=0;i_<4;i_++){                                                  \
        int idx_ = tid*4 + i_; int r_ = idx_>>3, u_ = idx_&7;                  \
        cp16(sA_ + (uint32_t)(r_*128 + ((u_^(r_&7))<<4)),                      \
             A2 + (size_t)(rowBase+r_)*K2 + (chunk)*64 + u_*8);                \
        cp16(sB_ + (uint32_t)(r_*128 + ((u_^(r_&7))<<4)),                      \
             B2 + (size_t)(colBase+r_)*K2 + (chunk)*64 + u_*8);                \
    } cp_commit(); } while(0)

    G_LOAD(0, 0);
    if (nC > 1) G_LOAD(1, 1);

    for (int c=0;c<nC;c++){
        int s = c % 3;
        if (c == nC-1) cp_wait0(); else cp_wait1();
        __syncthreads();
        if (c+2 < nC) G_LOAD(c+2, (c+2)%3);
        uint32_t sA = sb + (uint32_t)s*32768u, sB = sA + 16384u;
        #pragma unroll
        for (int ks=0;ks<2;ks++){
            uint32_t ah[4][4], al[4][4], bh4[2][4], bl4[2][4];
            #pragma unroll
            for (int mt=0;mt<4;mt++){
                int r = wr*64 + mt*16 + (lane&15);
                uint32_t uh = ks*2 + (lane>>4);
                ldsm4(ah[mt], sA + r*128 + ((uh^(r&7))<<4));
                ldsm4(al[mt], sA + r*128 + (((uh+4)^(r&7))<<4));
            }
            #pragma unroll
            for (int np=0;np<2;np++){
                int r = wc*32 + np*16 + (lane&15);
                uint32_t uh = ks*2 + (lane>>4);
                ldsm4(bh4[np], sB + r*128 + ((uh^(r&7))<<4));
                ldsm4(bl4[np], sB + r*128 + (((uh+4)^(r&7))<<4));
            }
            #pragma unroll
            for (int mt=0;mt<4;mt++)
                #pragma unroll
                for (int nt=0;nt<4;nt++)
                    mmabf(acc[mt][nt], ah[mt], bh4[nt>>1][nt&1], bh4[nt>>1][2+(nt&1)]);
            #pragma unroll
            for (int mt=0;mt<4;mt++)
                #pragma unroll
                for (int nt=0;nt<4;nt++)
                    mmabf(acc[mt][nt], al[mt], bh4[nt>>1][nt&1], bh4[nt>>1][2+(nt&1)]);
            #pragma unroll
            for (int mt=0;mt<4;mt++)
                #pragma unroll
                for (int nt=0;nt<4;nt++)
                    mmabf(acc[mt][nt], ah[mt], bl4[nt>>1][nt&1], bl4[nt>>1][2+(nt&1)]);
        }
        __syncthreads();
    }
#undef G_LOAD

    int ra = lane>>2;
    #pragma unroll
    for (int mt=0;mt<4;mt++){
        int r0 = rowBase + wr*64 + mt*16 + ra;
        #pragma unroll
        for (int nt=0;nt<4;nt++){
            int n0 = colBase + wc*32 + nt*8 + 2*(lane&3);
            float* a = acc[mt][nt];
            #pragma unroll
            for (int hh=0;hh<2;hh++){
                int r = r0 + hh*8;
                float v0 = a[2*hh+0], v1 = a[2*hh+1];
                if (EPI==2){
                    v0 = gelu_exact(v0 + bias[n0]); v1 = gelu_exact(v1 + bias[n0+1]);
                    int c2 = ((n0>>5)<<6) + (n0&31);
                    split_pair_store(C2 + (size_t)r*(size_t)(2*N) + c2, v0, v1);
                } else if (EPI==4){
                    __half2 hp; hp.x = __float2half_rn(v0); hp.y = __float2half_rn(v1);
                    *(__half2*)(Ch + (size_t)r*N + n0) = hp;
                } else if (EPI==5){
                    int c2 = ((n0>>5)<<6) + (n0&31);
                    __half h0 = __float2half_rn(v0), h1 = __float2half_rn(v1);
                    __half2 hp; hp.x=h0; hp.y=h1;
                    *(__half2*)(Ch + (size_t)r*(size_t)(2*N) + c2) = hp;
                    __half2 lp;
                    lp.x = __float2half_rn(v0 - __half2float(h0));
                    lp.y = __float2half_rn(v1 - __half2float(h1));
                    *(__half2*)(Ch + (size_t)r*(size_t)(2*N) + c2 + 32) = lp;
                } else {
                    size_t o = (size_t)r*N + n0;
                    if (EPI==1){ v0 += resid[o]; v1 += resid[o+1]; }
                    else       { v0 += bias[n0] + resid[o]; v1 += bias[n0+1] + resid[o+1]; }
                    float2 f2; f2.x=v0; f2.y=v1;
                    *(float2*)(Cf + o) = f2;
                }
            }
        }
    }
}

// ================= Flash attention (fp16 2-pass mma.sync) =================
// smem: Qh 16K | 2 stages x [Kh 8K|Kl 8K|Vh 8K] = 64KB total
#define A_QH 0u
#define A_KV 16384u
#define ATTN_SMEM 65536

__global__ __launch_bounds__(256)
void attn_mma(const __half* __restrict__ q2h, const __half* __restrict__ k2h,
              const __half* __restrict__ v2h, bf16* __restrict__ ctx2)
{
    extern __shared__ char smc[];
    uint32_t sb = smem_u32(smc);
    const int tid = threadIdx.x, lane = tid&31, w = tid>>5;
    const int qt = blockIdx.x, h = blockIdx.y, b = blockIdx.z;
    const int rowQ0 = b*SS + qt*128;

#define KV_LOAD(it, s) do{                                                     \
    uint32_t stg_ = sb + A_KV + (uint32_t)(s)*24576u;                          \
    int rk0_ = b*SS + (it)*64;                                                 \
    _Pragma("unroll")                                                          \
    for (int i_=0;i_<6;i_++){                                                  \
        int idx_ = tid*6 + i_;                                                 \
        if (idx_ < 1024){                                                      \
            int r_ = idx_>>4, us_ = idx_&15;                                   \
            uint32_t plane_ = (uint32_t)((us_>>2)&1);                          \
            uint32_t du_ = (uint32_t)((us_&3) + ((us_>>3)<<2));                \
            cp16(stg_ + plane_*8192u + (uint32_t)(r_*128 + ((du_^(r_&7))<<4)), \
                 k2h + (size_t)(rk0_+r_)*1024 + h*128 + us_*8);                \
        } else {                                                               \
            int j_ = idx_ - 1024; int r_ = j_>>3, u_ = j_&7;                   \
            cp16(stg_ + 16384u + (uint32_t)(r_*128 + (((uint32_t)u_^(r_&7))<<4)), \
                 v2h + (size_t)(rk0_+r_)*512 + h*64 + u_*8);                   \
        }                                                                      \
    } cp_commit(); } while(0)

    // prologue: Q (rides in group 0) + KV0, then KV1
    {
        #pragma unroll
        for (int i=0;i<4;i++){
            int idx = tid*4 + i;
            int r = idx>>3, u = idx&7;
            cp16(sb + A_QH + (uint32_t)(r*128 + (((uint32_t)u^(r&7))<<4)),
                 q2h + (size_t)(rowQ0+r)*512 + h*64 + u*8);
        }
        KV_LOAD(0, 0);
        KV_LOAD(1, 1);
    }

    uint32_t qh[4][4];
    float m0=-INFINITY, m1=-INFINITY, l0=0.f, l1=0.f;
    float ctx[8][4];
    #pragma unroll
    for (int nt=0;nt<8;nt++){ ctx[nt][0]=0;ctx[nt][1]=0;ctx[nt][2]=0;ctx[nt][3]=0; }
    const float SCALE = (float)(1.0/(8.0 + 1e-6));

    for (int it=0; it<SS/64; it++){
        int s = it&1;
        if (it == SS/64-1) cp_wait0(); else cp_wait1();
        __syncthreads();
        if (it == 0){
            #pragma unroll
            for (int ks=0;ks<4;ks++){
                int r = w*16 + (lane&15);
                uint32_t u = ks*2 + (lane>>4);
                ldsm4(qh[ks], sb + A_QH + r*128 + ((u^(r&7))<<4));
            }
        }
        uint32_t sK = sb + A_KV + (uint32_t)s*24576u;
        uint32_t sKl = sK + 8192u;
        uint32_t sV = sK + 16384u;

        // ---- QK^T: Qh*Kh + Qh*Kl (2-pass, pass-major) ----
        float sc[8][4];
        #pragma unroll
        for (int nt=0;nt<8;nt++){ sc[nt][0]=0;sc[nt][1]=0;sc[nt][2]=0;sc[nt][3]=0; }
        #pragma unroll
        for (int ks=0;ks<4;ks++){
            uint32_t kh4[4][4], kl4[4][4];
            #pragma unroll
            for (int np=0;np<4;np++){
                int r = np*16 + (lane&15);
                uint32_t u = ks*2 + (lane>>4);
                ldsm4(kh4[np], sK  + r*128 + ((u^(r&7))<<4));
                ldsm4(kl4[np], sKl + r*128 + ((u^(r&7))<<4));
            }
            #pragma unroll
            for (int nt=0;nt<8;nt++)
                mmafp(sc[nt], qh[ks], kh4[nt>>1][nt&1], kh4[nt>>1][2+(nt&1)]);
            #pragma unroll
            for (int nt=0;nt<8;nt++)
                mmafp(sc[nt], qh[ks], kl4[nt>>1][nt&1], kl4[nt>>1][2+(nt&1)]);
        }

        // ---- streaming softmax (rows lane>>2 and +8) ----
        float mxa=-INFINITY, mxb=-INFINITY;
        #pragma unroll
        for (int nt=0;nt<8;nt++){
            sc[nt][0]*=SCALE; sc[nt][1]*=SCALE; sc[nt][2]*=SCALE; sc[nt][3]*=SCALE;
            mxa = fmaxf(mxa, fmaxf(sc[nt][0], sc[nt][1]));
            mxb = fmaxf(mxb, fmaxf(sc[nt][2], sc[nt][3]));
        }
        mxa = fmaxf(mxa, __shfl_xor_sync(0xffffffffu, mxa, 1));
        mxa = fmaxf(mxa, __shfl_xor_sync(0xffffffffu, mxa, 2));
        mxb = fmaxf(mxb, __shfl_xor_sync(0xffffffffu, mxb, 1));
        mxb = fmaxf(mxb, __shfl_xor_sync(0xffffffffu, mxb, 2));
        float na = fmaxf(m0, mxa), nb = fmaxf(m1, mxb);
        float ca = __expf(m0 - na), cb = __expf(m1 - nb);
        m0 = na; m1 = nb;
        float sa = 0.f, sbm = 0.f;
        #pragma unroll
        for (int nt=0;nt<8;nt++){
            float p0 = __expf(sc[nt][0]-na), p1 = __expf(sc[nt][1]-na);
            float p2 = __expf(sc[nt][2]-nb), p3 = __expf(sc[nt][3]-nb);
            sc[nt][0]=p0; sc[nt][1]=p1; sc[nt][2]=p2; sc[nt][3]=p3;
            sa += p0+p1; sbm += p2+p3;
        }
        sa  += __shfl_xor_sync(0xffffffffu, sa, 1);
        sa  += __shfl_xor_sync(0xffffffffu, sa, 2);
        sbm += __shfl_xor_sync(0xffffffffu, sbm, 1);
        sbm += __shfl_xor_sync(0xffffffffu, sbm, 2);
        l0 = l0*ca + sa; l1 = l1*cb + sbm;
        #pragma unroll
        for (int nt=0;nt<8;nt++){ ctx[nt][0]*=ca; ctx[nt][1]*=ca; ctx[nt][2]*=cb; ctx[nt][3]*=cb; }

        // ---- P @ V: Ph*Vh + Pl*Vh (2-pass, register P frags) ----
        #pragma unroll
        for (int ks=0;ks<4;ks++){
            uint32_t aPh[4], aPl[4];
            packPairH(sc[2*ks  ][0], sc[2*ks  ][1], aPh[0], aPl[0]);
            packPairH(sc[2*ks  ][2], sc[2*ks  ][3], aPh[1], aPl[1]);
            packPairH(sc[2*ks+1][0], sc[2*ks+1][1], aPh[2], aPl[2]);
            packPairH(sc[2*ks+1][2], sc[2*ks+1][3], aPh[3], aPl[3]);
            uint32_t vh4[4][4];
            #pragma unroll
            for (int np2=0;np2<4;np2++){
                int r = ks*16 + (lane&15);
                uint32_t u = np2*2 + (lane>>4);
                ldsm4t(vh4[np2], sV + r*128 + ((u^(r&7))<<4));
            }
            #pragma unroll
            for (int np2=0;np2<4;np2++)
                #pragma unroll
                for (int q2i=0;q2i<2;q2i++)
                    mmafp(ctx[np2*2+q2i], aPh, vh4[np2][q2i*2], vh4[np2][q2i*2+1]);
            #pragma unroll
            for (int np2=0;np2<4;np2++)
                #pragma unroll
                for (int q2i=0;q2i<2;q2i++)
                    mmafp(ctx[np2*2+q2i], aPl, vh4[np2][q2i*2], vh4[np2][q2i*2+1]);
        }
        __syncthreads();
        if (it+2 < SS/64) KV_LOAD(it+2, s);
    }
#undef KV_LOAD

    // ---- normalize + write ctx2 (bf16 split layout) ----
    float i0 = 1.0f/l0, i1 = 1.0f/l1;
    int hoff = h*128;
    #pragma unroll
    for (int nt=0;nt<8;nt++){
        int d = nt*8 + 2*(lane&3);
        int c2 = hoff + ((d>>5)<<6) + (d&31);
        int rA = rowQ0 + w*16 + (lane>>2);
        split_pair_store(ctx2 + (size_t)rA*(2*DD) + c2, ctx[nt][0]*i0, ctx[nt][1]*i0);
        split_pair_store(ctx2 + (size_t)(rA+8)*(2*DD) + c2, ctx[nt][2]*i1, ctx[nt][3]*i1);
    }
}

extern "C" void kernel_launch(void* const* d_in, const int* in_sizes, int n_in,
                              void* d_out, int out_size)
{
    (void)in_sizes; (void)n_in; (void)out_size;
    const float* Q     = (const float*)d_in[0];
    const float* Kin   = (const float*)d_in[1];
    const float* Vin   = (const float*)d_in[2];
    const float* W_q   = (const float*)d_in[3];
    const float* W_k   = (const float*)d_in[4];
    const float* W_v   = (const float*)d_in[5];
    const float* W_o   = (const float*)d_in[6];
    const float* ln1_g = (const float*)d_in[7];
    const float* ln1_b = (const float*)d_in[8];
    const float* ln2_g = (const float*)d_in[9];
    const float* ln2_b = (const float*)d_in[10];
    const float* w1    = (const float*)d_in[11];
    const float* b1    = (const float*)d_in[12];
    const float* w2    = (const float*)d_in[13];
    const float* b2    = (const float*)d_in[14];
    float* out = (float*)d_out;

    bf16 *Qn2,*Kin2,*Vin2,*ctx2,*Xn2,*h2,*Wq2,*Wk2,*Wv2,*Wo2,*w12,*w22;
    __half *q2h,*k2h,*v2h;
    float *X;
    cudaGetSymbolAddress((void**)&Qn2,  g_Qn2);
    cudaGetSymbolAddress((void**)&Kin2, g_Kin2);
    cudaGetSymbolAddress((void**)&Vin2, g_Vin2);
    cudaGetSymbolAddress((void**)&ctx2, g_ctx2);
    cudaGetSymbolAddress((void**)&Xn2,  g_Xn2);
    cudaGetSymbolAddress((void**)&h2,   g_h2);
    cudaGetSymbolAddress((void**)&X,    g_X);
    cudaGetSymbolAddress((void**)&Wq2,  g_Wq2);
    cudaGetSymbolAddress((void**)&Wk2,  g_Wk2);
    cudaGetSymbolAddress((void**)&Wv2,  g_Wv2);
    cudaGetSymbolAddress((void**)&Wo2,  g_Wo2);
    cudaGetSymbolAddress((void**)&w12,  g_w12);
    cudaGetSymbolAddress((void**)&w22,  g_w22);
    cudaGetSymbolAddress((void**)&q2h,  g_q2h);
    cudaGetSymbolAddress((void**)&k2h,  g_k2h);
    cudaGetSymbolAddress((void**)&v2h,  g_v2h);

    cudaFuncSetAttribute(attn_mma,    cudaFuncAttributeMaxDynamicSharedMemorySize, ATTN_SMEM);
    cudaFuncSetAttribute(gemm_mma<1>, cudaFuncAttributeMaxDynamicSharedMemorySize, GEMM_SMEM);
    cudaFuncSetAttribute(gemm_mma<2>, cudaFuncAttributeMaxDynamicSharedMemorySize, GEMM_SMEM);
    cudaFuncSetAttribute(gemm_mma<3>, cudaFuncAttributeMaxDynamicSharedMemorySize, GEMM_SMEM);
    cudaFuncSetAttribute(gemm_mma<4>, cudaFuncAttributeMaxDynamicSharedMemorySize, GEMM_SMEM);
    cudaFuncSetAttribute(gemm_mma<5>, cudaFuncAttributeMaxDynamicSharedMemorySize, GEMM_SMEM);

    dim3 tb(32, 8), tg(16, 16);

    // conversions
    ln_split<<<ROWS,128>>>(Q, ln1_g, ln1_b, Qn2);
    split_k<<<(ROWS*DD/4+255)/256,256>>>(Kin, Kin2, DD, ROWS*DD/4);
    split_k<<<(ROWS*DD/4+255)/256,256>>>(Vin, Vin2, DD, ROWS*DD/4);
    tsplit<<<tg, tb>>>(W_q, Wq2);
    tsplit<<<tg, tb>>>(W_k, Wk2);
    tsplit<<<tg, tb>>>(W_v, Wv2);
    tsplit<<<tg, tb>>>(W_o, Wo2);
    split_k<<<(DFF*DD/4+255)/256,256>>>(w1, w12, DD, DFF*DD/4);
    split_k<<<(DD*DFF/4+255)/256,256>>>(w2, w22, DFF, DD*DFF/4);

    // projections -> fp16 attention operands
    gemm_mma<4><<<dim3(DD/128,  ROWS/128), 256, GEMM_SMEM>>>(Qn2,  Wq2, DD,  DD,  nullptr, nullptr, nullptr, nullptr, q2h);
    gemm_mma<5><<<dim3(DD/128,  ROWS/128), 256, GEMM_SMEM>>>(Kin2, Wk2, DD,  DD,  nullptr, nullptr, nullptr, nullptr, k2h);
    gemm_mma<4><<<dim3(DD/128,  ROWS/128), 256, GEMM_SMEM>>>(Vin2, Wv2, DD,  DD,  nullptr, nullptr, nullptr, nullptr, v2h);
    // attention
    attn_mma<<<dim3(SS/128, HH, BB), 256, ATTN_SMEM>>>(q2h, k2h, v2h, ctx2);
    // X = Q + ctx @ Wo
    gemm_mma<1><<<dim3(DD/128,  ROWS/128), 256, GEMM_SMEM>>>(ctx2, Wo2, DD,  DD,  nullptr, Q, X, nullptr, nullptr);
    // LN2 + FFN
    ln_split<<<ROWS,128>>>(X, ln2_g, ln2_b, Xn2);
    gemm_mma<2><<<dim3(DFF/128, ROWS/128), 256, GEMM_SMEM>>>(Xn2,  w12, DFF, DD,  b1, nullptr, nullptr, h2, nullptr);
    gemm_mma<3><<<dim3(DD/128,  ROWS/128), 256, GEMM_SMEM>>>(h2,   w22, DD,  DFF, b2, X, out, nullptr, nullptr);
}

// round 9
// speedup vs baseline: 2.9544x; 1.1606x over previous
#include <cuda_runtime.h>
#include <cuda_fp16.h>
#include <cstdint>
#include <math.h>

#define BB   2
#define SS   4096
#define DD   512
#define HH   8
#define ROWS (BB*SS)
#define DFF  2048

// activations: plain fp16 [row][C]
__device__ __half g_QnH [ROWS*DD];
__device__ __half g_KinH[ROWS*DD];
__device__ __half g_VinH[ROWS*DD];
__device__ __half g_q2h [ROWS*DD];
__device__ __half g_k2h [ROWS*2*DD];   // split, 32-block layout (attention loader)
__device__ __half g_v2h [ROWS*DD];
__device__ __half g_ctxH[ROWS*DD];
__device__ __half g_XnH [ROWS*DD];
__device__ __half g_hH  [(size_t)ROWS*DFF];
__device__ float  g_X   [ROWS*DD];
// weights: fp16 split, 64-block layout [n][2K]
__device__ __half g_WqH [DD*2*DD];
__device__ __half g_WkH [DD*2*DD];
__device__ __half g_WvH [DD*2*DD];
__device__ __half g_WoH [DD*2*DD];
__device__ __half g_w1H [DFF*2*DD];
__device__ __half g_w2H [DD*2*DFF];

// ---------------- asm helpers ----------------
__device__ __forceinline__ uint32_t smem_u32(const void* p) {
    uint32_t a;
    asm("{ .reg .u64 t; cvta.to.shared.u64 t, %1; cvt.u32.u64 %0, t; }" : "=r"(a) : "l"(p));
    return a;
}
__device__ __forceinline__ void cp16(uint32_t dst, const void* src){
    asm volatile("cp.async.cg.shared.global [%0], [%1], 16;" :: "r"(dst), "l"(src));
}
__device__ __forceinline__ void cp_commit(){ asm volatile("cp.async.commit_group;" ::: "memory"); }
__device__ __forceinline__ void cp_wait0(){ asm volatile("cp.async.wait_group 0;" ::: "memory"); }
__device__ __forceinline__ void cp_wait1(){ asm volatile("cp.async.wait_group 1;" ::: "memory"); }

__device__ __forceinline__ void ldsm4(uint32_t* r, uint32_t a){
    asm volatile("ldmatrix.sync.aligned.m8n8.x4.shared.b16 {%0,%1,%2,%3}, [%4];"
        : "=r"(r[0]),"=r"(r[1]),"=r"(r[2]),"=r"(r[3]) : "r"(a));
}
__device__ __forceinline__ void ldsm4t(uint32_t* r, uint32_t a){
    asm volatile("ldmatrix.sync.aligned.m8n8.x4.trans.shared.b16 {%0,%1,%2,%3}, [%4];"
        : "=r"(r[0]),"=r"(r[1]),"=r"(r[2]),"=r"(r[3]) : "r"(a));
}
__device__ __forceinline__ void mmafp(float* d, const uint32_t* a, uint32_t b0, uint32_t b1){
    asm volatile("mma.sync.aligned.m16n8k16.row.col.f32.f16.f16.f32 "
        "{%0,%1,%2,%3}, {%4,%5,%6,%7}, {%8,%9}, {%0,%1,%2,%3};"
        : "+f"(d[0]),"+f"(d[1]),"+f"(d[2]),"+f"(d[3])
        : "r"(a[0]),"r"(a[1]),"r"(a[2]),"r"(a[3]), "r"(b0), "r"(b1));
}
__device__ __forceinline__ float gelu_exact(float x) {
    return 0.5f * x * (1.0f + erff(x * 0.70710678118654752440f));
}
__device__ __forceinline__ void packPairH(float a, float b, uint32_t& hi, uint32_t& lo){
    __half ha = __float2half_rn(a), hb = __float2half_rn(b);
    __half2 h; h.x = ha; h.y = hb; hi = *(uint32_t*)&h;
    __half2 l;
    l.x = __float2half_rn(a - __half2float(ha));
    l.y = __float2half_rn(b - __half2float(hb));
    lo = *(uint32_t*)&l;
}
__device__ __forceinline__ __half2 h2of(float a, float b){
    __half2 h; h.x = __float2half_rn(a); h.y = __float2half_rn(b); return h;
}

// ---------------- LayerNorm -> fp16 plain ----------------
__global__ void ln_h(const float* __restrict__ x, const float* __restrict__ g,
                     const float* __restrict__ b, __half* __restrict__ y)
{
    __shared__ float red[8];
    int row = blockIdx.x;
    int t = threadIdx.x;
    float4 v = ((const float4*)(x + (size_t)row*DD))[t];
    float s  = v.x+v.y+v.z+v.w;
    float s2 = v.x*v.x+v.y*v.y+v.z*v.z+v.w*v.w;
    #pragma unroll
    for (int o=16;o>0;o>>=1){
        s  += __shfl_xor_sync(0xffffffffu, s,  o);
        s2 += __shfl_xor_sync(0xffffffffu, s2, o);
    }
    if ((t&31)==0){ red[t>>5]=s; red[4+(t>>5)]=s2; }
    __syncthreads();
    s  = red[0]+red[1]+red[2]+red[3];
    s2 = red[4]+red[5]+red[6]+red[7];
    float mu  = s * (1.0f/DD);
    float var = s2 * (1.0f/DD) - mu*mu;
    float inv = rsqrtf(var + 1e-5f);
    float4 gv = ((const float4*)g)[t];
    float4 bv = ((const float4*)b)[t];
    __half* yr = y + (size_t)row*DD + 4*t;
    *(__half2*)(yr)   = h2of((v.x-mu)*inv*gv.x + bv.x, (v.y-mu)*inv*gv.y + bv.y);
    *(__half2*)(yr+2) = h2of((v.z-mu)*inv*gv.z + bv.z, (v.w-mu)*inv*gv.w + bv.w);
}

// ---------------- fp32 -> fp16 plain ----------------
__global__ void toH(const float* __restrict__ in, __half* __restrict__ out, int total4)
{
    int i = blockIdx.x*blockDim.x + threadIdx.x;
    if (i >= total4) return;
    size_t e = (size_t)i*4;
    float4 v = *(const float4*)(in + e);
    *(__half2*)(out + e)     = h2of(v.x, v.y);
    *(__half2*)(out + e + 2) = h2of(v.z, v.w);
}

// ---------------- fp32 [R][C] -> fp16 split [R][2C], 64-block ----------------
__global__ void splitH(const float* __restrict__ in, __half* __restrict__ out,
                       int C, int total4)
{
    int i = blockIdx.x*blockDim.x + threadIdx.x;
    if (i >= total4) return;
    size_t e = (size_t)i*4;
    int r = (int)(e / C); int k = (int)(e % C);
    float4 v = *(const float4*)(in + e);
    __half* o = out + (size_t)r*2*C + ((k>>6)*128) + (k&63);
    __half h0=__float2half_rn(v.x), h1=__float2half_rn(v.y);
    __half h2=__float2half_rn(v.z), h3=__float2half_rn(v.w);
    __half2 t;
    t.x=h0; t.y=h1; *(__half2*)(o) = t;
    t.x=h2; t.y=h3; *(__half2*)(o+2) = t;
    t.x=__float2half_rn(v.x-__half2float(h0)); t.y=__float2half_rn(v.y-__half2float(h1));
    *(__half2*)(o+64) = t;
    t.x=__float2half_rn(v.z-__half2float(h2)); t.y=__float2half_rn(v.w-__half2float(h3));
    *(__half2*)(o+66) = t;
}

// ---------------- transpose + split: W[512k][512n] -> out[n][1024], 64-block ----------------
__global__ void tsplitH(const float* __restrict__ Win, __half* __restrict__ out)
{
    __shared__ float t[32][33];
    int bk = blockIdx.y*32, bn = blockIdx.x*32;
    int x = threadIdx.x, y = threadIdx.y;
    #pragma unroll
    for (int j=0;j<4;j++)
        t[y+8*j][x] = Win[(size_t)(bk+y+8*j)*DD + bn + x];
    __syncthreads();
    #pragma unroll
    for (int j=0;j<4;j++){
        int n = bn + y + 8*j;
        float v = t[x][y+8*j];
        __half hv = __float2half_rn(v);
        __half* o = out + (size_t)n*(2*DD) + ((bk>>6)*128) + (bk&32);
        o[x]      = hv;
        o[x + 64] = __float2half_rn(v - __half2float(hv));
    }
}

// ================= fp16 2-pass GEMM (mma.sync) =================
// C = A (*) B2^T : A plain fp16 [M][K], B2 split fp16 [N][2K] (64-block).
// 128x128 tile, 64-k chunks, 2-stage cp.async, pass-major.
// EPI: 1 fp32+resid ; 2 gelu(+bias)->fp16 plain ; 3 fp32+bias+resid ;
//      4 fp16 plain ; 5 fp16 split(32-block, for attention K)
#define GH_STAGE 49152
#define GH_SMEM  (2*GH_STAGE)

template<int EPI>
__global__ __launch_bounds__(256,2)
void gemm_h(const __half* __restrict__ A, const __half* __restrict__ B2,
            int N, int K,
            const float* __restrict__ bias, const float* __restrict__ resid,
            float* __restrict__ Cf, __half* __restrict__ Ch)
{
    extern __shared__ char smc[];
    uint32_t sb = smem_u32(smc);
    const int tid = threadIdx.x, lane = tid&31, w = tid>>5;
    const int wr = w>>2, wc = w&3;
    const int rowBase = blockIdx.y*128, colBase = blockIdx.x*128;
    const int K2 = 2*K;
    const int nC = K>>6;

    float acc[4][4][4];
    #pragma unroll
    for (int a=0;a<4;a++)
        #pragma unroll
        for (int b=0;b<4;b++)
            #pragma unroll
            for (int c=0;c<4;c++) acc[a][b][c]=0.f;

#define H_LOAD(chunk, s) do{                                                   \
    uint32_t sA_ = sb + (uint32_t)(s)*GH_STAGE;                                \
    uint32_t sBh_ = sA_ + 16384u, sBl_ = sA_ + 32768u;                         \
    _Pragma("unroll")                                                          \
    for (int i_=0;i_<4;i_++){                                                  \
        int idx_ = tid*4 + i_; int r_ = idx_>>3, u_ = idx_&7;                  \
        cp16(sA_ + (uint32_t)(r_*128 + ((u_^(r_&7))<<4)),                      \
             A + (size_t)(rowBase+r_)*K + (chunk)*64 + u_*8);                  \
    }                                                                          \
    _Pragma("unroll")                                                          \
    for (int i_=0;i_<8;i_++){                                                  \
        int idx_ = tid*8 + i_; int r_ = idx_>>4, us_ = idx_&15;                \
        int u_ = us_&7, pl_ = us_>>3;                                          \
        cp16((pl_?sBl_:sBh_) + (uint32_t)(r_*128 + ((u_^(r_&7))<<4)),          \
             B2 + (size_t)(colBase+r_)*K2 + (chunk)*128 + pl_*64 + u_*8);      \
    } cp_commit(); } while(0)

    H_LOAD(0, 0);
    if (nC > 1) H_LOAD(1, 1);

    for (int c=0;c<nC;c++){
        int s = c & 1;
        if (c == nC-1) cp_wait0(); else cp_wait1();
        __syncthreads();
        uint32_t sA = sb + (uint32_t)s*GH_STAGE;
        uint32_t sBh = sA + 16384u, sBl = sA + 32768u;
        #pragma unroll
        for (int ks=0;ks<4;ks++){
            uint32_t ah[4][4], bh4[2][4], bl4[2][4];
            #pragma unroll
            for (int mt=0;mt<4;mt++){
                int r = wr*64 + mt*16 + (lane&15);
                uint32_t u = ks*2 + (lane>>4);
                ldsm4(ah[mt], sA + r*128 + ((u^(r&7))<<4));
            }
            #pragma unroll
            for (int np=0;np<2;np++){
                int r = wc*32 + np*16 + (lane&15);
                uint32_t u = ks*2 + (lane>>4);
                ldsm4(bh4[np], sBh + r*128 + ((u^(r&7))<<4));
                ldsm4(bl4[np], sBl + r*128 + ((u^(r&7))<<4));
            }
            #pragma unroll
            for (int mt=0;mt<4;mt++)
                #pragma unroll
                for (int nt=0;nt<4;nt++)
                    mmafp(acc[mt][nt], ah[mt], bh4[nt>>1][nt&1], bh4[nt>>1][2+(nt&1)]);
            #pragma unroll
            for (int mt=0;mt<4;mt++)
                #pragma unroll
                for (int nt=0;nt<4;nt++)
                    mmafp(acc[mt][nt], ah[mt], bl4[nt>>1][nt&1], bl4[nt>>1][2+(nt&1)]);
        }
        __syncthreads();
        if (c+2 < nC) H_LOAD(c+2, s);
    }
#undef H_LOAD

    int ra = lane>>2;
    #pragma unroll
    for (int mt=0;mt<4;mt++){
        int r0 = rowBase + wr*64 + mt*16 + ra;
        #pragma unroll
        for (int nt=0;nt<4;nt++){
            int n0 = colBase + wc*32 + nt*8 + 2*(lane&3);
            float* a = acc[mt][nt];
            #pragma unroll
            for (int hh=0;hh<2;hh++){
                int r = r0 + hh*8;
                float v0 = a[2*hh+0], v1 = a[2*hh+1];
                if (EPI==2){
                    v0 = gelu_exact(v0 + bias[n0]); v1 = gelu_exact(v1 + bias[n0+1]);
                    *(__half2*)(Ch + (size_t)r*N + n0) = h2of(v0, v1);
                } else if (EPI==4){
                    *(__half2*)(Ch + (size_t)r*N + n0) = h2of(v0, v1);
                } else if (EPI==5){
                    int c2 = ((n0>>5)<<6) + (n0&31);
                    __half h0 = __float2half_rn(v0), h1 = __float2half_rn(v1);
                    __half2 hp; hp.x=h0; hp.y=h1;
                    *(__half2*)(Ch + (size_t)r*(size_t)(2*N) + c2) = hp;
                    __half2 lp;
                    lp.x = __float2half_rn(v0 - __half2float(h0));
                    lp.y = __float2half_rn(v1 - __half2float(h1));
                    *(__half2*)(Ch + (size_t)r*(size_t)(2*N) + c2 + 32) = lp;
                } else {
                    size_t o = (size_t)r*N + n0;
                    if (EPI==1){ v0 += resid[o]; v1 += resid[o+1]; }
                    else       { v0 += bias[n0] + resid[o]; v1 += bias[n0+1] + resid[o+1]; }
                    float2 f2; f2.x=v0; f2.y=v1;
                    *(float2*)(Cf + o) = f2;
                }
            }
        }
    }
}

// ================= Flash attention (fp16 2-pass mma.sync) =================
// smem: Qh 16K | 2 stages x [Kh 8K|Kl 8K|Vh 8K] = 64KB total
#define A_QH 0u
#define A_KV 16384u
#define ATTN_SMEM 65536

__global__ __launch_bounds__(256)
void attn_mma(const __half* __restrict__ q2h, const __half* __restrict__ k2h,
              const __half* __restrict__ v2h, __half* __restrict__ ctxH)
{
    extern __shared__ char smc[];
    uint32_t sb = smem_u32(smc);
    const int tid = threadIdx.x, lane = tid&31, w = tid>>5;
    const int qt = blockIdx.x, h = blockIdx.y, b = blockIdx.z;
    const int rowQ0 = b*SS + qt*128;

#define KV_LOAD(it, s) do{                                                     \
    uint32_t stg_ = sb + A_KV + (uint32_t)(s)*24576u;                          \
    int rk0_ = b*SS + (it)*64;                                                 \
    _Pragma("unroll")                                                          \
    for (int i_=0;i_<6;i_++){                                                  \
        int idx_ = tid*6 + i_;                                                 \
        if (idx_ < 1024){                                                      \
            int r_ = idx_>>4, us_ = idx_&15;                                   \
            uint32_t plane_ = (uint32_t)((us_>>2)&1);                          \
            uint32_t du_ = (uint32_t)((us_&3) + ((us_>>3)<<2));                \
        cp16(stg_ + plane_*8192u + (uint32_t)(r_*128 + ((du_^(r_&7))<<4)),     \
                 k2h + (size_t)(rk0_+r_)*1024 + h*128 + us_*8);                \
        } else {                                                               \
            int j_ = idx_ - 1024; int r_ = j_>>3, u_ = j_&7;                   \
            cp16(stg_ + 16384u + (uint32_t)(r_*128 + (((uint32_t)u_^(r_&7))<<4)), \
                 v2h + (size_t)(rk0_+r_)*512 + h*64 + u_*8);                   \
        }                                                                      \
    } cp_commit(); } while(0)

    {
        #pragma unroll
        for (int i=0;i<4;i++){
            int idx = tid*4 + i;
            int r = idx>>3, u = idx&7;
            cp16(sb + A_QH + (uint32_t)(r*128 + (((uint32_t)u^(r&7))<<4)),
                 q2h + (size_t)(rowQ0+r)*512 + h*64 + u*8);
        }
        KV_LOAD(0, 0);
        KV_LOAD(1, 1);
    }

    uint32_t qh[4][4];
    float m0=-INFINITY, m1=-INFINITY, l0=0.f, l1=0.f;
    float ctx[8][4];
    #pragma unroll
    for (int nt=0;nt<8;nt++){ ctx[nt][0]=0;ctx[nt][1]=0;ctx[nt][2]=0;ctx[nt][3]=0; }
    const float SCALE = (float)(1.0/(8.0 + 1e-6));

    for (int it=0; it<SS/64; it++){
        int s = it&1;
        if (it == SS/64-1) cp_wait0(); else cp_wait1();
        __syncthreads();
        if (it == 0){
            #pragma unroll
            for (int ks=0;ks<4;ks++){
                int r = w*16 + (lane&15);
                uint32_t u = ks*2 + (lane>>4);
                ldsm4(qh[ks], sb + A_QH + r*128 + ((u^(r&7))<<4));
            }
        }
        uint32_t sK = sb + A_KV + (uint32_t)s*24576u;
        uint32_t sKl = sK + 8192u;
        uint32_t sV = sK + 16384u;

        float sc[8][4];
        #pragma unroll
        for (int nt=0;nt<8;nt++){ sc[nt][0]=0;sc[nt][1]=0;sc[nt][2]=0;sc[nt][3]=0; }
        #pragma unroll
        for (int ks=0;ks<4;ks++){
            uint32_t kh4[4][4], kl4[4][4];
            #pragma unroll
            for (int np=0;np<4;np++){
                int r = np*16 + (lane&15);
                uint32_t u = ks*2 + (lane>>4);
                ldsm4(kh4[np], sK  + r*128 + ((u^(r&7))<<4));
                ldsm4(kl4[np], sKl + r*128 + ((u^(r&7))<<4));
            }
            #pragma unroll
            for (int nt=0;nt<8;nt++)
                mmafp(sc[nt], qh[ks], kh4[nt>>1][nt&1], kh4[nt>>1][2+(nt&1)]);
            #pragma unroll
            for (int nt=0;nt<8;nt++)
                mmafp(sc[nt], qh[ks], kl4[nt>>1][nt&1], kl4[nt>>1][2+(nt&1)]);
        }

        float mxa=-INFINITY, mxb=-INFINITY;
        #pragma unroll
        for (int nt=0;nt<8;nt++){
            sc[nt][0]*=SCALE; sc[nt][1]*=SCALE; sc[nt][2]*=SCALE; sc[nt][3]*=SCALE;
            mxa = fmaxf(mxa, fmaxf(sc[nt][0], sc[nt][1]));
            mxb = fmaxf(mxb, fmaxf(sc[nt][2], sc[nt][3]));
        }
        mxa = fmaxf(mxa, __shfl_xor_sync(0xffffffffu, mxa, 1));
        mxa = fmaxf(mxa, __shfl_xor_sync(0xffffffffu, mxa, 2));
        mxb = fmaxf(mxb, __shfl_xor_sync(0xffffffffu, mxb, 1));
        mxb = fmaxf(mxb, __shfl_xor_sync(0xffffffffu, mxb, 2));
        float na = fmaxf(m0, mxa), nb = fmaxf(m1, mxb);
        float ca = __expf(m0 - na), cb = __expf(m1 - nb);
        m0 = na; m1 = nb;
        float sa = 0.f, sbm = 0.f;
        #pragma unroll
        for (int nt=0;nt<8;nt++){
            float p0 = __expf(sc[nt][0]-na), p1 = __expf(sc[nt][1]-na);
            float p2 = __expf(sc[nt][2]-nb), p3 = __expf(sc[nt][3]-nb);
            sc[nt][0]=p0; sc[nt][1]=p1; sc[nt][2]=p2; sc[nt][3]=p3;
            sa += p0+p1; sbm += p2+p3;
        }
        sa  += __shfl_xor_sync(0xffffffffu, sa, 1);
        sa  += __shfl_xor_sync(0xffffffffu, sa, 2);
        sbm += __shfl_xor_sync(0xffffffffu, sbm, 1);
        sbm += __shfl_xor_sync(0xffffffffu, sbm, 2);
        l0 = l0*ca + sa; l1 = l1*cb + sbm;
        #pragma unroll
        for (int nt=0;nt<8;nt++){ ctx[nt][0]*=ca; ctx[nt][1]*=ca; ctx[nt][2]*=cb; ctx[nt][3]*=cb; }

        #pragma unroll
        for (int ks=0;ks<4;ks++){
            uint32_t aPh[4], aPl[4];
            packPairH(sc[2*ks  ][0], sc[2*ks  ][1], aPh[0], aPl[0]);
            packPairH(sc[2*ks  ][2], sc[2*ks  ][3], aPh[1], aPl[1]);
            packPairH(sc[2*ks+1][0], sc[2*ks+1][1], aPh[2], aPl[2]);
            packPairH(sc[2*ks+1][2], sc[2*ks+1][3], aPh[3], aPl[3]);
            uint32_t vh4[4][4];
            #pragma unroll
            for (int np2=0;np2<4;np2++){
                int r = ks*16 + (lane&15);
                uint32_t u = np2*2 + (lane>>4);
                ldsm4t(vh4[np2], sV + r*128 + ((u^(r&7))<<4));
            }
            #pragma unroll
            for (int np2=0;np2<4;np2++)
                #pragma unroll
                for (int q2i=0;q2i<2;q2i++)
                    mmafp(ctx[np2*2+q2i], aPh, vh4[np2][q2i*2], vh4[np2][q2i*2+1]);
            #pragma unroll
            for (int np2=0;np2<4;np2++)
                #pragma unroll
                for (int q2i=0;q2i<2;q2i++)
                    mmafp(ctx[np2*2+q2i], aPl, vh4[np2][q2i*2], vh4[np2][q2i*2+1]);
        }
        __syncthreads();
        if (it+2 < SS/64) KV_LOAD(it+2, s);
    }
#undef KV_LOAD

    // normalize + write ctx plain fp16 [row][512]
    float i0 = 1.0f/l0, i1 = 1.0f/l1;
    #pragma unroll
    for (int nt=0;nt<8;nt++){
        int d = nt*8 + 2*(lane&3);
        int col = h*64 + d;
        int rA = rowQ0 + w*16 + (lane>>2);
        *(__half2*)(ctxH + (size_t)rA*DD + col)     = h2of(ctx[nt][0]*i0, ctx[nt][1]*i0);
        *(__half2*)(ctxH + (size_t)(rA+8)*DD + col) = h2of(ctx[nt][2]*i1, ctx[nt][3]*i1);
    }
}

extern "C" void kernel_launch(void* const* d_in, const int* in_sizes, int n_in,
                              void* d_out, int out_size)
{
    (void)in_sizes; (void)n_in; (void)out_size;
    const float* Q     = (const float*)d_in[0];
    const float* Kin   = (const float*)d_in[1];
    const float* Vin   = (const float*)d_in[2];
    const float* W_q   = (const float*)d_in[3];
    const float* W_k   = (const float*)d_in[4];
    const float* W_v   = (const float*)d_in[5];
    const float* W_o   = (const float*)d_in[6];
    const float* ln1_g = (const float*)d_in[7];
    const float* ln1_b = (const float*)d_in[8];
    const float* ln2_g = (const float*)d_in[9];
    const float* ln2_b = (const float*)d_in[10];
    const float* w1    = (const float*)d_in[11];
    const float* b1    = (const float*)d_in[12];
    const float* w2    = (const float*)d_in[13];
    const float* b2    = (const float*)d_in[14];
    float* out = (float*)d_out;

    __half *QnH,*KinH,*VinH,*q2h,*k2h,*v2h,*ctxH,*XnH,*hH;
    __half *WqH,*WkH,*WvH,*WoH,*w1H,*w2H;
    float *X;
    cudaGetSymbolAddress((void**)&QnH,  g_QnH);
    cudaGetSymbolAddress((void**)&KinH, g_KinH);
    cudaGetSymbolAddress((void**)&VinH, g_VinH);
    cudaGetSymbolAddress((void**)&q2h,  g_q2h);
    cudaGetSymbolAddress((void**)&k2h,  g_k2h);
    cudaGetSymbolAddress((void**)&v2h,  g_v2h);
    cudaGetSymbolAddress((void**)&ctxH, g_ctxH);
    cudaGetSymbolAddress((void**)&XnH,  g_XnH);
    cudaGetSymbolAddress((void**)&hH,   g_hH);
    cudaGetSymbolAddress((void**)&X,    g_X);
    cudaGetSymbolAddress((void**)&WqH,  g_WqH);
    cudaGetSymbolAddress((void**)&WkH,  g_WkH);
    cudaGetSymbolAddress((void**)&WvH,  g_WvH);
    cudaGetSymbolAddress((void**)&WoH,  g_WoH);
    cudaGetSymbolAddress((void**)&w1H,  g_w1H);
    cudaGetSymbolAddress((void**)&w2H,  g_w2H);

    cudaFuncSetAttribute(attn_mma,  cudaFuncAttributeMaxDynamicSharedMemorySize, ATTN_SMEM);
    cudaFuncSetAttribute(gemm_h<1>, cudaFuncAttributeMaxDynamicSharedMemorySize, GH_SMEM);
    cudaFuncSetAttribute(gemm_h<2>, cudaFuncAttributeMaxDynamicSharedMemorySize, GH_SMEM);
    cudaFuncSetAttribute(gemm_h<3>, cudaFuncAttributeMaxDynamicSharedMemorySize, GH_SMEM);
    cudaFuncSetAttribute(gemm_h<4>, cudaFuncAttributeMaxDynamicSharedMemorySize, GH_SMEM);
    cudaFuncSetAttribute(gemm_h<5>, cudaFuncAttributeMaxDynamicSharedMemorySize, GH_SMEM);

    dim3 tb(32, 8), tg(16, 16);

    // conversions
    ln_h<<<ROWS,128>>>(Q, ln1_g, ln1_b, QnH);
    toH<<<(ROWS*DD/4+255)/256,256>>>(Kin, KinH, ROWS*DD/4);
    toH<<<(ROWS*DD/4+255)/256,256>>>(Vin, VinH, ROWS*DD/4);
    tsplitH<<<tg, tb>>>(W_q, WqH);
    tsplitH<<<tg, tb>>>(W_k, WkH);
    tsplitH<<<tg, tb>>>(W_v, WvH);
    tsplitH<<<tg, tb>>>(W_o, WoH);
    splitH<<<(DFF*DD/4+255)/256,256>>>(w1, w1H, DD, DFF*DD/4);
    splitH<<<(DD*DFF/4+255)/256,256>>>(w2, w2H, DFF, DD*DFF/4);

    // projections
    gemm_h<4><<<dim3(DD/128,  ROWS/128), 256, GH_SMEM>>>(QnH,  WqH, DD,  DD,  nullptr, nullptr, nullptr, q2h);
    gemm_h<5><<<dim3(DD/128,  ROWS/128), 256, GH_SMEM>>>(KinH, WkH, DD,  DD,  nullptr, nullptr, nullptr, k2h);
    gemm_h<4><<<dim3(DD/128,  ROWS/128), 256, GH_SMEM>>>(VinH, WvH, DD,  DD,  nullptr, nullptr, nullptr, v2h);
    // attention
    attn_mma<<<dim3(SS/128, HH, BB), 256, ATTN_SMEM>>>(q2h, k2h, v2h, ctxH);
    // X = Q + ctx @ Wo
    gemm_h<1><<<dim3(DD/128,  ROWS/128), 256, GH_SMEM>>>(ctxH, WoH, DD,  DD,  nullptr, Q, X, nullptr);
    // LN2 + FFN
    ln_h<<<ROWS,128>>>(X, ln2_g, ln2_b, XnH);
    gemm_h<2><<<dim3(DFF/128, ROWS/128), 256, GH_SMEM>>>(XnH, w1H, DFF, DD,  b1, nullptr, nullptr, hH);
    gemm_h<3><<<dim3(DD/128,  ROWS/128), 256, GH_SMEM>>>(hH,  w2H, DD,  DFF, b2, X, out, nullptr);
}

// round 10
// speedup vs baseline: 4.1737x; 1.4127x over previous
#include <cuda_runtime.h>
#include <cuda_fp16.h>
#include <cstdint>
#include <math.h>

#define BB   2
#define SS   4096
#define DD   512
#define HH   8
#define ROWS (BB*SS)
#define DFF  2048

// activations: plain fp16 [row][C]
__device__ __half g_QnH [ROWS*DD];
__device__ __half g_KinH[ROWS*DD];
__device__ __half g_VinH[ROWS*DD];
__device__ __half g_q2h [ROWS*DD];
__device__ __half g_k2h [ROWS*DD];
__device__ __half g_v2h [ROWS*DD];
__device__ __half g_ctxH[ROWS*DD];
__device__ __half g_XnH [ROWS*DD];
__device__ __half g_hH  [(size_t)ROWS*DFF];
__device__ float  g_X   [ROWS*DD];
// weights: fp16 split, 64-block layout [n][2K]
__device__ __half g_WqH [DD*2*DD];
__device__ __half g_WkH [DD*2*DD];
__device__ __half g_WvH [DD*2*DD];
__device__ __half g_WoH [DD*2*DD];
__device__ __half g_w1H [DFF*2*DD];
__device__ __half g_w2H [DD*2*DFF];

// ---------------- asm helpers ----------------
__device__ __forceinline__ uint32_t smem_u32(const void* p) {
    uint32_t a;
    asm("{ .reg .u64 t; cvta.to.shared.u64 t, %1; cvt.u32.u64 %0, t; }" : "=r"(a) : "l"(p));
    return a;
}
__device__ __forceinline__ void cp16(uint32_t dst, const void* src){
    asm volatile("cp.async.cg.shared.global [%0], [%1], 16;" :: "r"(dst), "l"(src));
}
__device__ __forceinline__ void cp_commit(){ asm volatile("cp.async.commit_group;" ::: "memory"); }
__device__ __forceinline__ void cp_wait0(){ asm volatile("cp.async.wait_group 0;" ::: "memory"); }
__device__ __forceinline__ void cp_wait1(){ asm volatile("cp.async.wait_group 1;" ::: "memory"); }

__device__ __forceinline__ void ldsm4(uint32_t* r, uint32_t a){
    asm volatile("ldmatrix.sync.aligned.m8n8.x4.shared.b16 {%0,%1,%2,%3}, [%4];"
        : "=r"(r[0]),"=r"(r[1]),"=r"(r[2]),"=r"(r[3]) : "r"(a));
}
__device__ __forceinline__ void ldsm4t(uint32_t* r, uint32_t a){
    asm volatile("ldmatrix.sync.aligned.m8n8.x4.trans.shared.b16 {%0,%1,%2,%3}, [%4];"
        : "=r"(r[0]),"=r"(r[1]),"=r"(r[2]),"=r"(r[3]) : "r"(a));
}
__device__ __forceinline__ void mmafp(float* d, const uint32_t* a, uint32_t b0, uint32_t b1){
    asm volatile("mma.sync.aligned.m16n8k16.row.col.f32.f16.f16.f32 "
        "{%0,%1,%2,%3}, {%4,%5,%6,%7}, {%8,%9}, {%0,%1,%2,%3};"
        : "+f"(d[0]),"+f"(d[1]),"+f"(d[2]),"+f"(d[3])
        : "r"(a[0]),"r"(a[1]),"r"(a[2]),"r"(a[3]), "r"(b0), "r"(b1));
}
__device__ __forceinline__ float gelu_exact(float x) {
    return 0.5f * x * (1.0f + erff(x * 0.70710678118654752440f));
}
__device__ __forceinline__ __half2 h2of(float a, float b){
    __half2 h; h.x = __float2half_rn(a); h.y = __float2half_rn(b); return h;
}

// ---------------- LayerNorm -> fp16 plain ----------------
__global__ void ln_h(const float* __restrict__ x, const float* __restrict__ g,
                     const float* __restrict__ b, __half* __restrict__ y)
{
    __shared__ float red[8];
    int row = blockIdx.x;
    int t = threadIdx.x;
    float4 v = ((const float4*)(x + (size_t)row*DD))[t];
    float s  = v.x+v.y+v.z+v.w;
    float s2 = v.x*v.x+v.y*v.y+v.z*v.z+v.w*v.w;
    #pragma unroll
    for (int o=16;o>0;o>>=1){
        s  += __shfl_xor_sync(0xffffffffu, s,  o);
        s2 += __shfl_xor_sync(0xffffffffu, s2, o);
    }
    if ((t&31)==0){ red[t>>5]=s; red[4+(t>>5)]=s2; }
    __syncthreads();
    s  = red[0]+red[1]+red[2]+red[3];
    s2 = red[4]+red[5]+red[6]+red[7];
    float mu  = s * (1.0f/DD);
    float var = s2 * (1.0f/DD) - mu*mu;
    float inv = rsqrtf(var + 1e-5f);
    float4 gv = ((const float4*)g)[t];
    float4 bv = ((const float4*)b)[t];
    __half* yr = y + (size_t)row*DD + 4*t;
    *(__half2*)(yr)   = h2of((v.x-mu)*inv*gv.x + bv.x, (v.y-mu)*inv*gv.y + bv.y);
    *(__half2*)(yr+2) = h2of((v.z-mu)*inv*gv.z + bv.z, (v.w-mu)*inv*gv.w + bv.w);
}

// ---------------- fp32 -> fp16 plain ----------------
__global__ void toH(const float* __restrict__ in, __half* __restrict__ out, int total4)
{
    int i = blockIdx.x*blockDim.x + threadIdx.x;
    if (i >= total4) return;
    size_t e = (size_t)i*4;
    float4 v = *(const float4*)(in + e);
    *(__half2*)(out + e)     = h2of(v.x, v.y);
    *(__half2*)(out + e + 2) = h2of(v.z, v.w);
}

// ---------------- fp32 [R][C] -> fp16 split [R][2C], 64-block ----------------
__global__ void splitH(const float* __restrict__ in, __half* __restrict__ out,
                       int C, int total4)
{
    int i = blockIdx.x*blockDim.x + threadIdx.x;
    if (i >= total4) return;
    size_t e = (size_t)i*4;
    int r = (int)(e / C); int k = (int)(e % C);
    float4 v = *(const float4*)(in + e);
    __half* o = out + (size_t)r*2*C + ((k>>6)*128) + (k&63);
    __half h0=__float2half_rn(v.x), h1=__float2half_rn(v.y);
    __half h2=__float2half_rn(v.z), h3=__float2half_rn(v.w);
    __half2 t;
    t.x=h0; t.y=h1; *(__half2*)(o) = t;
    t.x=h2; t.y=h3; *(__half2*)(o+2) = t;
    t.x=__float2half_rn(v.x-__half2float(h0)); t.y=__float2half_rn(v.y-__half2float(h1));
    *(__half2*)(o+64) = t;
    t.x=__float2half_rn(v.z-__half2float(h2)); t.y=__float2half_rn(v.w-__half2float(h3));
    *(__half2*)(o+66) = t;
}

// ---------------- transpose + split: W[512k][512n] -> out[n][1024], 64-block ----------------
__global__ void tsplitH(const float* __restrict__ Win, __half* __restrict__ out)
{
    __shared__ float t[32][33];
    int bk = blockIdx.y*32, bn = blockIdx.x*32;
    int x = threadIdx.x, y = threadIdx.y;
    #pragma unroll
    for (int j=0;j<4;j++)
        t[y+8*j][x] = Win[(size_t)(bk+y+8*j)*DD + bn + x];
    __syncthreads();
    #pragma unroll
    for (int j=0;j<4;j++){
        int n = bn + y + 8*j;
        float v = t[x][y+8*j];
        __half hv = __float2half_rn(v);
        __half* o = out + (size_t)n*(2*DD) + ((bk>>6)*128) + (bk&32);
        o[x]      = hv;
        o[x + 64] = __float2half_rn(v - __half2float(hv));
    }
}

// ================= fp16 2-pass GEMM (mma.sync) =================
// C = A (*) B2^T : A plain fp16 [M][K], B2 split fp16 [N][2K] (64-block).
// 128x128 tile, 64-k chunks, 2-stage cp.async, pass-major.
// EPI: 1 fp32+resid ; 2 gelu(+bias)->fp16 plain ; 3 fp32+bias+resid ; 4 fp16 plain
#define GH_STAGE 49152
#define GH_SMEM  (2*GH_STAGE)

template<int EPI>
__global__ __launch_bounds__(256,2)
void gemm_h(const __half* __restrict__ A, const __half* __restrict__ B2,
            int N, int K,
            const float* __restrict__ bias, const float* __restrict__ resid,
            float* __restrict__ Cf, __half* __restrict__ Ch)
{
    extern __shared__ char smc[];
    uint32_t sb = smem_u32(smc);
    const int tid = threadIdx.x, lane = tid&31, w = tid>>5;
    const int wr = w>>2, wc = w&3;
    const int rowBase = blockIdx.y*128, colBase = blockIdx.x*128;
    const int K2 = 2*K;
    const int nC = K>>6;

    float acc[4][4][4];
    #pragma unroll
    for (int a=0;a<4;a++)
        #pragma unroll
        for (int b=0;b<4;b++)
            #pragma unroll
            for (int c=0;c<4;c++) acc[a][b][c]=0.f;

#define H_LOAD(chunk, s) do{                                                   \
    uint32_t sA_ = sb + (uint32_t)(s)*GH_STAGE;                                \
    uint32_t sBh_ = sA_ + 16384u, sBl_ = sA_ + 32768u;                         \
    _Pragma("unroll")                                                          \
    for (int i_=0;i_<4;i_++){                                                  \
        int idx_ = tid*4 + i_; int r_ = idx_>>3, u_ = idx_&7;                  \
        cp16(sA_ + (uint32_t)(r_*128 + ((u_^(r_&7))<<4)),                      \
             A + (size_t)(rowBase+r_)*K + (chunk)*64 + u_*8);                  \
    }                                                                          \
    _Pragma("unroll")                                                          \
    for (int i_=0;i_<8;i_++){                                                  \
        int idx_ = tid*8 + i_; int r_ = idx_>>4, us_ = idx_&15;                \
        int u_ = us_&7, pl_ = us_>>3;                                          \
        cp16((pl_?sBl_:sBh_) + (uint32_t)(r_*128 + ((u_^(r_&7))<<4)),          \
             B2 + (size_t)(colBase+r_)*K2 + (chunk)*128 + pl_*64 + u_*8);      \
    } cp_commit(); } while(0)

    H_LOAD(0, 0);
    if (nC > 1) H_LOAD(1, 1);

    for (int c=0;c<nC;c++){
        int s = c & 1;
        if (c == nC-1) cp_wait0(); else cp_wait1();
        __syncthreads();
        uint32_t sA = sb + (uint32_t)s*GH_STAGE;
        uint32_t sBh = sA + 16384u, sBl = sA + 32768u;
        #pragma unroll
        for (int ks=0;ks<4;ks++){
            uint32_t ah[4][4], bh4[2][4], bl4[2][4];
            #pragma unroll
            for (int mt=0;mt<4;mt++){
                int r = wr*64 + mt*16 + (lane&15);
                uint32_t u = ks*2 + (lane>>4);
                ldsm4(ah[mt], sA + r*128 + ((u^(r&7))<<4));
            }
            #pragma unroll
            for (int np=0;np<2;np++){
                int r = wc*32 + np*16 + (lane&15);
                uint32_t u = ks*2 + (lane>>4);
                ldsm4(bh4[np], sBh + r*128 + ((u^(r&7))<<4));
                ldsm4(bl4[np], sBl + r*128 + ((u^(r&7))<<4));
            }
            #pragma unroll
            for (int mt=0;mt<4;mt++)
                #pragma unroll
                for (int nt=0;nt<4;nt++)
                    mmafp(acc[mt][nt], ah[mt], bh4[nt>>1][nt&1], bh4[nt>>1][2+(nt&1)]);
            #pragma unroll
            for (int mt=0;mt<4;mt++)
                #pragma unroll
                for (int nt=0;nt<4;nt++)
                    mmafp(acc[mt][nt], ah[mt], bl4[nt>>1][nt&1], bl4[nt>>1][2+(nt&1)]);
        }
        __syncthreads();
        if (c+2 < nC) H_LOAD(c+2, s);
    }
#undef H_LOAD

    int ra = lane>>2;
    #pragma unroll
    for (int mt=0;mt<4;mt++){
        int r0 = rowBase + wr*64 + mt*16 + ra;
        #pragma unroll
        for (int nt=0;nt<4;nt++){
            int n0 = colBase + wc*32 + nt*8 + 2*(lane&3);
            float* a = acc[mt][nt];
            #pragma unroll
            for (int hh=0;hh<2;hh++){
                int r = r0 + hh*8;
                float v0 = a[2*hh+0], v1 = a[2*hh+1];
                if (EPI==2){
                    v0 = gelu_exact(v0 + bias[n0]); v1 = gelu_exact(v1 + bias[n0+1]);
                    *(__half2*)(Ch + (size_t)r*N + n0) = h2of(v0, v1);
                } else if (EPI==4){
                    *(__half2*)(Ch + (size_t)r*N + n0) = h2of(v0, v1);
                } else {
                    size_t o = (size_t)r*N + n0;
                    if (EPI==1){ v0 += resid[o]; v1 += resid[o+1]; }
                    else       { v0 += bias[n0] + resid[o]; v1 += bias[n0+1] + resid[o+1]; }
                    float2 f2; f2.x=v0; f2.y=v1;
                    *(float2*)(Cf + o) = f2;
                }
            }
        }
    }
}

// ================= Flash attention (fp16 1-pass mma.sync) =================
// smem: Q 16K | 2 stages x [K 8K | V 8K] = 48KB total
#define A_Q  0u
#define A_KV 16384u
#define ATTN_SMEM 49152

__global__ __launch_bounds__(256,2)
void attn_mma(const __half* __restrict__ q2h, const __half* __restrict__ k2h,
              const __half* __restrict__ v2h, __half* __restrict__ ctxH)
{
    extern __shared__ char smc[];
    uint32_t sb = smem_u32(smc);
    const int tid = threadIdx.x, lane = tid&31, w = tid>>5;
    const int qt = blockIdx.x, h = blockIdx.y, b = blockIdx.z;
    const int rowQ0 = b*SS + qt*128;

#define KV_LOAD(it, s) do{                                                     \
    uint32_t stg_ = sb + A_KV + (uint32_t)(s)*16384u;                          \
    int rk0_ = b*SS + (it)*64;                                                 \
    _Pragma("unroll")                                                          \
    for (int i_=0;i_<4;i_++){                                                  \
        int idx_ = tid*4 + i_;                                                 \
        if (idx_ < 512){                                                       \
            int r_ = idx_>>3, u_ = idx_&7;                                     \
            cp16(stg_ + (uint32_t)(r_*128 + (((uint32_t)u_^(r_&7))<<4)),       \
                 k2h + (size_t)(rk0_+r_)*512 + h*64 + u_*8);                   \
        } else {                                                               \
            int j_ = idx_ - 512; int r_ = j_>>3, u_ = j_&7;                    \
            cp16(stg_ + 8192u + (uint32_t)(r_*128 + (((uint32_t)u_^(r_&7))<<4)), \
                 v2h + (size_t)(rk0_+r_)*512 + h*64 + u_*8);                   \
        }                                                                      \
    } cp_commit(); } while(0)

    {
        #pragma unroll
        for (int i=0;i<4;i++){
            int idx = tid*4 + i;
            int r = idx>>3, u = idx&7;
            cp16(sb + A_Q + (uint32_t)(r*128 + (((uint32_t)u^(r&7))<<4)),
                 q2h + (size_t)(rowQ0+r)*512 + h*64 + u*8);
        }
        KV_LOAD(0, 0);
        KV_LOAD(1, 1);
    }

    uint32_t qh[4][4];
    float m0=-INFINITY, m1=-INFINITY, l0=0.f, l1=0.f;
    float ctx[8][4];
    #pragma unroll
    for (int nt=0;nt<8;nt++){ ctx[nt][0]=0;ctx[nt][1]=0;ctx[nt][2]=0;ctx[nt][3]=0; }
    const float SCALE = (float)(1.0/(8.0 + 1e-6));

    for (int it=0; it<SS/64; it++){
        int s = it&1;
        if (it == SS/64-1) cp_wait0(); else cp_wait1();
        __syncthreads();
        if (it == 0){
            #pragma unroll
            for (int ks=0;ks<4;ks++){
                int r = w*16 + (lane&15);
                uint32_t u = ks*2 + (lane>>4);
                ldsm4(qh[ks], sb + A_Q + r*128 + ((u^(r&7))<<4));
            }
        }
        uint32_t sK = sb + A_KV + (uint32_t)s*16384u;
        uint32_t sV = sK + 8192u;

        // ---- QK^T (1-pass fp16) ----
        float sc[8][4];
        #pragma unroll
        for (int nt=0;nt<8;nt++){ sc[nt][0]=0;sc[nt][1]=0;sc[nt][2]=0;sc[nt][3]=0; }
        #pragma unroll
        for (int ks=0;ks<4;ks++){
            uint32_t kh4[4][4];
            #pragma unroll
            for (int np=0;np<4;np++){
                int r = np*16 + (lane&15);
                uint32_t u = ks*2 + (lane>>4);
                ldsm4(kh4[np], sK + r*128 + ((u^(r&7))<<4));
            }
            #pragma unroll
            for (int nt=0;nt<8;nt++)
                mmafp(sc[nt], qh[ks], kh4[nt>>1][nt&1], kh4[nt>>1][2+(nt&1)]);
        }

        // ---- streaming softmax (rows lane>>2 and +8) ----
        float mxa=-INFINITY, mxb=-INFINITY;
        #pragma unroll
        for (int nt=0;nt<8;nt++){
            sc[nt][0]*=SCALE; sc[nt][1]*=SCALE; sc[nt][2]*=SCALE; sc[nt][3]*=SCALE;
            mxa = fmaxf(mxa, fmaxf(sc[nt][0], sc[nt][1]));
            mxb = fmaxf(mxb, fmaxf(sc[nt][2], sc[nt][3]));
        }
        mxa = fmaxf(mxa, __shfl_xor_sync(0xffffffffu, mxa, 1));
        mxa = fmaxf(mxa, __shfl_xor_sync(0xffffffffu, mxa, 2));
        mxb = fmaxf(mxb, __shfl_xor_sync(0xffffffffu, mxb, 1));
        mxb = fmaxf(mxb, __shfl_xor_sync(0xffffffffu, mxb, 2));
        float na = fmaxf(m0, mxa), nb = fmaxf(m1, mxb);
        float ca = __expf(m0 - na), cb = __expf(m1 - nb);
        m0 = na; m1 = nb;
        float sa = 0.f, sbm = 0.f;
        #pragma unroll
        for (int nt=0;nt<8;nt++){
            float p0 = __expf(sc[nt][0]-na), p1 = __expf(sc[nt][1]-na);
            float p2 = __expf(sc[nt][2]-nb), p3 = __expf(sc[nt][3]-nb);
            sc[nt][0]=p0; sc[nt][1]=p1; sc[nt][2]=p2; sc[nt][3]=p3;
            sa += p0+p1; sbm += p2+p3;
        }
        sa  += __shfl_xor_sync(0xffffffffu, sa, 1);
        sa  += __shfl_xor_sync(0xffffffffu, sa, 2);
        sbm += __shfl_xor_sync(0xffffffffu, sbm, 1);
        sbm += __shfl_xor_sync(0xffffffffu, sbm, 2);
        l0 = l0*ca + sa; l1 = l1*cb + sbm;
        #pragma unroll
        for (int nt=0;nt<8;nt++){ ctx[nt][0]*=ca; ctx[nt][1]*=ca; ctx[nt][2]*=cb; ctx[nt][3]*=cb; }

        // ---- P @ V (1-pass fp16, register P frags) ----
        #pragma unroll
        for (int ks=0;ks<4;ks++){
            uint32_t aPh[4];
            {
                __half2 t;
                t = h2of(sc[2*ks  ][0], sc[2*ks  ][1]); aPh[0] = *(uint32_t*)&t;
                t = h2of(sc[2*ks  ][2], sc[2*ks  ][3]); aPh[1] = *(uint32_t*)&t;
                t = h2of(sc[2*ks+1][0], sc[2*ks+1][1]); aPh[2] = *(uint32_t*)&t;
                t = h2of(sc[2*ks+1][2], sc[2*ks+1][3]); aPh[3] = *(uint32_t*)&t;
            }
            uint32_t vh4[4][4];
            #pragma unroll
            for (int np2=0;np2<4;np2++){
                int r = ks*16 + (lane&15);
                uint32_t u = np2*2 + (lane>>4);
                ldsm4t(vh4[np2], sV + r*128 + ((u^(r&7))<<4));
            }
            #pragma unroll
            for (int np2=0;np2<4;np2++)
                #pragma unroll
                for (int q2i=0;q2i<2;q2i++)
                    mmafp(ctx[np2*2+q2i], aPh, vh4[np2][q2i*2], vh4[np2][q2i*2+1]);
        }
        __syncthreads();
        if (it+2 < SS/64) KV_LOAD(it+2, s);
    }
#undef KV_LOAD

    // normalize + write ctx plain fp16 [row][512]
    float i0 = 1.0f/l0, i1 = 1.0f/l1;
    #pragma unroll
    for (int nt=0;nt<8;nt++){
        int d = nt*8 + 2*(lane&3);
        int col = h*64 + d;
        int rA = rowQ0 + w*16 + (lane>>2);
        *(__half2*)(ctxH + (size_t)rA*DD + col)     = h2of(ctx[nt][0]*i0, ctx[nt][1]*i0);
        *(__half2*)(ctxH + (size_t)(rA+8)*DD + col) = h2of(ctx[nt][2]*i1, ctx[nt][3]*i1);
    }
}

extern "C" void kernel_launch(void* const* d_in, const int* in_sizes, int n_in,
                              void* d_out, int out_size)
{
    (void)in_sizes; (void)n_in; (void)out_size;
    const float* Q     = (const float*)d_in[0];
    const float* Kin   = (const float*)d_in[1];
    const float* Vin   = (const float*)d_in[2];
    const float* W_q   = (const float*)d_in[3];
    const float* W_k   = (const float*)d_in[4];
    const float* W_v   = (const float*)d_in[5];
    const float* W_o   = (const float*)d_in[6];
    const float* ln1_g = (const float*)d_in[7];
    const float* ln1_b = (const float*)d_in[8];
    const float* ln2_g = (const float*)d_in[9];
    const float* ln2_b = (const float*)d_in[10];
    const float* w1    = (const float*)d_in[11];
    const float* b1    = (const float*)d_in[12];
    const float* w2    = (const float*)d_in[13];
    const float* b2    = (const float*)d_in[14];
    float* out = (float*)d_out;

    __half *QnH,*KinH,*VinH,*q2h,*k2h,*v2h,*ctxH,*XnH,*hH;
    __half *WqH,*WkH,*WvH,*WoH,*w1H,*w2H;
    float *X;
    cudaGetSymbolAddress((void**)&QnH,  g_QnH);
    cudaGetSymbolAddress((void**)&KinH, g_KinH);
    cudaGetSymbolAddress((void**)&VinH, g_VinH);
    cudaGetSymbolAddress((void**)&q2h,  g_q2h);
    cudaGetSymbolAddress((void**)&k2h,  g_k2h);
    cudaGetSymbolAddress((void**)&v2h,  g_v2h);
    cudaGetSymbolAddress((void**)&ctxH, g_ctxH);
    cudaGetSymbolAddress((void**)&XnH,  g_XnH);
    cudaGetSymbolAddress((void**)&hH,   g_hH);
    cudaGetSymbolAddress((void**)&X,    g_X);
    cudaGetSymbolAddress((void**)&WqH,  g_WqH);
    cudaGetSymbolAddress((void**)&WkH,  g_WkH);
    cudaGetSymbolAddress((void**)&WvH,  g_WvH);
    cudaGetSymbolAddress((void**)&WoH,  g_WoH);
    cudaGetSymbolAddress((void**)&w1H,  g_w1H);
    cudaGetSymbolAddress((void**)&w2H,  g_w2H);

    cudaFuncSetAttribute(attn_mma,  cudaFuncAttributeMaxDynamicSharedMemorySize, ATTN_SMEM);
    cudaFuncSetAttribute(gemm_h<1>, cudaFuncAttributeMaxDynamicSharedMemorySize, GH_SMEM);
    cudaFuncSetAttribute(gemm_h<2>, cudaFuncAttributeMaxDynamicSharedMemorySize, GH_SMEM);
    cudaFuncSetAttribute(gemm_h<3>, cudaFuncAttributeMaxDynamicSharedMemorySize, GH_SMEM);
    cudaFuncSetAttribute(gemm_h<4>, cudaFuncAttributeMaxDynamicSharedMemorySize, GH_SMEM);

    dim3 tb(32, 8), tg(16, 16);

    // conversions
    ln_h<<<ROWS,128>>>(Q, ln1_g, ln1_b, QnH);
    toH<<<(ROWS*DD/4+255)/256,256>>>(Kin, KinH, ROWS*DD/4);
    toH<<<(ROWS*DD/4+255)/256,256>>>(Vin, VinH, ROWS*DD/4);
    tsplitH<<<tg, tb>>>(W_q, WqH);
    tsplitH<<<tg, tb>>>(W_k, WkH);
    tsplitH<<<tg, tb>>>(W_v, WvH);
    tsplitH<<<tg, tb>>>(W_o, WoH);
    splitH<<<(DFF*DD/4+255)/256,256>>>(w1, w1H, DD, DFF*DD/4);
    splitH<<<(DD*DFF/4+255)/256,256>>>(w2, w2H, DFF, DD*DFF/4);

    // projections (all plain fp16 outputs)
    gemm_h<4><<<dim3(DD/128,  ROWS/128), 256, GH_SMEM>>>(QnH,  WqH, DD,  DD,  nullptr, nullptr, nullptr, q2h);
    gemm_h<4><<<dim3(DD/128,  ROWS/128), 256, GH_SMEM>>>(KinH, WkH, DD,  DD,  nullptr, nullptr, nullptr, k2h);
    gemm_h<4><<<dim3(DD/128,  ROWS/128), 256, GH_SMEM>>>(VinH, WvH, DD,  DD,  nullptr, nullptr, nullptr, v2h);
    // attention (1-pass fp16)
    attn_mma<<<dim3(SS/128, HH, BB), 256, ATTN_SMEM>>>(q2h, k2h, v2h, ctxH);
    // X = Q + ctx @ Wo
    gemm_h<1><<<dim3(DD/128,  ROWS/128), 256, GH_SMEM>>>(ctxH, WoH, DD,  DD,  nullptr, Q, X, nullptr);
    // LN2 + FFN
    ln_h<<<ROWS,128>>>(X, ln2_g, ln2_b, XnH);
    gemm_h<2><<<dim3(DFF/128, ROWS/128), 256, GH_SMEM>>>(XnH, w1H, DFF, DD,  b1, nullptr, nullptr, hH);
    gemm_h<3><<<dim3(DD/128,  ROWS/128), 256, GH_SMEM>>>(hH,  w2H, DD,  DFF, b2, X, out, nullptr);
}

// round 11
// speedup vs baseline: 5.0478x; 1.2094x over previous
#include <cuda_runtime.h>
#include <cuda_fp16.h>
#include <cstdint>
#include <math.h>

#define BB   2
#define SS   4096
#define DD   512
#define HH   8
#define ROWS (BB*SS)
#define DFF  2048

// activations: plain fp16 [row][C]
__device__ __half g_QnH [ROWS*DD];
__device__ __half g_KinH[ROWS*DD];
__device__ __half g_VinH[ROWS*DD];
__device__ __half g_q2h [ROWS*DD];
__device__ __half g_k2h [ROWS*DD];
__device__ __half g_v2h [ROWS*DD];
__device__ __half g_ctxH[ROWS*DD];
__device__ __half g_XnH [ROWS*DD];
__device__ __half g_hH  [(size_t)ROWS*DFF];
__device__ float  g_X   [ROWS*DD];
// weights: fp16 split, 64-block layout [n][2K]
__device__ __half g_WqH [DD*2*DD];
__device__ __half g_WkH [DD*2*DD];
__device__ __half g_WvH [DD*2*DD];
__device__ __half g_WoH [DD*2*DD];
__device__ __half g_w1H [DFF*2*DD];
__device__ __half g_w2H [DD*2*DFF];

// ---------------- asm helpers ----------------
__device__ __forceinline__ uint32_t smem_u32(const void* p) {
    uint32_t a;
    asm("{ .reg .u64 t; cvta.to.shared.u64 t, %1; cvt.u32.u64 %0, t; }" : "=r"(a) : "l"(p));
    return a;
}
__device__ __forceinline__ void cp16(uint32_t dst, const void* src){
    asm volatile("cp.async.cg.shared.global [%0], [%1], 16;" :: "r"(dst), "l"(src));
}
__device__ __forceinline__ void cp_commit(){ asm volatile("cp.async.commit_group;" ::: "memory"); }
__device__ __forceinline__ void cp_wait0(){ asm volatile("cp.async.wait_group 0;" ::: "memory"); }
__device__ __forceinline__ void cp_wait1(){ asm volatile("cp.async.wait_group 1;" ::: "memory"); }

__device__ __forceinline__ void ldsm4(uint32_t* r, uint32_t a){
    asm volatile("ldmatrix.sync.aligned.m8n8.x4.shared.b16 {%0,%1,%2,%3}, [%4];"
        : "=r"(r[0]),"=r"(r[1]),"=r"(r[2]),"=r"(r[3]) : "r"(a));
}
__device__ __forceinline__ void ldsm4t(uint32_t* r, uint32_t a){
    asm volatile("ldmatrix.sync.aligned.m8n8.x4.trans.shared.b16 {%0,%1,%2,%3}, [%4];"
        : "=r"(r[0]),"=r"(r[1]),"=r"(r[2]),"=r"(r[3]) : "r"(a));
}
__device__ __forceinline__ void mmafp(float* d, const uint32_t* a, uint32_t b0, uint32_t b1){
    asm volatile("mma.sync.aligned.m16n8k16.row.col.f32.f16.f16.f32 "
        "{%0,%1,%2,%3}, {%4,%5,%6,%7}, {%8,%9}, {%0,%1,%2,%3};"
        : "+f"(d[0]),"+f"(d[1]),"+f"(d[2]),"+f"(d[3])
        : "r"(a[0]),"r"(a[1]),"r"(a[2]),"r"(a[3]), "r"(b0), "r"(b1));
}
__device__ __forceinline__ float gelu_exact(float x) {
    return 0.5f * x * (1.0f + erff(x * 0.70710678118654752440f));
}
__device__ __forceinline__ __half2 h2of(float a, float b){
    __half2 h; h.x = __float2half_rn(a); h.y = __float2half_rn(b); return h;
}

// ---------------- LayerNorm -> fp16 plain ----------------
__global__ void ln_h(const float* __restrict__ x, const float* __restrict__ g,
                     const float* __restrict__ b, __half* __restrict__ y)
{
    __shared__ float red[8];
    int row = blockIdx.x;
    int t = threadIdx.x;
    float4 v = ((const float4*)(x + (size_t)row*DD))[t];
    float s  = v.x+v.y+v.z+v.w;
    float s2 = v.x*v.x+v.y*v.y+v.z*v.z+v.w*v.w;
    #pragma unroll
    for (int o=16;o>0;o>>=1){
        s  += __shfl_xor_sync(0xffffffffu, s,  o);
        s2 += __shfl_xor_sync(0xffffffffu, s2, o);
    }
    if ((t&31)==0){ red[t>>5]=s; red[4+(t>>5)]=s2; }
    __syncthreads();
    s  = red[0]+red[1]+red[2]+red[3];
    s2 = red[4]+red[5]+red[6]+red[7];
    float mu  = s * (1.0f/DD);
    float var = s2 * (1.0f/DD) - mu*mu;
    float inv = rsqrtf(var + 1e-5f);
    float4 gv = ((const float4*)g)[t];
    float4 bv = ((const float4*)b)[t];
    __half* yr = y + (size_t)row*DD + 4*t;
    *(__half2*)(yr)   = h2of((v.x-mu)*inv*gv.x + bv.x, (v.y-mu)*inv*gv.y + bv.y);
    *(__half2*)(yr+2) = h2of((v.z-mu)*inv*gv.z + bv.z, (v.w-mu)*inv*gv.w + bv.w);
}

// ---------------- fp32 -> fp16 plain ----------------
__global__ void toH(const float* __restrict__ in, __half* __restrict__ out, int total4)
{
    int i = blockIdx.x*blockDim.x + threadIdx.x;
    if (i >= total4) return;
    size_t e = (size_t)i*4;
    float4 v = *(const float4*)(in + e);
    *(__half2*)(out + e)     = h2of(v.x, v.y);
    *(__half2*)(out + e + 2) = h2of(v.z, v.w);
}

// ---------------- fp32 [R][C] -> fp16 split [R][2C], 64-block ----------------
__global__ void splitH(const float* __restrict__ in, __half* __restrict__ out,
                       int C, int total4)
{
    int i = blockIdx.x*blockDim.x + threadIdx.x;
    if (i >= total4) return;
    size_t e = (size_t)i*4;
    int r = (int)(e / C); int k = (int)(e % C);
    float4 v = *(const float4*)(in + e);
    __half* o = out + (size_t)r*2*C + ((k>>6)*128) + (k&63);
    __half h0=__float2half_rn(v.x), h1=__float2half_rn(v.y);
    __half h2=__float2half_rn(v.z), h3=__float2half_rn(v.w);
    __half2 t;
    t.x=h0; t.y=h1; *(__half2*)(o) = t;
    t.x=h2; t.y=h3; *(__half2*)(o+2) = t;
    t.x=__float2half_rn(v.x-__half2float(h0)); t.y=__float2half_rn(v.y-__half2float(h1));
    *(__half2*)(o+64) = t;
    t.x=__float2half_rn(v.z-__half2float(h2)); t.y=__float2half_rn(v.w-__half2float(h3));
    *(__half2*)(o+66) = t;
}

// ---------------- transpose + split: W[512k][512n] -> out[n][1024], 64-block ----------------
__global__ void tsplitH(const float* __restrict__ Win, __half* __restrict__ out)
{
    __shared__ float t[32][33];
    int bk = blockIdx.y*32, bn = blockIdx.x*32;
    int x = threadIdx.x, y = threadIdx.y;
    #pragma unroll
    for (int j=0;j<4;j++)
        t[y+8*j][x] = Win[(size_t)(bk+y+8*j)*DD + bn + x];
    __syncthreads();
    #pragma unroll
    for (int j=0;j<4;j++){
        int n = bn + y + 8*j;
        float v = t[x][y+8*j];
        __half hv = __float2half_rn(v);
        __half* o = out + (size_t)n*(2*DD) + ((bk>>6)*128) + (bk&32);
        o[x]      = hv;
        o[x + 64] = __float2half_rn(v - __half2float(hv));
    }
}

// ================= fp16 GEMM (mma.sync), PASSES = 1 or 2 =================
// C = A (*) B2^T : A plain fp16 [M][K], B2 split fp16 [N][2K] (64-block).
// 128x128 tile, 64-k chunks, 2-stage cp.async, pass-major.
// EPI: 1 fp32+resid ; 2 gelu(+bias)->fp16 plain ; 3 fp32+bias+resid ; 4 fp16 plain
#define GH_STAGE 49152
#define GH_SMEM  (2*GH_STAGE)

template<int EPI, int PASSES>
__global__ __launch_bounds__(256,2)
void gemm_h(const __half* __restrict__ A, const __half* __restrict__ B2,
            int N, int K,
            const float* __restrict__ bias, const float* __restrict__ resid,
            float* __restrict__ Cf, __half* __restrict__ Ch)
{
    extern __shared__ char smc[];
    uint32_t sb = smem_u32(smc);
    const int tid = threadIdx.x, lane = tid&31, w = tid>>5;
    const int wr = w>>2, wc = w&3;
    const int rowBase = blockIdx.y*128, colBase = blockIdx.x*128;
    const int K2 = 2*K;
    const int nC = K>>6;

    float acc[4][4][4];
    #pragma unroll
    for (int a=0;a<4;a++)
        #pragma unroll
        for (int b=0;b<4;b++)
            #pragma unroll
            for (int c=0;c<4;c++) acc[a][b][c]=0.f;

#define H_LOAD(chunk, s) do{                                                   \
    uint32_t sA_ = sb + (uint32_t)(s)*GH_STAGE;                                \
    uint32_t sBh_ = sA_ + 16384u, sBl_ = sA_ + 32768u;                         \
    _Pragma("unroll")                                                          \
    for (int i_=0;i_<4;i_++){                                                  \
        int idx_ = tid*4 + i_; int r_ = idx_>>3, u_ = idx_&7;                  \
        cp16(sA_ + (uint32_t)(r_*128 + ((u_^(r_&7))<<4)),                      \
             A + (size_t)(rowBase+r_)*K + (chunk)*64 + u_*8);                  \
    }                                                                          \
    if (PASSES == 2){                                                          \
        _Pragma("unroll")                                                      \
        for (int i_=0;i_<8;i_++){                                              \
            int idx_ = tid*8 + i_; int r_ = idx_>>4, us_ = idx_&15;            \
            int u_ = us_&7, pl_ = us_>>3;                                      \
            cp16((pl_?sBl_:sBh_) + (uint32_t)(r_*128 + ((u_^(r_&7))<<4)),      \
                 B2 + (size_t)(colBase+r_)*K2 + (chunk)*128 + pl_*64 + u_*8);  \
        }                                                                      \
    } else {                                                                   \
        _Pragma("unroll")                                                      \
        for (int i_=0;i_<4;i_++){                                              \
            int idx_ = tid*4 + i_; int r_ = idx_>>3, u_ = idx_&7;              \
            cp16(sBh_ + (uint32_t)(r_*128 + ((u_^(r_&7))<<4)),                 \
                 B2 + (size_t)(colBase+r_)*K2 + (chunk)*128 + u_*8);           \
        }                                                                      \
    } cp_commit(); } while(0)

    H_LOAD(0, 0);
    if (nC > 1) H_LOAD(1, 1);

    for (int c=0;c<nC;c++){
        int s = c & 1;
        if (c == nC-1) cp_wait0(); else cp_wait1();
        __syncthreads();
        uint32_t sA = sb + (uint32_t)s*GH_STAGE;
        uint32_t sBh = sA + 16384u, sBl = sA + 32768u;
        #pragma unroll
        for (int ks=0;ks<4;ks++){
            uint32_t ah[4][4], bh4[2][4], bl4[2][4];
            #pragma unroll
            for (int mt=0;mt<4;mt++){
                int r = wr*64 + mt*16 + (lane&15);
                uint32_t u = ks*2 + (lane>>4);
                ldsm4(ah[mt], sA + r*128 + ((u^(r&7))<<4));
            }
            #pragma unroll
            for (int np=0;np<2;np++){
                int r = wc*32 + np*16 + (lane&15);
                uint32_t u = ks*2 + (lane>>4);
                ldsm4(bh4[np], sBh + r*128 + ((u^(r&7))<<4));
                if (PASSES == 2) ldsm4(bl4[np], sBl + r*128 + ((u^(r&7))<<4));
            }
            #pragma unroll
            for (int mt=0;mt<4;mt++)
                #pragma unroll
                for (int nt=0;nt<4;nt++)
                    mmafp(acc[mt][nt], ah[mt], bh4[nt>>1][nt&1], bh4[nt>>1][2+(nt&1)]);
            if (PASSES == 2){
                #pragma unroll
                for (int mt=0;mt<4;mt++)
                    #pragma unroll
                    for (int nt=0;nt<4;nt++)
                        mmafp(acc[mt][nt], ah[mt], bl4[nt>>1][nt&1], bl4[nt>>1][2+(nt&1)]);
            }
        }
        __syncthreads();
        if (c+2 < nC) H_LOAD(c+2, s);
    }
#undef H_LOAD

    int ra = lane>>2;
    #pragma unroll
    for (int mt=0;mt<4;mt++){
        int r0 = rowBase + wr*64 + mt*16 + ra;
        #pragma unroll
        for (int nt=0;nt<4;nt++){
            int n0 = colBase + wc*32 + nt*8 + 2*(lane&3);
            float* a = acc[mt][nt];
            #pragma unroll
            for (int hh=0;hh<2;hh++){
                int r = r0 + hh*8;
                float v0 = a[2*hh+0], v1 = a[2*hh+1];
                if (EPI==2){
                    v0 = gelu_exact(v0 + bias[n0]); v1 = gelu_exact(v1 + bias[n0+1]);
                    *(__half2*)(Ch + (size_t)r*N + n0) = h2of(v0, v1);
                } else if (EPI==4){
                    *(__half2*)(Ch + (size_t)r*N + n0) = h2of(v0, v1);
                } else {
                    size_t o = (size_t)r*N + n0;
                    if (EPI==1){ v0 += resid[o]; v1 += resid[o+1]; }
                    else       { v0 += bias[n0] + resid[o]; v1 += bias[n0+1] + resid[o+1]; }
                    float2 f2; f2.x=v0; f2.y=v1;
                    *(float2*)(Cf + o) = f2;
                }
            }
        }
    }
}

// ================= Flash attention (fp16 1-pass mma.sync) =================
// smem: Q 16K | 2 stages x [K 8K | V 8K] = 48KB total
#define A_Q  0u
#define A_KV 16384u
#define ATTN_SMEM 49152

__global__ __launch_bounds__(256,2)
void attn_mma(const __half* __restrict__ q2h, const __half* __restrict__ k2h,
              const __half* __restrict__ v2h, __half* __restrict__ ctxH)
{
    extern __shared__ char smc[];
    uint32_t sb = smem_u32(smc);
    const int tid = threadIdx.x, lane = tid&31, w = tid>>5;
    const int qt = blockIdx.x, h = blockIdx.y, b = blockIdx.z;
    const int rowQ0 = b*SS + qt*128;

#define KV_LOAD(it, s) do{                                                     \
    uint32_t stg_ = sb + A_KV + (uint32_t)(s)*16384u;                          \
    int rk0_ = b*SS + (it)*64;                                                 \
    _Pragma("unroll")                                                          \
    for (int i_=0;i_<4;i_++){                                                  \
        int idx_ = tid*4 + i_;                                                 \
        if (idx_ < 512){                                                       \
            int r_ = idx_>>3, u_ = idx_&7;                                     \
            cp16(stg_ + (uint32_t)(r_*128 + (((uint32_t)u_^(r_&7))<<4)),       \
                 k2h + (size_t)(rk0_+r_)*512 + h*64 + u_*8);                   \
        } else {                                                               \
            int j_ = idx_ - 512; int r_ = j_>>3, u_ = j_&7;                    \
            cp16(stg_ + 8192u + (uint32_t)(r_*128 + (((uint32_t)u_^(r_&7))<<4)), \
                 v2h + (size_t)(rk0_+r_)*512 + h*64 + u_*8);                   \
        }                                                                      \
    } cp_commit(); } while(0)

    {
        #pragma unroll
        for (int i=0;i<4;i++){
            int idx = tid*4 + i;
            int r = idx>>3, u = idx&7;
            cp16(sb + A_Q + (uint32_t)(r*128 + (((uint32_t)u^(r&7))<<4)),
                 q2h + (size_t)(rowQ0+r)*512 + h*64 + u*8);
        }
        KV_LOAD(0, 0);
        KV_LOAD(1, 1);
    }

    uint32_t qh[4][4];
    float m0=-INFINITY, m1=-INFINITY, l0=0.f, l1=0.f;
    float ctx[8][4];
    #pragma unroll
    for (int nt=0;nt<8;nt++){ ctx[nt][0]=0;ctx[nt][1]=0;ctx[nt][2]=0;ctx[nt][3]=0; }
    const float SCALE = (float)(1.0/(8.0 + 1e-6));

    for (int it=0; it<SS/64; it++){
        int s = it&1;
        if (it == SS/64-1) cp_wait0(); else cp_wait1();
        __syncthreads();
        if (it == 0){
            #pragma unroll
            for (int ks=0;ks<4;ks++){
                int r = w*16 + (lane&15);
                uint32_t u = ks*2 + (lane>>4);
                ldsm4(qh[ks], sb + A_Q + r*128 + ((u^(r&7))<<4));
            }
        }
        uint32_t sK = sb + A_KV + (uint32_t)s*16384u;
        uint32_t sV = sK + 8192u;

        // ---- QK^T (1-pass fp16) ----
        float sc[8][4];
        #pragma unroll
        for (int nt=0;nt<8;nt++){ sc[nt][0]=0;sc[nt][1]=0;sc[nt][2]=0;sc[nt][3]=0; }
        #pragma unroll
        for (int ks=0;ks<4;ks++){
            uint32_t kh4[4][4];
            #pragma unroll
            for (int np=0;np<4;np++){
                int r = np*16 + (lane&15);
                uint32_t u = ks*2 + (lane>>4);
                ldsm4(kh4[np], sK + r*128 + ((u^(r&7))<<4));
            }
            #pragma unroll
            for (int nt=0;nt<8;nt++)
                mmafp(sc[nt], qh[ks], kh4[nt>>1][nt&1], kh4[nt>>1][2+(nt&1)]);
        }

        // ---- streaming softmax (rows lane>>2 and +8) ----
        float mxa=-INFINITY, mxb=-INFINITY;
        #pragma unroll
        for (int nt=0;nt<8;nt++){
            sc[nt][0]*=SCALE; sc[nt][1]*=SCALE; sc[nt][2]*=SCALE; sc[nt][3]*=SCALE;
            mxa = fmaxf(mxa, fmaxf(sc[nt][0], sc[nt][1]));
            mxb = fmaxf(mxb, fmaxf(sc[nt][2], sc[nt][3]));
        }
        mxa = fmaxf(mxa, __shfl_xor_sync(0xffffffffu, mxa, 1));
        mxa = fmaxf(mxa, __shfl_xor_sync(0xffffffffu, mxa, 2));
        mxb = fmaxf(mxb, __shfl_xor_sync(0xffffffffu, mxb, 1));
        mxb = fmaxf(mxb, __shfl_xor_sync(0xffffffffu, mxb, 2));
        float na = fmaxf(m0, mxa), nb = fmaxf(m1, mxb);
        float ca = __expf(m0 - na), cb = __expf(m1 - nb);
        m0 = na; m1 = nb;
        float sa = 0.f, sbm = 0.f;
        #pragma unroll
        for (int nt=0;nt<8;nt++){
            float p0 = __expf(sc[nt][0]-na), p1 = __expf(sc[nt][1]-na);
            float p2 = __expf(sc[nt][2]-nb), p3 = __expf(sc[nt][3]-nb);
            sc[nt][0]=p0; sc[nt][1]=p1; sc[nt][2]=p2; sc[nt][3]=p3;
            sa += p0+p1; sbm += p2+p3;
        }
        sa  += __shfl_xor_sync(0xffffffffu, sa, 1);
        sa  += __shfl_xor_sync(0xffffffffu, sa, 2);
        sbm += __shfl_xor_sync(0xffffffffu, sbm, 1);
        sbm += __shfl_xor_sync(0xffffffffu, sbm, 2);
        l0 = l0*ca + sa; l1 = l1*cb + sbm;
        #pragma unroll
        for (int nt=0;nt<8;nt++){ ctx[nt][0]*=ca; ctx[nt][1]*=ca; ctx[nt][2]*=cb; ctx[nt][3]*=cb; }

        // ---- P @ V (1-pass fp16, register P frags) ----
        #pragma unroll
        for (int ks=0;ks<4;ks++){
            uint32_t aPh[4];
            {
                __half2 t;
                t = h2of(sc[2*ks  ][0], sc[2*ks  ][1]); aPh[0] = *(uint32_t*)&t;
                t = h2of(sc[2*ks  ][2], sc[2*ks  ][3]); aPh[1] = *(uint32_t*)&t;
                t = h2of(sc[2*ks+1][0], sc[2*ks+1][1]); aPh[2] = *(uint32_t*)&t;
                t = h2of(sc[2*ks+1][2], sc[2*ks+1][3]); aPh[3] = *(uint32_t*)&t;
            }
            uint32_t vh4[4][4];
            #pragma unroll
            for (int np2=0;np2<4;np2++){
                int r = ks*16 + (lane&15);
                uint32_t u = np2*2 + (lane>>4);
                ldsm4t(vh4[np2], sV + r*128 + ((u^(r&7))<<4));
            }
            #pragma unroll
            for (int np2=0;np2<4;np2++)
                #pragma unroll
                for (int q2i=0;q2i<2;q2i++)
                    mmafp(ctx[np2*2+q2i], aPh, vh4[np2][q2i*2], vh4[np2][q2i*2+1]);
        }
        __syncthreads();
        if (it+2 < SS/64) KV_LOAD(it+2, s);
    }
#undef KV_LOAD

    // normalize + write ctx plain fp16 [row][512]
    float i0 = 1.0f/l0, i1 = 1.0f/l1;
    #pragma unroll
    for (int nt=0;nt<8;nt++){
        int d = nt*8 + 2*(lane&3);
        int col = h*64 + d;
        int rA = rowQ0 + w*16 + (lane>>2);
        *(__half2*)(ctxH + (size_t)rA*DD + col)     = h2of(ctx[nt][0]*i0, ctx[nt][1]*i0);
        *(__half2*)(ctxH + (size_t)(rA+8)*DD + col) = h2of(ctx[nt][2]*i1, ctx[nt][3]*i1);
    }
}

extern "C" void kernel_launch(void* const* d_in, const int* in_sizes, int n_in,
                              void* d_out, int out_size)
{
    (void)in_sizes; (void)n_in; (void)out_size;
    const float* Q     = (const float*)d_in[0];
    const float* Kin   = (const float*)d_in[1];
    const float* Vin   = (const float*)d_in[2];
    const float* W_q   = (const float*)d_in[3];
    const float* W_k   = (const float*)d_in[4];
    const float* W_v   = (const float*)d_in[5];
    const float* W_o   = (const float*)d_in[6];
    const float* ln1_g = (const float*)d_in[7];
    const float* ln1_b = (const float*)d_in[8];
    const float* ln2_g = (const float*)d_in[9];
    const float* ln2_b = (const float*)d_in[10];
    const float* w1    = (const float*)d_in[11];
    const float* b1    = (const float*)d_in[12];
    const float* w2    = (const float*)d_in[13];
    const float* b2    = (const float*)d_in[14];
    float* out = (float*)d_out;

    __half *QnH,*KinH,*VinH,*q2h,*k2h,*v2h,*ctxH,*XnH,*hH;
    __half *WqH,*WkH,*WvH,*WoH,*w1H,*w2H;
    float *X;
    cudaGetSymbolAddress((void**)&QnH,  g_QnH);
    cudaGetSymbolAddress((void**)&KinH, g_KinH);
    cudaGetSymbolAddress((void**)&VinH, g_VinH);
    cudaGetSymbolAddress((void**)&q2h,  g_q2h);
    cudaGetSymbolAddress((void**)&k2h,  g_k2h);
    cudaGetSymbolAddress((void**)&v2h,  g_v2h);
    cudaGetSymbolAddress((void**)&ctxH, g_ctxH);
    cudaGetSymbolAddress((void**)&XnH,  g_XnH);
    cudaGetSymbolAddress((void**)&hH,   g_hH);
    cudaGetSymbolAddress((void**)&X,    g_X);
    cudaGetSymbolAddress((void**)&WqH,  g_WqH);
    cudaGetSymbolAddress((void**)&WkH,  g_WkH);
    cudaGetSymbolAddress((void**)&WvH,  g_WvH);
    cudaGetSymbolAddress((void**)&WoH,  g_WoH);
    cudaGetSymbolAddress((void**)&w1H,  g_w1H);
    cudaGetSymbolAddress((void**)&w2H,  g_w2H);

    cudaFuncSetAttribute(attn_mma,      cudaFuncAttributeMaxDynamicSharedMemorySize, ATTN_SMEM);
    cudaFuncSetAttribute((gemm_h<1,2>), cudaFuncAttributeMaxDynamicSharedMemorySize, GH_SMEM);
    cudaFuncSetAttribute((gemm_h<2,1>), cudaFuncAttributeMaxDynamicSharedMemorySize, GH_SMEM);
    cudaFuncSetAttribute((gemm_h<3,2>), cudaFuncAttributeMaxDynamicSharedMemorySize, GH_SMEM);
    cudaFuncSetAttribute((gemm_h<4,1>), cudaFuncAttributeMaxDynamicSharedMemorySize, GH_SMEM);

    dim3 tb(32, 8), tg(16, 16);

    // conversions
    ln_h<<<ROWS,128>>>(Q, ln1_g, ln1_b, QnH);
    toH<<<(ROWS*DD/4+255)/256,256>>>(Kin, KinH, ROWS*DD/4);
    toH<<<(ROWS*DD/4+255)/256,256>>>(Vin, VinH, ROWS*DD/4);
    tsplitH<<<tg, tb>>>(W_q, WqH);
    tsplitH<<<tg, tb>>>(W_k, WkH);
    tsplitH<<<tg, tb>>>(W_v, WvH);
    tsplitH<<<tg, tb>>>(W_o, WoH);
    splitH<<<(DFF*DD/4+255)/256,256>>>(w1, w1H, DD, DFF*DD/4);
    splitH<<<(DD*DFF/4+255)/256,256>>>(w2, w2H, DFF, DD*DFF/4);

    // projections (1-pass fp16: attention input path is softmax-damped)
    gemm_h<4,1><<<dim3(DD/128,  ROWS/128), 256, GH_SMEM>>>(QnH,  WqH, DD,  DD,  nullptr, nullptr, nullptr, q2h);
    gemm_h<4,1><<<dim3(DD/128,  ROWS/128), 256, GH_SMEM>>>(KinH, WkH, DD,  DD,  nullptr, nullptr, nullptr, k2h);
    gemm_h<4,1><<<dim3(DD/128,  ROWS/128), 256, GH_SMEM>>>(VinH, WvH, DD,  DD,  nullptr, nullptr, nullptr, v2h);
    // attention (1-pass fp16)
    attn_mma<<<dim3(SS/128, HH, BB), 256, ATTN_SMEM>>>(q2h, k2h, v2h, ctxH);
    // X = Q + ctx @ Wo   (2-pass: direct residual path)
    gemm_h<1,2><<<dim3(DD/128,  ROWS/128), 256, GH_SMEM>>>(ctxH, WoH, DD,  DD,  nullptr, Q, X, nullptr);
    // LN2 + FFN (w1 1-pass: averaged by w2 ; w2 2-pass: direct output path)
    ln_h<<<ROWS,128>>>(X, ln2_g, ln2_b, XnH);
    gemm_h<2,1><<<dim3(DFF/128, ROWS/128), 256, GH_SMEM>>>(XnH, w1H, DFF, DD,  b1, nullptr, nullptr, hH);
    gemm_h<3,2><<<dim3(DD/128,  ROWS/128), 256, GH_SMEM>>>(hH,  w2H, DD,  DFF, b2, X, out, nullptr);
}

// round 12
// speedup vs baseline: 6.0218x; 1.1929x over previous
#include <cuda_runtime.h>
#include <cuda_fp16.h>
#include <cstdint>
#include <math.h>

#define BB   2
#define SS   4096
#define DD   512
#define HH   8
#define ROWS (BB*SS)
#define DFF  2048

// activations: plain fp16 [row][C]
__device__ __half g_QnH [ROWS*DD];
__device__ __half g_KinH[ROWS*DD];
__device__ __half g_VinH[ROWS*DD];
__device__ __half g_q2h [ROWS*DD];
__device__ __half g_k2h [ROWS*DD];
__device__ __half g_v2h [ROWS*DD];
__device__ __half g_ctxH[ROWS*DD];
__device__ __half g_XnH [ROWS*DD];
__device__ __half g_hH  [(size_t)ROWS*DFF];
__device__ float  g_X   [ROWS*DD];
// weights: plain fp16 [n][K]
__device__ __half g_WqH [DD*DD];
__device__ __half g_WkH [DD*DD];
__device__ __half g_WvH [DD*DD];
__device__ __half g_WoH [DD*DD];
__device__ __half g_w1H [DFF*DD];
__device__ __half g_w2H [DD*DFF];

// ---------------- asm helpers ----------------
__device__ __forceinline__ uint32_t smem_u32(const void* p) {
    uint32_t a;
    asm("{ .reg .u64 t; cvta.to.shared.u64 t, %1; cvt.u32.u64 %0, t; }" : "=r"(a) : "l"(p));
    return a;
}
__device__ __forceinline__ void cp16(uint32_t dst, const void* src){
    asm volatile("cp.async.cg.shared.global [%0], [%1], 16;" :: "r"(dst), "l"(src));
}
__device__ __forceinline__ void cp_commit(){ asm volatile("cp.async.commit_group;" ::: "memory"); }
__device__ __forceinline__ void cp_wait0(){ asm volatile("cp.async.wait_group 0;" ::: "memory"); }
__device__ __forceinline__ void cp_wait1(){ asm volatile("cp.async.wait_group 1;" ::: "memory"); }

__device__ __forceinline__ void ldsm4(uint32_t* r, uint32_t a){
    asm volatile("ldmatrix.sync.aligned.m8n8.x4.shared.b16 {%0,%1,%2,%3}, [%4];"
        : "=r"(r[0]),"=r"(r[1]),"=r"(r[2]),"=r"(r[3]) : "r"(a));
}
__device__ __forceinline__ void ldsm4t(uint32_t* r, uint32_t a){
    asm volatile("ldmatrix.sync.aligned.m8n8.x4.trans.shared.b16 {%0,%1,%2,%3}, [%4];"
        : "=r"(r[0]),"=r"(r[1]),"=r"(r[2]),"=r"(r[3]) : "r"(a));
}
__device__ __forceinline__ void mmafp(float* d, const uint32_t* a, uint32_t b0, uint32_t b1){
    asm volatile("mma.sync.aligned.m16n8k16.row.col.f32.f16.f16.f32 "
        "{%0,%1,%2,%3}, {%4,%5,%6,%7}, {%8,%9}, {%0,%1,%2,%3};"
        : "+f"(d[0]),"+f"(d[1]),"+f"(d[2]),"+f"(d[3])
        : "r"(a[0]),"r"(a[1]),"r"(a[2]),"r"(a[3]), "r"(b0), "r"(b1));
}
__device__ __forceinline__ float gelu_exact(float x) {
    return 0.5f * x * (1.0f + erff(x * 0.70710678118654752440f));
}
__device__ __forceinline__ __half2 h2of(float a, float b){
    __half2 h; h.x = __float2half_rn(a); h.y = __float2half_rn(b); return h;
}

// ---------------- LayerNorm -> fp16 plain ----------------
__global__ void ln_h(const float* __restrict__ x, const float* __restrict__ g,
                     const float* __restrict__ b, __half* __restrict__ y)
{
    __shared__ float red[8];
    int row = blockIdx.x;
    int t = threadIdx.x;
    float4 v = ((const float4*)(x + (size_t)row*DD))[t];
    float s  = v.x+v.y+v.z+v.w;
    float s2 = v.x*v.x+v.y*v.y+v.z*v.z+v.w*v.w;
    #pragma unroll
    for (int o=16;o>0;o>>=1){
        s  += __shfl_xor_sync(0xffffffffu, s,  o);
        s2 += __shfl_xor_sync(0xffffffffu, s2, o);
    }
    if ((t&31)==0){ red[t>>5]=s; red[4+(t>>5)]=s2; }
    __syncthreads();
    s  = red[0]+red[1]+red[2]+red[3];
    s2 = red[4]+red[5]+red[6]+red[7];
    float mu  = s * (1.0f/DD);
    float var = s2 * (1.0f/DD) - mu*mu;
    float inv = rsqrtf(var + 1e-5f);
    float4 gv = ((const float4*)g)[t];
    float4 bv = ((const float4*)b)[t];
    __half* yr = y + (size_t)row*DD + 4*t;
    *(__half2*)(yr)   = h2of((v.x-mu)*inv*gv.x + bv.x, (v.y-mu)*inv*gv.y + bv.y);
    *(__half2*)(yr+2) = h2of((v.z-mu)*inv*gv.z + bv.z, (v.w-mu)*inv*gv.w + bv.w);
}

// ---------------- fp32 -> fp16 plain ----------------
__global__ void toH(const float* __restrict__ in, __half* __restrict__ out, int total4)
{
    int i = blockIdx.x*blockDim.x + threadIdx.x;
    if (i >= total4) return;
    size_t e = (size_t)i*4;
    float4 v = *(const float4*)(in + e);
    *(__half2*)(out + e)     = h2of(v.x, v.y);
    *(__half2*)(out + e + 2) = h2of(v.z, v.w);
}

// ---------------- transpose -> fp16: W[512k][512n] -> out[n][512k] ----------------
__global__ void tpH(const float* __restrict__ Win, __half* __restrict__ out)
{
    __shared__ float t[32][33];
    int bk = blockIdx.y*32, bn = blockIdx.x*32;
    int x = threadIdx.x, y = threadIdx.y;
    #pragma unroll
    for (int j=0;j<4;j++)
        t[y+8*j][x] = Win[(size_t)(bk+y+8*j)*DD + bn + x];
    __syncthreads();
    #pragma unroll
    for (int j=0;j<4;j++){
        int n = bn + y + 8*j;
        out[(size_t)n*DD + bk + x] = __float2half_rn(t[x][y+8*j]);
    }
}

// ================= fp16 1-pass GEMM (mma.sync) =================
// C = A * B^T : A plain fp16 [M][K], B plain fp16 [N][K].
// 128x128 tile, 64-k chunks, 2-stage cp.async, stage = 32KB (A 16K + B 16K).
// EPI: 1 fp32+resid ; 2 gelu(+bias)->fp16 plain ; 3 fp32+bias+resid ; 4 fp16 plain
#define GH_STAGE 32768
#define GH_SMEM  (2*GH_STAGE)

template<int EPI>
__global__ __launch_bounds__(256,2)
void gemm_h(const __half* __restrict__ A, const __half* __restrict__ B,
            int N, int K,
            const float* __restrict__ bias, const float* __restrict__ resid,
            float* __restrict__ Cf, __half* __restrict__ Ch)
{
    extern __shared__ char smc[];
    uint32_t sb = smem_u32(smc);
    const int tid = threadIdx.x, lane = tid&31, w = tid>>5;
    const int wr = w>>2, wc = w&3;
    const int rowBase = blockIdx.y*128, colBase = blockIdx.x*128;
    const int nC = K>>6;

    float acc[4][4][4];
    #pragma unroll
    for (int a=0;a<4;a++)
        #pragma unroll
        for (int b=0;b<4;b++)
            #pragma unroll
            for (int c=0;c<4;c++) acc[a][b][c]=0.f;

#define H_LOAD(chunk, s) do{                                                   \
    uint32_t sA_ = sb + (uint32_t)(s)*GH_STAGE;                                \
    uint32_t sB_ = sA_ + 16384u;                                               \
    _Pragma("unroll")                                                          \
    for (int i_=0;i_<4;i_++){                                                  \
        int idx_ = tid*4 + i_; int r_ = idx_>>3, u_ = idx_&7;                  \
        cp16(sA_ + (uint32_t)(r_*128 + ((u_^(r_&7))<<4)),                      \
             A + (size_t)(rowBase+r_)*K + (chunk)*64 + u_*8);                  \
        cp16(sB_ + (uint32_t)(r_*128 + ((u_^(r_&7))<<4)),                      \
             B + (size_t)(colBase+r_)*K + (chunk)*64 + u_*8);                  \
    } cp_commit(); } while(0)

    H_LOAD(0, 0);
    if (nC > 1) H_LOAD(1, 1);

    for (int c=0;c<nC;c++){
        int s = c & 1;
        if (c == nC-1) cp_wait0(); else cp_wait1();
        __syncthreads();
        uint32_t sA = sb + (uint32_t)s*GH_STAGE;
        uint32_t sB = sA + 16384u;
        #pragma unroll
        for (int ks=0;ks<4;ks++){
            uint32_t ah[4][4], bh4[2][4];
            #pragma unroll
            for (int mt=0;mt<4;mt++){
                int r = wr*64 + mt*16 + (lane&15);
                uint32_t u = ks*2 + (lane>>4);
                ldsm4(ah[mt], sA + r*128 + ((u^(r&7))<<4));
            }
            #pragma unroll
            for (int np=0;np<2;np++){
                int r = wc*32 + np*16 + (lane&15);
                uint32_t u = ks*2 + (lane>>4);
                ldsm4(bh4[np], sB + r*128 + ((u^(r&7))<<4));
            }
            #pragma unroll
            for (int mt=0;mt<4;mt++)
                #pragma unroll
                for (int nt=0;nt<4;nt++)
                    mmafp(acc[mt][nt], ah[mt], bh4[nt>>1][nt&1], bh4[nt>>1][2+(nt&1)]);
        }
        __syncthreads();
        if (c+2 < nC) H_LOAD(c+2, s);
    }
#undef H_LOAD

    int ra = lane>>2;
    #pragma unroll
    for (int mt=0;mt<4;mt++){
        int r0 = rowBase + wr*64 + mt*16 + ra;
        #pragma unroll
        for (int nt=0;nt<4;nt++){
            int n0 = colBase + wc*32 + nt*8 + 2*(lane&3);
            float* a = acc[mt][nt];
            #pragma unroll
            for (int hh=0;hh<2;hh++){
                int r = r0 + hh*8;
                float v0 = a[2*hh+0], v1 = a[2*hh+1];
                if (EPI==2){
                    v0 = gelu_exact(v0 + bias[n0]); v1 = gelu_exact(v1 + bias[n0+1]);
                    *(__half2*)(Ch + (size_t)r*N + n0) = h2of(v0, v1);
                } else if (EPI==4){
                    *(__half2*)(Ch + (size_t)r*N + n0) = h2of(v0, v1);
                } else {
                    size_t o = (size_t)r*N + n0;
                    if (EPI==1){ v0 += resid[o]; v1 += resid[o+1]; }
                    else       { v0 += bias[n0] + resid[o]; v1 += bias[n0+1] + resid[o+1]; }
                    float2 f2; f2.x=v0; f2.y=v1;
                    *(float2*)(Cf + o) = f2;
                }
            }
        }
    }
}

// ================= Flash attention (fp16 1-pass mma.sync) =================
// smem: Q 16K | 2 stages x [K 8K | V 8K] = 48KB total
#define A_Q  0u
#define A_KV 16384u
#define ATTN_SMEM 49152

__global__ __launch_bounds__(256,2)
void attn_mma(const __half* __restrict__ q2h, const __half* __restrict__ k2h,
              const __half* __restrict__ v2h, __half* __restrict__ ctxH)
{
    extern __shared__ char smc[];
    uint32_t sb = smem_u32(smc);
    const int tid = threadIdx.x, lane = tid&31, w = tid>>5;
    const int qt = blockIdx.x, h = blockIdx.y, b = blockIdx.z;
    const int rowQ0 = b*SS + qt*128;

#define KV_LOAD(it, s) do{                                                     \
    uint32_t stg_ = sb + A_KV + (uint32_t)(s)*16384u;                          \
    int rk0_ = b*SS + (it)*64;                                                 \
    _Pragma("unroll")                                                          \
    for (int i_=0;i_<4;i_++){                                                  \
        int idx_ = tid*4 + i_;                                                 \
        if (idx_ < 512){                                                       \
            int r_ = idx_>>3, u_ = idx_&7;                                     \
            cp16(stg_ + (uint32_t)(r_*128 + (((uint32_t)u_^(r_&7))<<4)),       \
                 k2h + (size_t)(rk0_+r_)*512 + h*64 + u_*8);                   \
        } else {                                                               \
            int j_ = idx_ - 512; int r_ = j_>>3, u_ = j_&7;                    \
            cp16(stg_ + 8192u + (uint32_t)(r_*128 + (((uint32_t)u_^(r_&7))<<4)), \
                 v2h + (size_t)(rk0_+r_)*512 + h*64 + u_*8);                   \
        }                                                                      \
    } cp_commit(); } while(0)

    {
        #pragma unroll
        for (int i=0;i<4;i++){
            int idx = tid*4 + i;
            int r = idx>>3, u = idx&7;
            cp16(sb + A_Q + (uint32_t)(r*128 + (((uint32_t)u^(r&7))<<4)),
                 q2h + (size_t)(rowQ0+r)*512 + h*64 + u*8);
        }
        KV_LOAD(0, 0);
        KV_LOAD(1, 1);
    }

    uint32_t qh[4][4];
    float m0=-INFINITY, m1=-INFINITY, l0=0.f, l1=0.f;
    float ctx[8][4];
    #pragma unroll
    for (int nt=0;nt<8;nt++){ ctx[nt][0]=0;ctx[nt][1]=0;ctx[nt][2]=0;ctx[nt][3]=0; }
    const float SCALE = (float)(1.0/(8.0 + 1e-6));

    for (int it=0; it<SS/64; it++){
        int s = it&1;
        if (it == SS/64-1) cp_wait0(); else cp_wait1();
        __syncthreads();
        if (it == 0){
            #pragma unroll
            for (int ks=0;ks<4;ks++){
                int r = w*16 + (lane&15);
                uint32_t u = ks*2 + (lane>>4);
                ldsm4(qh[ks], sb + A_Q + r*128 + ((u^(r&7))<<4));
            }
        }
        uint32_t sK = sb + A_KV + (uint32_t)s*16384u;
        uint32_t sV = sK + 8192u;

        // ---- QK^T (1-pass fp16) ----
        float sc[8][4];
        #pragma unroll
        for (int nt=0;nt<8;nt++){ sc[nt][0]=0;sc[nt][1]=0;sc[nt][2]=0;sc[nt][3]=0; }
        #pragma unroll
        for (int ks=0;ks<4;ks++){
            uint32_t kh4[4][4];
            #pragma unroll
            for (int np=0;np<4;np++){
                int r = np*16 + (lane&15);
                uint32_t u = ks*2 + (lane>>4);
                ldsm4(kh4[np], sK + r*128 + ((u^(r&7))<<4));
            }
            #pragma unroll
            for (int nt=0;nt<8;nt++)
                mmafp(sc[nt], qh[ks], kh4[nt>>1][nt&1], kh4[nt>>1][2+(nt&1)]);
        }

        // ---- streaming softmax (rows lane>>2 and +8) ----
        float mxa=-INFINITY, mxb=-INFINITY;
        #pragma unroll
        for (int nt=0;nt<8;nt++){
            sc[nt][0]*=SCALE; sc[nt][1]*=SCALE; sc[nt][2]*=SCALE; sc[nt][3]*=SCALE;
            mxa = fmaxf(mxa, fmaxf(sc[nt][0], sc[nt][1]));
            mxb = fmaxf(mxb, fmaxf(sc[nt][2], sc[nt][3]));
        }
        mxa = fmaxf(mxa, __shfl_xor_sync(0xffffffffu, mxa, 1));
        mxa = fmaxf(mxa, __shfl_xor_sync(0xffffffffu, mxa, 2));
        mxb = fmaxf(mxb, __shfl_xor_sync(0xffffffffu, mxb, 1));
        mxb = fmaxf(mxb, __shfl_xor_sync(0xffffffffu, mxb, 2));
        float na = fmaxf(m0, mxa), nb = fmaxf(m1, mxb);
        float ca = __expf(m0 - na), cb = __expf(m1 - nb);
        m0 = na; m1 = nb;
        float sa = 0.f, sbm = 0.f;
        #pragma unroll
        for (int nt=0;nt<8;nt++){
            float p0 = __expf(sc[nt][0]-na), p1 = __expf(sc[nt][1]-na);
            float p2 = __expf(sc[nt][2]-nb), p3 = __expf(sc[nt][3]-nb);
            sc[nt][0]=p0; sc[nt][1]=p1; sc[nt][2]=p2; sc[nt][3]=p3;
            sa += p0+p1; sbm += p2+p3;
        }
        sa  += __shfl_xor_sync(0xffffffffu, sa, 1);
        sa  += __shfl_xor_sync(0xffffffffu, sa, 2);
        sbm += __shfl_xor_sync(0xffffffffu, sbm, 1);
        sbm += __shfl_xor_sync(0xffffffffu, sbm, 2);
        l0 = l0*ca + sa; l1 = l1*cb + sbm;
        #pragma unroll
        for (int nt=0;nt<8;nt++){ ctx[nt][0]*=ca; ctx[nt][1]*=ca; ctx[nt][2]*=cb; ctx[nt][3]*=cb; }

        // ---- P @ V (1-pass fp16, register P frags) ----
        #pragma unroll
        for (int ks=0;ks<4;ks++){
            uint32_t aPh[4];
            {
                __half2 t;
                t = h2of(sc[2*ks  ][0], sc[2*ks  ][1]); aPh[0] = *(uint32_t*)&t;
                t = h2of(sc[2*ks  ][2], sc[2*ks  ][3]); aPh[1] = *(uint32_t*)&t;
                t = h2of(sc[2*ks+1][0], sc[2*ks+1][1]); aPh[2] = *(uint32_t*)&t;
                t = h2of(sc[2*ks+1][2], sc[2*ks+1][3]); aPh[3] = *(uint32_t*)&t;
            }
            uint32_t vh4[4][4];
            #pragma unroll
            for (int np2=0;np2<4;np2++){
                int r = ks*16 + (lane&15);
                uint32_t u = np2*2 + (lane>>4);
                ldsm4t(vh4[np2], sV + r*128 + ((u^(r&7))<<4));
            }
            #pragma unroll
            for (int np2=0;np2<4;np2++)
                #pragma unroll
                for (int q2i=0;q2i<2;q2i++)
                    mmafp(ctx[np2*2+q2i], aPh, vh4[np2][q2i*2], vh4[np2][q2i*2+1]);
        }
        __syncthreads();
        if (it+2 < SS/64) KV_LOAD(it+2, s);
    }
#undef KV_LOAD

    // normalize + write ctx plain fp16 [row][512]
    float i0 = 1.0f/l0, i1 = 1.0f/l1;
    #pragma unroll
    for (int nt=0;nt<8;nt++){
        int d = nt*8 + 2*(lane&3);
        int col = h*64 + d;
        int rA = rowQ0 + w*16 + (lane>>2);
        *(__half2*)(ctxH + (size_t)rA*DD + col)     = h2of(ctx[nt][0]*i0, ctx[nt][1]*i0);
        *(__half2*)(ctxH + (size_t)(rA+8)*DD + col) = h2of(ctx[nt][2]*i1, ctx[nt][3]*i1);
    }
}

extern "C" void kernel_launch(void* const* d_in, const int* in_sizes, int n_in,
                              void* d_out, int out_size)
{
    (void)in_sizes; (void)n_in; (void)out_size;
    const float* Q     = (const float*)d_in[0];
    const float* Kin   = (const float*)d_in[1];
    const float* Vin   = (const float*)d_in[2];
    const float* W_q   = (const float*)d_in[3];
    const float* W_k   = (const float*)d_in[4];
    const float* W_v   = (const float*)d_in[5];
    const float* W_o   = (const float*)d_in[6];
    const float* ln1_g = (const float*)d_in[7];
    const float* ln1_b = (const float*)d_in[8];
    const float* ln2_g = (const float*)d_in[9];
    const float* ln2_b = (const float*)d_in[10];
    const float* w1    = (const float*)d_in[11];
    const float* b1    = (const float*)d_in[12];
    const float* w2    = (const float*)d_in[13];
    const float* b2    = (const float*)d_in[14];
    float* out = (float*)d_out;

    __half *QnH,*KinH,*VinH,*q2h,*k2h,*v2h,*ctxH,*XnH,*hH;
    __half *WqH,*WkH,*WvH,*WoH,*w1H,*w2H;
    float *X;
    cudaGetSymbolAddress((void**)&QnH,  g_QnH);
    cudaGetSymbolAddress((void**)&KinH, g_KinH);
    cudaGetSymbolAddress((void**)&VinH, g_VinH);
    cudaGetSymbolAddress((void**)&q2h,  g_q2h);
    cudaGetSymbolAddress((void**)&k2h,  g_k2h);
    cudaGetSymbolAddress((void**)&v2h,  g_v2h);
    cudaGetSymbolAddress((void**)&ctxH, g_ctxH);
    cudaGetSymbolAddress((void**)&XnH,  g_XnH);
    cudaGetSymbolAddress((void**)&hH,   g_hH);
    cudaGetSymbolAddress((void**)&X,    g_X);
    cudaGetSymbolAddress((void**)&WqH,  g_WqH);
    cudaGetSymbolAddress((void**)&WkH,  g_WkH);
    cudaGetSymbolAddress((void**)&WvH,  g_WvH);
    cudaGetSymbolAddress((void**)&WoH,  g_WoH);
    cudaGetSymbolAddress((void**)&w1H,  g_w1H);
    cudaGetSymbolAddress((void**)&w2H,  g_w2H);

    cudaFuncSetAttribute(attn_mma,    cudaFuncAttributeMaxDynamicSharedMemorySize, ATTN_SMEM);
    cudaFuncSetAttribute(gemm_h<1>, cudaFuncAttributeMaxDynamicSharedMemorySize, GH_SMEM);
    cudaFuncSetAttribute(gemm_h<2>, cudaFuncAttributeMaxDynamicSharedMemorySize, GH_SMEM);
    cudaFuncSetAttribute(gemm_h<3>, cudaFuncAttributeMaxDynamicSharedMemorySize, GH_SMEM);
    cudaFuncSetAttribute(gemm_h<4>, cudaFuncAttributeMaxDynamicSharedMemorySize, GH_SMEM);

    dim3 tb(32, 8), tg(16, 16);

    // conversions (all plain fp16 now)
    ln_h<<<ROWS,128>>>(Q, ln1_g, ln1_b, QnH);
    toH<<<(ROWS*DD/4+255)/256,256>>>(Kin, KinH, ROWS*DD/4);
    toH<<<(ROWS*DD/4+255)/256,256>>>(Vin, VinH, ROWS*DD/4);
    tpH<<<tg, tb>>>(W_q, WqH);
    tpH<<<tg, tb>>>(W_k, WkH);
    tpH<<<tg, tb>>>(W_v, WvH);
    tpH<<<tg, tb>>>(W_o, WoH);
    toH<<<(DFF*DD/4+255)/256,256>>>(w1, w1H, DFF*DD/4);
    toH<<<(DD*DFF/4+255)/256,256>>>(w2, w2H, DD*DFF/4);

    // projections
    gemm_h<4><<<dim3(DD/128,  ROWS/128), 256, GH_SMEM>>>(QnH,  WqH, DD,  DD,  nullptr, nullptr, nullptr, q2h);
    gemm_h<4><<<dim3(DD/128,  ROWS/128), 256, GH_SMEM>>>(KinH, WkH, DD,  DD,  nullptr, nullptr, nullptr, k2h);
    gemm_h<4><<<dim3(DD/128,  ROWS/128), 256, GH_SMEM>>>(VinH, WvH, DD,  DD,  nullptr, nullptr, nullptr, v2h);
    // attention
    attn_mma<<<dim3(SS/128, HH, BB), 256, ATTN_SMEM>>>(q2h, k2h, v2h, ctxH);
    // X = Q + ctx @ Wo
    gemm_h<1><<<dim3(DD/128,  ROWS/128), 256, GH_SMEM>>>(ctxH, WoH, DD,  DD,  nullptr, Q, X, nullptr);
    // LN2 + FFN
    ln_h<<<ROWS,128>>>(X, ln2_g, ln2_b, XnH);
    gemm_h<2><<<dim3(DFF/128, ROWS/128), 256, GH_SMEM>>>(XnH, w1H, DFF, DD,  b1, nullptr, nullptr, hH);
    gemm_h<3><<<dim3(DD/128,  ROWS/128), 256, GH_SMEM>>>(hH,  w2H, DD,  DFF, b2, X, out, nullptr);
}

// round 17
// speedup vs baseline: 6.0695x; 1.0079x over previous
#include <cuda_runtime.h>
#include <cuda_fp16.h>
#include <cstdint>
#include <math.h>

#define BB   2
#define SS   4096
#define DD   512
#define HH   8
#define ROWS (BB*SS)
#define DFF  2048

// activations: plain fp16 [row][C]
__device__ __half g_QnH [ROWS*DD];
__device__ __half g_KinH[ROWS*DD];
__device__ __half g_VinH[ROWS*DD];
__device__ __half g_q2h [ROWS*DD];
__device__ __half g_k2h [ROWS*DD];
__device__ __half g_v2h [ROWS*DD];
__device__ __half g_ctxH[ROWS*DD];
__device__ __half g_XnH [ROWS*DD];
__device__ __half g_hH  [(size_t)ROWS*DFF];
__device__ float  g_X   [ROWS*DD];
// weights: plain fp16 [n][K]
__device__ __half g_WqH [DD*DD];
__device__ __half g_WkH [DD*DD];
__device__ __half g_WvH [DD*DD];
__device__ __half g_WoH [DD*DD];
__device__ __half g_w1H [DFF*DD];
__device__ __half g_w2H [DD*DFF];

// ---------------- asm helpers ----------------
__device__ __forceinline__ uint32_t smem_u32(const void* p) {
    uint32_t a;
    asm("{ .reg .u64 t; cvta.to.shared.u64 t, %1; cvt.u32.u64 %0, t; }" : "=r"(a) : "l"(p));
    return a;
}
__device__ __forceinline__ void cp16(uint32_t dst, const void* src){
    asm volatile("cp.async.cg.shared.global [%0], [%1], 16;" :: "r"(dst), "l"(src));
}
__device__ __forceinline__ void cp_commit(){ asm volatile("cp.async.commit_group;" ::: "memory"); }
__device__ __forceinline__ void cp_wait0(){ asm volatile("cp.async.wait_group 0;" ::: "memory"); }
__device__ __forceinline__ void cp_wait1(){ asm volatile("cp.async.wait_group 1;" ::: "memory"); }

__device__ __forceinline__ void ldsm4(uint32_t* r, uint32_t a){
    asm volatile("ldmatrix.sync.aligned.m8n8.x4.shared.b16 {%0,%1,%2,%3}, [%4];"
        : "=r"(r[0]),"=r"(r[1]),"=r"(r[2]),"=r"(r[3]) : "r"(a));
}
__device__ __forceinline__ void ldsm4t(uint32_t* r, uint32_t a){
    asm volatile("ldmatrix.sync.aligned.m8n8.x4.trans.shared.b16 {%0,%1,%2,%3}, [%4];"
        : "=r"(r[0]),"=r"(r[1]),"=r"(r[2]),"=r"(r[3]) : "r"(a));
}
__device__ __forceinline__ void mmafp(float* d, const uint32_t* a, uint32_t b0, uint32_t b1){
    asm volatile("mma.sync.aligned.m16n8k16.row.col.f32.f16.f16.f32 "
        "{%0,%1,%2,%3}, {%4,%5,%6,%7}, {%8,%9}, {%0,%1,%2,%3};"
        : "+f"(d[0]),"+f"(d[1]),"+f"(d[2]),"+f"(d[3])
        : "r"(a[0]),"r"(a[1]),"r"(a[2]),"r"(a[3]), "r"(b0), "r"(b1));
}
__device__ __forceinline__ float gelu_exact(float x) {
    return 0.5f * x * (1.0f + erff(x * 0.70710678118654752440f));
}
__device__ __forceinline__ __half2 h2of(float a, float b){
    __half2 h; h.x = __float2half_rn(a); h.y = __float2half_rn(b); return h;
}

// ---------------- LayerNorm -> fp16 plain ----------------
__global__ void ln_h(const float* __restrict__ x, const float* __restrict__ g,
                     const float* __restrict__ b, __half* __restrict__ y)
{
    __shared__ float red[8];
    int row = blockIdx.x;
    int t = threadIdx.x;
    float4 v = ((const float4*)(x + (size_t)row*DD))[t];
    float s  = v.x+v.y+v.z+v.w;
    float s2 = v.x*v.x+v.y*v.y+v.z*v.z+v.w*v.w;
    #pragma unroll
    for (int o=16;o>0;o>>=1){
        s  += __shfl_xor_sync(0xffffffffu, s,  o);
        s2 += __shfl_xor_sync(0xffffffffu, s2, o);
    }
    if ((t&31)==0){ red[t>>5]=s; red[4+(t>>5)]=s2; }
    __syncthreads();
    s  = red[0]+red[1]+red[2]+red[3];
    s2 = red[4]+red[5]+red[6]+red[7];
    float mu  = s * (1.0f/DD);
    float var = s2 * (1.0f/DD) - mu*mu;
    float inv = rsqrtf(var + 1e-5f);
    float4 gv = ((const float4*)g)[t];
    float4 bv = ((const float4*)b)[t];
    __half* yr = y + (size_t)row*DD + 4*t;
    *(__half2*)(yr)   = h2of((v.x-mu)*inv*gv.x + bv.x, (v.y-mu)*inv*gv.y + bv.y);
    *(__half2*)(yr+2) = h2of((v.z-mu)*inv*gv.z + bv.z, (v.w-mu)*inv*gv.w + bv.w);
}

// ---------------- fp32 -> fp16 plain (two tensors in one launch) ----------------
__global__ void toH2(const float* __restrict__ in1, __half* __restrict__ out1,
                     const float* __restrict__ in2, __half* __restrict__ out2,
                     int total4)
{
    int i = blockIdx.x*blockDim.x + threadIdx.x;
    const float* in;
    __half* out;
    if (i < total4){ in = in1; out = out1; }
    else { in = in2; out = out2; i -= total4; if (i >= total4) return; }
    size_t e = (size_t)i*4;
    float4 v = *(const float4*)(in + e);
    *(__half2*)(out + e)     = h2of(v.x, v.y);
    *(__half2*)(out + e + 2) = h2of(v.z, v.w);
}

__global__ void toH(const float* __restrict__ in, __half* __restrict__ out, int total4)
{
    int i = blockIdx.x*blockDim.x + threadIdx.x;
    if (i >= total4) return;
    size_t e = (size_t)i*4;
    float4 v = *(const float4*)(in + e);
    *(__half2*)(out + e)     = h2of(v.x, v.y);
    *(__half2*)(out + e + 2) = h2of(v.z, v.w);
}

// ---------------- transpose -> fp16: W[512k][512n] -> out[n][512k] ----------------
__global__ void tpH(const float* __restrict__ Win, __half* __restrict__ out)
{
    __shared__ float t[32][33];
    int bk = blockIdx.y*32, bn = blockIdx.x*32;
    int x = threadIdx.x, y = threadIdx.y;
    #pragma unroll
    for (int j=0;j<4;j++)
        t[y+8*j][x] = Win[(size_t)(bk+y+8*j)*DD + bn + x];
    __syncthreads();
    #pragma unroll
    for (int j=0;j<4;j++){
        int n = bn + y + 8*j;
        out[(size_t)n*DD + bk + x] = __float2half_rn(t[x][y+8*j]);
    }
}

// ================= fp16 1-pass GEMM (mma.sync, 3-stage single-sync) =================
// C = A * B^T : A plain fp16 [M][K], B plain fp16 [N][K].
// 128x128 tile, 64-k chunks, 3-stage cp.async, ONE barrier per chunk.
// EPI: 1 fp32+resid ; 2 gelu(+bias)->fp16 plain ; 3 fp32+bias+resid ; 4 fp16 plain
#define GH_STAGE 32768
#define GH_SMEM  (3*GH_STAGE)

template<int EPI>
__global__ __launch_bounds__(256,2)
void gemm_h(const __half* __restrict__ A, const __half* __restrict__ B,
            int N, int K,
            const float* __restrict__ bias, const float* __restrict__ resid,
            float* __restrict__ Cf, __half* __restrict__ Ch)
{
    extern __shared__ char smc[];
    uint32_t sb = smem_u32(smc);
    const int tid = threadIdx.x, lane = tid&31, w = tid>>5;
    const int wr = w>>2, wc = w&3;
    const int rowBase = blockIdx.y*128, colBase = blockIdx.x*128;
    const int nC = K>>6;

    float acc[4][4][4];
    #pragma unroll
    for (int a=0;a<4;a++)
        #pragma unroll
        for (int b=0;b<4;b++)
            #pragma unroll
            for (int c=0;c<4;c++) acc[a][b][c]=0.f;

#define H_LOAD(chunk, s) do{                                                   \
    uint32_t sA_ = sb + (uint32_t)(s)*GH_STAGE;                                \
    uint32_t sB_ = sA_ + 16384u;                                               \
    _Pragma("unroll")                                                          \
    for (int i_=0;i_<4;i_++){                                                  \
        int idx_ = tid*4 + i_; int r_ = idx_>>3, u_ = idx_&7;                  \
        cp16(sA_ + (uint32_t)(r_*128 + ((u_^(r_&7))<<4)),                      \
             A + (size_t)(rowBase+r_)*K + (chunk)*64 + u_*8);                  \
        cp16(sB_ + (uint32_t)(r_*128 + ((u_^(r_&7))<<4)),                      \
             B + (size_t)(colBase+r_)*K + (chunk)*64 + u_*8);                  \
    } cp_commit(); } while(0)

    H_LOAD(0, 0);
    H_LOAD(1, 1);

    for (int c=0;c<nC;c++){
        if (c+1 < nC) cp_wait1(); else cp_wait0();
        __syncthreads();
        if (c+2 < nC) H_LOAD(c+2, (c+2)%3);   // slot (c-1)%3, protected by the sync above
        uint32_t sA = sb + (uint32_t)(c%3)*GH_STAGE;
        uint32_t sB = sA + 16384u;
        #pragma unroll
        for (int ks=0;ks<4;ks++){
            uint32_t ah[4][4], bh4[2][4];
            #pragma unroll
            for (int mt=0;mt<4;mt++){
                int r = wr*64 + mt*16 + (lane&15);
                uint32_t u = ks*2 + (lane>>4);
                ldsm4(ah[mt], sA + r*128 + ((u^(r&7))<<4));
            }
            #pragma unroll
            for (int np=0;np<2;np++){
                int r = wc*32 + np*16 + (lane&15);
                uint32_t u = ks*2 + (lane>>4);
                ldsm4(bh4[np], sB + r*128 + ((u^(r&7))<<4));
            }
            #pragma unroll
            for (int mt=0;mt<4;mt++)
                #pragma unroll
                for (int nt=0;nt<4;nt++)
                    mmafp(acc[mt][nt], ah[mt], bh4[nt>>1][nt&1], bh4[nt>>1][2+(nt&1)]);
        }
    }
#undef H_LOAD

    int ra = lane>>2;
    #pragma unroll
    for (int mt=0;mt<4;mt++){
        int r0 = rowBase + wr*64 + mt*16 + ra;
        #pragma unroll
        for (int nt=0;nt<4;nt++){
            int n0 = colBase + wc*32 + nt*8 + 2*(lane&3);
            float* a = acc[mt][nt];
            #pragma unroll
            for (int hh=0;hh<2;hh++){
                int r = r0 + hh*8;
                float v0 = a[2*hh+0], v1 = a[2*hh+1];
                if (EPI==2){
                    v0 = gelu_exact(v0 + bias[n0]); v1 = gelu_exact(v1 + bias[n0+1]);
                    *(__half2*)(Ch + (size_t)r*N + n0) = h2of(v0, v1);
                } else if (EPI==4){
                    *(__half2*)(Ch + (size_t)r*N + n0) = h2of(v0, v1);
                } else {
                    size_t o = (size_t)r*N + n0;
                    if (EPI==1){ v0 += resid[o]; v1 += resid[o+1]; }
                    else       { v0 += bias[n0] + resid[o]; v1 += bias[n0+1] + resid[o+1]; }
                    float2 f2; f2.x=v0; f2.y=v1;
                    *(float2*)(Cf + o) = f2;
                }
            }
        }
    }
}

// ================= Flash attention (fp16 1-pass, 3-stage single-sync) =================
// smem: Q 16K | 3 stages x [K 8K | V 8K] = 64KB total
#define A_Q  0u
#define A_KV 16384u
#define ATTN_SMEM 65536

__global__ __launch_bounds__(256,2)
void attn_mma(const __half* __restrict__ q2h, const __half* __restrict__ k2h,
              const __half* __restrict__ v2h, __half* __restrict__ ctxH)
{
    extern __shared__ char smc[];
    uint32_t sb = smem_u32(smc);
    const int tid = threadIdx.x, lane = tid&31, w = tid>>5;
    const int qt = blockIdx.x, h = blockIdx.y, b = blockIdx.z;
    const int rowQ0 = b*SS + qt*128;

#define KV_LOAD(it, s) do{                                                     \
    uint32_t stg_ = sb + A_KV + (uint32_t)(s)*16384u;                          \
    int rk0_ = b*SS + (it)*64;                                                 \
    _Pragma("unroll")                                                          \
    for (int i_=0;i_<4;i_++){                                                  \
        int idx_ = tid*4 + i_;                                                 \
        if (idx_ < 512){                                                       \
            int r_ = idx_>>3, u_ = idx_&7;                                     \
            cp16(stg_ + (uint32_t)(r_*128 + (((uint32_t)u_^(r_&7))<<4)),       \
                 k2h + (size_t)(rk0_+r_)*512 + h*64 + u_*8);                   \
        } else {                                                               \
            int j_ = idx_ - 512; int r_ = j_>>3, u_ = j_&7;                    \
            cp16(stg_ + 8192u + (uint32_t)(r_*128 + (((uint32_t)u_^(r_&7))<<4)), \
                 v2h + (size_t)(rk0_+r_)*512 + h*64 + u_*8);                   \
        }                                                                      \
    } cp_commit(); } while(0)

    {
        #pragma unroll
        for (int i=0;i<4;i++){
            int idx = tid*4 + i;
            int r = idx>>3, u = idx&7;
            cp16(sb + A_Q + (uint32_t)(r*128 + (((uint32_t)u^(r&7))<<4)),
                 q2h + (size_t)(rowQ0+r)*512 + h*64 + u*8);
        }
        KV_LOAD(0, 0);   // Q rides with group 0
        KV_LOAD(1, 1);
    }

    uint32_t qh[4][4];
    float m0=-INFINITY, m1=-INFINITY, l0=0.f, l1=0.f;
    float ctx[8][4];
    #pragma unroll
    for (int nt=0;nt<8;nt++){ ctx[nt][0]=0;ctx[nt][1]=0;ctx[nt][2]=0;ctx[nt][3]=0; }
    // exp2 domain: scores scaled by (1/(sqrt(dk)+eps)) * log2(e)
    const float SCALE2 = (float)((1.0/(8.0 + 1e-6)) * 1.4426950408889634);

    for (int it=0; it<SS/64; it++){
        if (it+1 < SS/64) cp_wait1(); else cp_wait0();
        __syncthreads();
        if (it+2 < SS/64) KV_LOAD(it+2, (it+2)%3);   // slot (it-1)%3, protected by sync
        if (it == 0){
            #pragma unroll
            for (int ks=0;ks<4;ks++){
                int r = w*16 + (lane&15);
                uint32_t u = ks*2 + (lane>>4);
                ldsm4(qh[ks], sb + A_Q + r*128 + ((u^(r&7))<<4));
            }
        }
        uint32_t sK = sb + A_KV + (uint32_t)(it%3)*16384u;
        uint32_t sV = sK + 8192u;

        // ---- QK^T (1-pass fp16) ----
        float sc[8][4];
        #pragma unroll
        for (int nt=0;nt<8;nt++){ sc[nt][0]=0;sc[nt][1]=0;sc[nt][2]=0;sc[nt][3]=0; }
        #pragma unroll
        for (int ks=0;ks<4;ks++){
            uint32_t kh4[4][4];
            #pragma unroll
            for (int np=0;np<4;np++){
                int r = np*16 + (lane&15);
                uint32_t u = ks*2 + (lane>>4);
                ldsm4(kh4[np], sK + r*128 + ((u^(r&7))<<4));
            }
            #pragma unroll
            for (int nt=0;nt<8;nt++)
                mmafp(sc[nt], qh[ks], kh4[nt>>1][nt&1], kh4[nt>>1][2+(nt&1)]);
        }

        // ---- streaming softmax in exp2 domain (rows lane>>2 and +8) ----
        float mxa=-INFINITY, mxb=-INFINITY;
        #pragma unroll
        for (int nt=0;nt<8;nt++){
            sc[nt][0]*=SCALE2; sc[nt][1]*=SCALE2; sc[nt][2]*=SCALE2; sc[nt][3]*=SCALE2;
            mxa = fmaxf(mxa, fmaxf(sc[nt][0], sc[nt][1]));
            mxb = fmaxf(mxb, fmaxf(sc[nt][2], sc[nt][3]));
        }
        mxa = fmaxf(mxa, __shfl_xor_sync(0xffffffffu, mxa, 1));
        mxa = fmaxf(mxa, __shfl_xor_sync(0xffffffffu, mxa, 2));
        mxb = fmaxf(mxb, __shfl_xor_sync(0xffffffffu, mxb, 1));
        mxb = fmaxf(mxb, __shfl_xor_sync(0xffffffffu, mxb, 2));
        float na = fmaxf(m0, mxa), nb = fmaxf(m1, mxb);
        float ca = exp2f(m0 - na), cb = exp2f(m1 - nb);
        m0 = na; m1 = nb;
        float sa = 0.f, sbm = 0.f;
        #pragma unroll
        for (int nt=0;nt<8;nt++){
            float p0 = exp2f(sc[nt][0]-na), p1 = exp2f(sc[nt][1]-na);
            float p2 = exp2f(sc[nt][2]-nb), p3 = exp2f(sc[nt][3]-nb);
            sc[nt][0]=p0; sc[nt][1]=p1; sc[nt][2]=p2; sc[nt][3]=p3;
            sa += p0+p1; sbm += p2+p3;
        }
        sa  += __shfl_xor_sync(0xffffffffu, sa, 1);
        sa  += __shfl_xor_sync(0xffffffffu, sa, 2);
        sbm += __shfl_xor_sync(0xffffffffu, sbm, 1);
        sbm += __shfl_xor_sync(0xffffffffu, sbm, 2);
        l0 = l0*ca + sa; l1 = l1*cb + sbm;
        #pragma unroll
        for (int nt=0;nt<8;nt++){ ctx[nt][0]*=ca; ctx[nt][1]*=ca; ctx[nt][2]*=cb; ctx[nt][3]*=cb; }

        // ---- P @ V (1-pass fp16, register P frags) ----
        #pragma unroll
        for (int ks=0;ks<4;ks++){
            uint32_t aPh[4];
            {
                __half2 t;
                t = h2of(sc[2*ks  ][0], sc[2*ks  ][1]); aPh[0] = *(uint32_t*)&t;
                t = h2of(sc[2*ks  ][2], sc[2*ks  ][3]); aPh[1] = *(uint32_t*)&t;
                t = h2of(sc[2*ks+1][0], sc[2*ks+1][1]); aPh[2] = *(uint32_t*)&t;
                t = h2of(sc[2*ks+1][2], sc[2*ks+1][3]); aPh[3] = *(uint32_t*)&t;
            }
            uint32_t vh4[4][4];
            #pragma unroll
            for (int np2=0;np2<4;np2++){
                int r = ks*16 + (lane&15);
                uint32_t u = np2*2 + (lane>>4);
                ldsm4t(vh4[np2], sV + r*128 + ((u^(r&7))<<4));
            }
            #pragma unroll
            for (int np2=0;np2<4;np2++)
                #pragma unroll
                for (int q2i=0;q2i<2;q2i++)
                    mmafp(ctx[np2*2+q2i], aPh, vh4[np2][q2i*2], vh4[np2][q2i*2+1]);
        }
    }
#undef KV_LOAD

    // normalize + write ctx plain fp16 [row][512]
    float i0 = 1.0f/l0, i1 = 1.0f/l1;
    #pragma unroll
    for (int nt=0;nt<8;nt++){
        int d = nt*8 + 2*(lane&3);
        int col = h*64 + d;
        int rA = rowQ0 + w*16 + (lane>>2);
        *(__half2*)(ctxH + (size_t)rA*DD + col)     = h2of(ctx[nt][0]*i0, ctx[nt][1]*i0);
        *(__half2*)(ctxH + (size_t)(rA+8)*DD + col) = h2of(ctx[nt][2]*i1, ctx[nt][3]*i1);
    }
}

extern "C" void kernel_launch(void* const* d_in, const int* in_sizes, int n_in,
                              void* d_out, int out_size)
{
    (void)in_sizes; (void)n_in; (void)out_size;
    const float* Q     = (const float*)d_in[0];
    const float* Kin   = (const float*)d_in[1];
    const float* Vin   = (const float*)d_in[2];
    const float* W_q   = (const float*)d_in[3];
    const float* W_k   = (const float*)d_in[4];
    const float* W_v   = (const float*)d_in[5];
    const float* W_o   = (const float*)d_in[6];
    const float* ln1_g = (const float*)d_in[7];
    const float* ln1_b = (const float*)d_in[8];
    const float* ln2_g = (const float*)d_in[9];
    const float* ln2_b = (const float*)d_in[10];
    const float* w1    = (const float*)d_in[11];
    const float* b1    = (const float*)d_in[12];
    const float* w2    = (const float*)d_in[13];
    const float* b2    = (const float*)d_in[14];
    float* out = (float*)d_out;

    __half *QnH,*KinH,*VinH,*q2h,*k2h,*v2h,*ctxH,*XnH,*hH;
    __half *WqH,*WkH,*WvH,*WoH,*w1H,*w2H;
    float *X;
    cudaGetSymbolAddress((void**)&QnH,  g_QnH);
    cudaGetSymbolAddress((void**)&KinH, g_KinH);
    cudaGetSymbolAddress((void**)&VinH, g_VinH);
    cudaGetSymbolAddress((void**)&q2h,  g_q2h);
    cudaGetSymbolAddress((void**)&k2h,  g_k2h);
    cudaGetSymbolAddress((void**)&v2h,  g_v2h);
    cudaGetSymbolAddress((void**)&ctxH, g_ctxH);
    cudaGetSymbolAddress((void**)&XnH,  g_XnH);
    cudaGetSymbolAddress((void**)&hH,   g_hH);
    cudaGetSymbolAddress((void**)&X,    g_X);
    cudaGetSymbolAddress((void**)&WqH,  g_WqH);
    cudaGetSymbolAddress((void**)&WkH,  g_WkH);
    cudaGetSymbolAddress((void**)&WvH,  g_WvH);
    cudaGetSymbolAddress((void**)&WoH,  g_WoH);
    cudaGetSymbolAddress((void**)&w1H,  g_w1H);
    cudaGetSymbolAddress((void**)&w2H,  g_w2H);

    cudaFuncSetAttribute(attn_mma,  cudaFuncAttributeMaxDynamicSharedMemorySize, ATTN_SMEM);
    cudaFuncSetAttribute(gemm_h<1>, cudaFuncAttributeMaxDynamicSharedMemorySize, GH_SMEM);
    cudaFuncSetAttribute(gemm_h<2>, cudaFuncAttributeMaxDynamicSharedMemorySize, GH_SMEM);
    cudaFuncSetAttribute(gemm_h<3>, cudaFuncAttributeMaxDynamicSharedMemorySize, GH_SMEM);
    cudaFuncSetAttribute(gemm_h<4>, cudaFuncAttributeMaxDynamicSharedMemorySize, GH_SMEM);

    dim3 tb(32, 8), tg(16, 16);

    // conversions
    ln_h<<<ROWS,128>>>(Q, ln1_g, ln1_b, QnH);
    toH2<<<(2*ROWS*DD/4+255)/256,256>>>(Kin, KinH, Vin, VinH, ROWS*DD/4);
    tpH<<<tg, tb>>>(W_q, WqH);
    tpH<<<tg, tb>>>(W_k, WkH);
    tpH<<<tg, tb>>>(W_v, WvH);
    tpH<<<tg, tb>>>(W_o, WoH);
    toH<<<(DFF*DD/4+255)/256,256>>>(w1, w1H, DFF*DD/4);
    toH<<<(DD*DFF/4+255)/256,256>>>(w2, w2H, DD*DFF/4);

    // projections
    gemm_h<4><<<dim3(DD/128,  ROWS/128), 256, GH_SMEM>>>(QnH,  WqH, DD,  DD,  nullptr, nullptr, nullptr, q2h);
    gemm_h<4><<<dim3(DD/128,  ROWS/128), 256, GH_SMEM>>>(KinH, WkH, DD,  DD,  nullptr, nullptr, nullptr, k2h);
    gemm_h<4><<<dim3(DD/128,  ROWS/128), 256, GH_SMEM>>>(VinH, WvH, DD,  DD,  nullptr, nullptr, nullptr, v2h);
    // attention
    attn_mma<<<dim3(SS/128, HH, BB), 256, ATTN_SMEM>>>(q2h, k2h, v2h, ctxH);
    // X = Q + ctx @ Wo
    gemm_h<1><<<dim3(DD/128,  ROWS/128), 256, GH_SMEM>>>(ctxH, WoH, DD,  DD,  nullptr, Q, X, nullptr);
    // LN2 + FFN
    ln_h<<<ROWS,128>>>(X, ln2_g, ln2_b, XnH);
    gemm_h<2><<<dim3(DFF/128, ROWS/128), 256, GH_SMEM>>>(XnH, w1H, DFF, DD,  b1, nullptr, nullptr, hH);
    gemm_h<3><<<dim3(DD/128,  ROWS/128), 256, GH_SMEM>>>(hH,  w2H, DD,  DFF, b2, X, out, nullptr);
}